// round 9
// baseline (speedup 1.0000x reference)
#include <cuda_runtime.h>
#include <cuda_bf16.h>
#include <cstdint>
#include <math.h>

#define DMODEL 1024
#define SEQ 512
#define BATCH 64
#define NTOK (BATCH * SEQ)

// ---------------- scratch (static device globals; no allocation) ----------------
__device__ float g_emb[(size_t)NTOK * DMODEL];
__device__ float g_h1[(size_t)NTOK * DMODEL];
__device__ float g_h2[(size_t)NTOK * DMODEL];
__device__ float g_q[(size_t)NTOK * DMODEL];   // reused as bf16 qhi/qlo halves
__device__ float g_k[(size_t)NTOK * DMODEL];   // khi/klo
__device__ float g_v[(size_t)NTOK * DMODEL];   // vhi/vlo
__device__ __nv_bfloat16 g_ahi[(size_t)NTOK * DMODEL];
__device__ __nv_bfloat16 g_alo[(size_t)NTOK * DMODEL];
__device__ __nv_bfloat16 g_bhi[(size_t)NTOK * DMODEL];
__device__ __nv_bfloat16 g_blo[(size_t)NTOK * DMODEL];
__device__ __nv_bfloat16 g_whi[(size_t)8 * DMODEL * DMODEL];
__device__ __nv_bfloat16 g_wlo[(size_t)8 * DMODEL * DMODEL];
__device__ float g_pooled[BATCH * DMODEL];
__device__ int g_is64;

// ---------------- helpers ----------------
__device__ __forceinline__ uint32_t smem_u32(const void* p) {
    uint32_t a;
    asm("{ .reg .u64 t; cvta.to.shared.u64 t, %1; cvt.u32.u64 %0, t; }" : "=r"(a) : "l"(p));
    return a;
}
__device__ __forceinline__ void cp_async16(uint32_t dst, const void* src) {
    asm volatile("cp.async.cg.shared.global [%0], [%1], 16;" :: "r"(dst), "l"(src));
}
__device__ __forceinline__ void ldsm_x4(uint32_t& r0, uint32_t& r1, uint32_t& r2, uint32_t& r3,
                                        uint32_t addr) {
    asm volatile("ldmatrix.sync.aligned.m8n8.x4.shared.b16 {%0,%1,%2,%3}, [%4];"
                 : "=r"(r0), "=r"(r1), "=r"(r2), "=r"(r3) : "r"(addr));
}
__device__ __forceinline__ void ldsm_x4t(uint32_t& r0, uint32_t& r1, uint32_t& r2, uint32_t& r3,
                                         uint32_t addr) {
    asm volatile("ldmatrix.sync.aligned.m8n8.x4.trans.shared.b16 {%0,%1,%2,%3}, [%4];"
                 : "=r"(r0), "=r"(r1), "=r"(r2), "=r"(r3) : "r"(addr));
}
__device__ __forceinline__ void mma_bf16(float& c0, float& c1, float& c2, float& c3,
                                         uint32_t a0, uint32_t a1, uint32_t a2, uint32_t a3,
                                         uint32_t b0, uint32_t b1) {
    asm volatile("mma.sync.aligned.m16n8k16.row.col.f32.bf16.bf16.f32 "
                 "{%0,%1,%2,%3}, {%4,%5,%6,%7}, {%8,%9}, {%0,%1,%2,%3};"
                 : "+f"(c0), "+f"(c1), "+f"(c2), "+f"(c3)
                 : "r"(a0), "r"(a1), "r"(a2), "r"(a3), "r"(b0), "r"(b1));
}
__device__ __forceinline__ void split_bf16(float v, __nv_bfloat16& hi, __nv_bfloat16& lo) {
    hi = __float2bfloat16_rn(v);
    lo = __float2bfloat16_rn(v - __bfloat162float(hi));
}
__device__ __forceinline__ float fast_exp(float x) {
    if (x < -80.f) return 0.f;
    float t = x * 1.4426950408889634f;
    float n = floorf(t + 0.5f);
    float g = (t - n) * 0.6931471805599453f;
    float p = 1.f + g * (1.f + g * (0.5f + g * (0.16666667f + g * (0.041666667f + g * 0.0083333f))));
    return __uint_as_float((uint32_t)(((int)n + 127) << 23)) * p;
}

// ---------------- dtype detection ----------------
__global__ void detect_kernel(const int* __restrict__ x) {
    __shared__ int any;
    if (threadIdx.x == 0) any = 0;
    __syncthreads();
    int local = 0;
    for (int i = threadIdx.x * 2 + 1; i < NTOK; i += blockDim.x * 2) local |= x[i];
    if (local) atomicOr(&any, 1);
    __syncthreads();
    if (threadIdx.x == 0) g_is64 = (any == 0) ? 1 : 0;
}
__device__ __forceinline__ long long get_id(const void* x, int i) {
    return g_is64 ? ((const long long*)x)[i] : (long long)((const int*)x)[i];
}

// ---------------- fused 8x weight transpose + bf16 hi/lo ----------------
__global__ void wtrans_all_kernel(
    const float* __restrict__ W0, const float* __restrict__ W1,
    const float* __restrict__ W2, const float* __restrict__ W3,
    const float* __restrict__ W4, const float* __restrict__ W5,
    const float* __restrict__ W6, const float* __restrict__ W7,
    __nv_bfloat16* __restrict__ WThi, __nv_bfloat16* __restrict__ WTlo) {
    __shared__ float t[32][33];
    int w = blockIdx.z;
    const float* W = (w == 0) ? W0 : (w == 1) ? W1 : (w == 2) ? W2 : (w == 3) ? W3
                   : (w == 4) ? W4 : (w == 5) ? W5 : (w == 6) ? W6 : W7;
    size_t wofs = (size_t)w * DMODEL * DMODEL;
    int n0 = blockIdx.x * 32, k0 = blockIdx.y * 32;
    int tx = threadIdx.x, ty = threadIdx.y;
#pragma unroll
    for (int i = 0; i < 4; i++)
        t[ty + 8 * i][tx] = W[(size_t)(k0 + ty + 8 * i) * DMODEL + n0 + tx];
    __syncthreads();
#pragma unroll
    for (int i = 0; i < 4; i++) {
        float v = t[tx][ty + 8 * i];
        __nv_bfloat16 hi, lo;
        split_bf16(v, hi, lo);
        size_t idx = wofs + (size_t)(n0 + ty + 8 * i) * DMODEL + k0 + tx;
        WThi[idx] = hi;
        WTlo[idx] = lo;
    }
}

// ---------------- embedding ----------------
__global__ void embed_kernel(const void* __restrict__ x,
                             const float* __restrict__ emb_w,
                             const float* __restrict__ pos_w) {
    int tok = blockIdx.x;
    int s = tok & (SEQ - 1);
    long long id = get_id(x, tok);
    const float4* ew = (const float4*)(emb_w + (size_t)id * DMODEL);
    const float4* pw = (const float4*)(pos_w + (size_t)s * DMODEL);
    float4* out = (float4*)(g_emb + (size_t)tok * DMODEL);
    __nv_bfloat16* ohi = g_ahi + (size_t)tok * DMODEL;
    __nv_bfloat16* olo = g_alo + (size_t)tok * DMODEL;
    for (int i = threadIdx.x; i < DMODEL / 4; i += blockDim.x) {
        float4 a = ew[i], b = pw[i];
        float4 o = make_float4(a.x + b.x, a.y + b.y, a.z + b.z, a.w + b.w);
        out[i] = o;
        __nv_bfloat16 h0, l0, h1, l1, h2, l2, h3, l3;
        split_bf16(o.x, h0, l0); split_bf16(o.y, h1, l1);
        split_bf16(o.z, h2, l2); split_bf16(o.w, h3, l3);
        ohi[4 * i + 0] = h0; ohi[4 * i + 1] = h1; ohi[4 * i + 2] = h2; ohi[4 * i + 3] = h3;
        olo[4 * i + 0] = l0; olo[4 * i + 1] = l1; olo[4 * i + 2] = l2; olo[4 * i + 3] = l3;
    }
}

// ---------------- 3-term split HMMA GEMM (BK=32, hoisted ldsm bases) ----------------
#define BKD 32
#define SSTR 40
#define TILE_E (128 * SSTR)
#define ROWB (SSTR * 2)             // bytes per smem row
__global__ __launch_bounds__(256) void gemm_split(
    const __nv_bfloat16* __restrict__ Ahi, const __nv_bfloat16* __restrict__ Alo,
    const __nv_bfloat16* __restrict__ Bhi, const __nv_bfloat16* __restrict__ Blo,
    const float* __restrict__ bias, const float* __restrict__ res,
    float* __restrict__ C, __nv_bfloat16* __restrict__ Chi, __nv_bfloat16* __restrict__ Clo) {
    extern __shared__ __nv_bfloat16 smem[];
    __nv_bfloat16* sAhi[2] = {smem + 0 * TILE_E, smem + 1 * TILE_E};
    __nv_bfloat16* sAlo[2] = {smem + 2 * TILE_E, smem + 3 * TILE_E};
    __nv_bfloat16* sBhi[2] = {smem + 4 * TILE_E, smem + 5 * TILE_E};
    __nv_bfloat16* sBlo[2] = {smem + 6 * TILE_E, smem + 7 * TILE_E};

    int tid = threadIdx.x, wid = tid >> 5, lane = tid & 31;
    int bn = blockIdx.x, bm = blockIdx.y;
    int wm = (wid >> 1) * 32;
    int wn = (wid & 1) * 64;

    float acc[2][8][4];
#pragma unroll
    for (int i = 0; i < 2; i++)
#pragma unroll
        for (int j = 0; j < 8; j++)
#pragma unroll
            for (int k = 0; k < 4; k++) acc[i][j][k] = 0.f;

    int lrow = tid >> 1;
    int lc0 = (tid & 1) * 2;
    const __nv_bfloat16* gAhi = Ahi + (size_t)(bm * 128 + lrow) * DMODEL;
    const __nv_bfloat16* gAlo = Alo + (size_t)(bm * 128 + lrow) * DMODEL;
    const __nv_bfloat16* gBhi = Bhi + (size_t)(bn * 128 + lrow) * DMODEL;
    const __nv_bfloat16* gBlo = Blo + (size_t)(bn * 128 + lrow) * DMODEL;
    uint32_t rowoff = lrow * ROWB;
    uint32_t dAhi[2], dAlo[2], dBhi[2], dBlo[2];
#pragma unroll
    for (int b = 0; b < 2; b++) {
        dAhi[b] = smem_u32(sAhi[b]) + rowoff;
        dAlo[b] = smem_u32(sAlo[b]) + rowoff;
        dBhi[b] = smem_u32(sBhi[b]) + rowoff;
        dBlo[b] = smem_u32(sBlo[b]) + rowoff;
    }

    int g = lane >> 3, r = lane & 7;
    int rofs = (g & 1) * 8 + r;
    int kofs = (g >> 1) * 8;

    // hoisted ldsm bases: addr = base[buf] + const
    uint32_t aHb[2], aLb[2], bHb[2], bLb[2];
#pragma unroll
    for (int b = 0; b < 2; b++) {
        uint32_t aoff = (uint32_t)((wm + rofs) * SSTR + kofs) * 2;
        uint32_t boff = (uint32_t)((wn + rofs) * SSTR + kofs) * 2;
        aHb[b] = smem_u32(sAhi[b]) + aoff;
        aLb[b] = smem_u32(sAlo[b]) + aoff;
        bHb[b] = smem_u32(sBhi[b]) + boff;
        bLb[b] = smem_u32(sBlo[b]) + boff;
    }

#define LOAD_TILE(buf, k0) do { \
    cp_async16(dAhi[buf] + (lc0 + 0) * 16, gAhi + (k0) + (lc0 + 0) * 8); \
    cp_async16(dAhi[buf] + (lc0 + 1) * 16, gAhi + (k0) + (lc0 + 1) * 8); \
    cp_async16(dAlo[buf] + (lc0 + 0) * 16, gAlo + (k0) + (lc0 + 0) * 8); \
    cp_async16(dAlo[buf] + (lc0 + 1) * 16, gAlo + (k0) + (lc0 + 1) * 8); \
    cp_async16(dBhi[buf] + (lc0 + 0) * 16, gBhi + (k0) + (lc0 + 0) * 8); \
    cp_async16(dBhi[buf] + (lc0 + 1) * 16, gBhi + (k0) + (lc0 + 1) * 8); \
    cp_async16(dBlo[buf] + (lc0 + 0) * 16, gBlo + (k0) + (lc0 + 0) * 8); \
    cp_async16(dBlo[buf] + (lc0 + 1) * 16, gBlo + (k0) + (lc0 + 1) * 8); \
    asm volatile("cp.async.commit_group;"); \
} while (0)

    LOAD_TILE(0, 0);
    LOAD_TILE(1, BKD);

    const int NIT = DMODEL / BKD;
    for (int it = 0; it < NIT; it++) {
        int buf = it & 1;
        if (it + 2 < NIT)
            asm volatile("cp.async.wait_group 1;" ::: "memory");
        else
            asm volatile("cp.async.wait_group 0;" ::: "memory");
        __syncthreads();

        uint32_t aHx = aHb[buf], aLx = aLb[buf], bHx = bHb[buf], bLx = bLb[buf];
#pragma unroll
        for (int kk = 0; kk < 2; kk++) {
            const uint32_t ko = kk * 32;   // 16 elements * 2B
            uint32_t aH[2][4];
#pragma unroll
            for (int mt = 0; mt < 2; mt++)
                ldsm_x4(aH[mt][0], aH[mt][1], aH[mt][2], aH[mt][3],
                        aHx + mt * (16 * ROWB) + ko);
            uint32_t bF[8][2];
#pragma unroll
            for (int np = 0; np < 4; np++) {
                uint32_t r0, r1, r2, r3;
                ldsm_x4(r0, r1, r2, r3, bHx + np * (16 * ROWB) + ko);
                bF[np * 2 + 0][0] = r0; bF[np * 2 + 0][1] = r2;
                bF[np * 2 + 1][0] = r1; bF[np * 2 + 1][1] = r3;
            }
#pragma unroll
            for (int mt = 0; mt < 2; mt++)
#pragma unroll
                for (int nt = 0; nt < 8; nt++)
                    mma_bf16(acc[mt][nt][0], acc[mt][nt][1], acc[mt][nt][2], acc[mt][nt][3],
                             aH[mt][0], aH[mt][1], aH[mt][2], aH[mt][3],
                             bF[nt][0], bF[nt][1]);
            {
                uint32_t aL[2][4];
#pragma unroll
                for (int mt = 0; mt < 2; mt++)
                    ldsm_x4(aL[mt][0], aL[mt][1], aL[mt][2], aL[mt][3],
                            aLx + mt * (16 * ROWB) + ko);
#pragma unroll
                for (int mt = 0; mt < 2; mt++)
#pragma unroll
                    for (int nt = 0; nt < 8; nt++)
                        mma_bf16(acc[mt][nt][0], acc[mt][nt][1], acc[mt][nt][2], acc[mt][nt][3],
                                 aL[mt][0], aL[mt][1], aL[mt][2], aL[mt][3],
                                 bF[nt][0], bF[nt][1]);
            }
#pragma unroll
            for (int np = 0; np < 4; np++) {
                uint32_t r0, r1, r2, r3;
                ldsm_x4(r0, r1, r2, r3, bLx + np * (16 * ROWB) + ko);
                bF[np * 2 + 0][0] = r0; bF[np * 2 + 0][1] = r2;
                bF[np * 2 + 1][0] = r1; bF[np * 2 + 1][1] = r3;
            }
#pragma unroll
            for (int mt = 0; mt < 2; mt++)
#pragma unroll
                for (int nt = 0; nt < 8; nt++)
                    mma_bf16(acc[mt][nt][0], acc[mt][nt][1], acc[mt][nt][2], acc[mt][nt][3],
                             aH[mt][0], aH[mt][1], aH[mt][2], aH[mt][3],
                             bF[nt][0], bF[nt][1]);
        }
        __syncthreads();
        if (it + 2 < NIT) LOAD_TILE(buf, (it + 2) * BKD);
    }
#undef LOAD_TILE

    int gid = lane >> 2, tig = lane & 3;
#pragma unroll
    for (int mt = 0; mt < 2; mt++) {
#pragma unroll
        for (int half = 0; half < 2; half++) {
            int m = bm * 128 + wm + mt * 16 + gid + half * 8;
            float* crow = C ? C + (size_t)m * DMODEL : nullptr;
            const float* rrow = res ? res + (size_t)m * DMODEL : nullptr;
            __nv_bfloat16* hrow = Chi ? Chi + (size_t)m * DMODEL : nullptr;
            __nv_bfloat16* lrow2 = Clo ? Clo + (size_t)m * DMODEL : nullptr;
#pragma unroll
            for (int nt = 0; nt < 8; nt++) {
                int ncol = bn * 128 + wn + nt * 8 + tig * 2;
                float v0 = acc[mt][nt][half * 2 + 0] + bias[ncol];
                float v1 = acc[mt][nt][half * 2 + 1] + bias[ncol + 1];
                if (rrow) { v0 += rrow[ncol]; v1 += rrow[ncol + 1]; }
                if (crow) *(float2*)(crow + ncol) = make_float2(v0, v1);
                if (hrow) {
                    __nv_bfloat16 h0, l0, h1, l1;
                    split_bf16(v0, h0, l0);
                    split_bf16(v1, h1, l1);
                    hrow[ncol] = h0; hrow[ncol + 1] = h1;
                    lrow2[ncol] = l0; lrow2[ncol + 1] = l1;
                }
            }
        }
    }
}

// ---------------- tensor-core flash attention (3-term bf16 split) ----------------
template <int DH>
__global__ __launch_bounds__(256) void attn_tc(
    const __nv_bfloat16* __restrict__ Qhi, const __nv_bfloat16* __restrict__ Qlo,
    const __nv_bfloat16* __restrict__ Khi, const __nv_bfloat16* __restrict__ Klo,
    const __nv_bfloat16* __restrict__ Vhi, const __nv_bfloat16* __restrict__ Vlo,
    const void* __restrict__ xids,
    __nv_bfloat16* __restrict__ Ohi, __nv_bfloat16* __restrict__ Olo) {
    extern __shared__ __nv_bfloat16 smb[];
    const int SSTRA = DH + 8;
    const int PSTR = 72;
    __nv_bfloat16* qhi_s = smb;
    __nv_bfloat16* qlo_s = qhi_s + 64 * SSTRA;
    __nv_bfloat16* khi_s = qlo_s + 64 * SSTRA;
    __nv_bfloat16* klo_s = khi_s + 64 * SSTRA;
    __nv_bfloat16* vhi_s = klo_s + 64 * SSTRA;
    __nv_bfloat16* vlo_s = vhi_s + 64 * SSTRA;
    __nv_bfloat16* phi_s = vlo_s + 64 * SSTRA;
    __nv_bfloat16* plo_s = phi_s + 64 * PSTR;
    __shared__ int msk[64];
    __shared__ float rmaxs[64][2], psumw[64][2];
    __shared__ float m_state[64], m_next[64], l_state[64], fac[64];

    int qt = blockIdx.x, h = blockIdx.y, b = blockIdx.z;
    int tid = threadIdx.x, wid = tid >> 5, lane = tid & 31;
    int mt = wid >> 1, nh = wid & 1;
    float scale = rsqrtf((float)DH);
    int q0 = qt * 64;
    int gg = lane >> 3, rr8 = lane & 7;
    int rofs = (gg & 1) * 8 + rr8, kofs = (gg >> 1) * 8;
    int rowA = mt * 16 + (lane >> 2), rowB = rowA + 8;
    int colq = (lane & 3) * 2;
    const int CHK = DH / 8;
    const int NG = DH / 16;

    for (int i = tid; i < 64 * CHK; i += 256) {
        int r = i / CHK, c = i % CHK;
        size_t gi = (size_t)(b * SEQ + q0 + r) * DMODEL + h * DH + c * 8;
        *(uint4*)(qhi_s + r * SSTRA + c * 8) = *(const uint4*)(Qhi + gi);
        *(uint4*)(qlo_s + r * SSTRA + c * 8) = *(const uint4*)(Qlo + gi);
    }
    if (tid < 64) { m_state[tid] = -1e30f; l_state[tid] = 0.f; }

    float o[NG][4];
#pragma unroll
    for (int i = 0; i < NG; i++) { o[i][0] = 0.f; o[i][1] = 0.f; o[i][2] = 0.f; o[i][3] = 0.f; }

    int is64 = g_is64;

    for (int kt = 0; kt < SEQ / 64; kt++) {
        int k0 = kt * 64;
        __syncthreads();
        for (int i = tid; i < 64 * CHK; i += 256) {
            int r = i / CHK, c = i % CHK;
            size_t gi = (size_t)(b * SEQ + k0 + r) * DMODEL + h * DH + c * 8;
            *(uint4*)(khi_s + r * SSTRA + c * 8) = *(const uint4*)(Khi + gi);
            *(uint4*)(klo_s + r * SSTRA + c * 8) = *(const uint4*)(Klo + gi);
            *(uint4*)(vhi_s + r * SSTRA + c * 8) = *(const uint4*)(Vhi + gi);
            *(uint4*)(vlo_s + r * SSTRA + c * 8) = *(const uint4*)(Vlo + gi);
        }
        if (tid < 64) {
            long long idv = is64 ? ((const long long*)xids)[b * SEQ + k0 + tid]
                                 : (long long)((const int*)xids)[b * SEQ + k0 + tid];
            msk[tid] = (idv != 0) ? 1 : 0;
        }
        __syncthreads();

        // ---- phase A: scores via 3-term HMMA ----
        float sc[4][4];
#pragma unroll
        for (int gq = 0; gq < 4; gq++) { sc[gq][0] = 0.f; sc[gq][1] = 0.f; sc[gq][2] = 0.f; sc[gq][3] = 0.f; }
#pragma unroll
        for (int ks = 0; ks < DH / 16; ks++) {
            uint32_t aH[4], aL[4];
            ldsm_x4(aH[0], aH[1], aH[2], aH[3],
                    smem_u32(qhi_s + (mt * 16 + rofs) * SSTRA + ks * 16 + kofs));
            ldsm_x4(aL[0], aL[1], aL[2], aL[3],
                    smem_u32(qlo_s + (mt * 16 + rofs) * SSTRA + ks * 16 + kofs));
            uint32_t bH[4][2], bL[4][2];
#pragma unroll
            for (int kg = 0; kg < 2; kg++) {
                uint32_t r0, r1, r2, r3;
                ldsm_x4(r0, r1, r2, r3,
                        smem_u32(khi_s + (nh * 32 + kg * 16 + rofs) * SSTRA + ks * 16 + kofs));
                bH[kg * 2 + 0][0] = r0; bH[kg * 2 + 0][1] = r2;
                bH[kg * 2 + 1][0] = r1; bH[kg * 2 + 1][1] = r3;
                ldsm_x4(r0, r1, r2, r3,
                        smem_u32(klo_s + (nh * 32 + kg * 16 + rofs) * SSTRA + ks * 16 + kofs));
                bL[kg * 2 + 0][0] = r0; bL[kg * 2 + 0][1] = r2;
                bL[kg * 2 + 1][0] = r1; bL[kg * 2 + 1][1] = r3;
            }
#pragma unroll
            for (int gq = 0; gq < 4; gq++) {
                mma_bf16(sc[gq][0], sc[gq][1], sc[gq][2], sc[gq][3],
                         aH[0], aH[1], aH[2], aH[3], bH[gq][0], bH[gq][1]);
                mma_bf16(sc[gq][0], sc[gq][1], sc[gq][2], sc[gq][3],
                         aL[0], aL[1], aL[2], aL[3], bH[gq][0], bH[gq][1]);
                mma_bf16(sc[gq][0], sc[gq][1], sc[gq][2], sc[gq][3],
                         aH[0], aH[1], aH[2], aH[3], bL[gq][0], bL[gq][1]);
            }
        }

        // mask + scale, row max
        float mA = -1e30f, mB = -1e30f;
#pragma unroll
        for (int gq = 0; gq < 4; gq++) {
            int cb = nh * 32 + gq * 8 + colq;
            bool k0m = msk[cb] != 0, k1m = msk[cb + 1] != 0;
            sc[gq][0] = k0m ? sc[gq][0] * scale : -1e30f;
            sc[gq][1] = k1m ? sc[gq][1] * scale : -1e30f;
            sc[gq][2] = k0m ? sc[gq][2] * scale : -1e30f;
            sc[gq][3] = k1m ? sc[gq][3] * scale : -1e30f;
            mA = fmaxf(mA, fmaxf(sc[gq][0], sc[gq][1]));
            mB = fmaxf(mB, fmaxf(sc[gq][2], sc[gq][3]));
        }
        mA = fmaxf(mA, __shfl_xor_sync(0xFFFFFFFF, mA, 1));
        mA = fmaxf(mA, __shfl_xor_sync(0xFFFFFFFF, mA, 2));
        mB = fmaxf(mB, __shfl_xor_sync(0xFFFFFFFF, mB, 1));
        mB = fmaxf(mB, __shfl_xor_sync(0xFFFFFFFF, mB, 2));
        if ((lane & 3) == 0) { rmaxs[rowA][nh] = mA; rmaxs[rowB][nh] = mB; }
        __syncthreads();
        if (nh == 0 && (lane & 3) == 0) {
#pragma unroll
            for (int rr = 0; rr < 2; rr++) {
                int rw = rr ? rowB : rowA;
                float rm = fmaxf(rmaxs[rw][0], rmaxs[rw][1]);
                float mold = m_state[rw];
                float mnew = fmaxf(mold, rm);
                m_next[rw] = mnew;
                fac[rw] = (mold < -1e29f) ? 0.f : fast_exp(mold - mnew);
            }
        }
        __syncthreads();

        // exp + P hi/lo write + partial sums
        float mnA = m_next[rowA], mnB = m_next[rowB];
        float sumA = 0.f, sumB = 0.f;
#pragma unroll
        for (int gq = 0; gq < 4; gq++) {
            int cb = nh * 32 + gq * 8 + colq;
            float p0 = (sc[gq][0] > -1e29f) ? fast_exp(sc[gq][0] - mnA) : 0.f;
            float p1 = (sc[gq][1] > -1e29f) ? fast_exp(sc[gq][1] - mnA) : 0.f;
            float p2 = (sc[gq][2] > -1e29f) ? fast_exp(sc[gq][2] - mnB) : 0.f;
            float p3 = (sc[gq][3] > -1e29f) ? fast_exp(sc[gq][3] - mnB) : 0.f;
            sumA += p0 + p1; sumB += p2 + p3;
            __nv_bfloat16 h0, l0, h1, l1;
            split_bf16(p0, h0, l0); split_bf16(p1, h1, l1);
            *(__nv_bfloat162*)(phi_s + rowA * PSTR + cb) = __nv_bfloat162(h0, h1);
            *(__nv_bfloat162*)(plo_s + rowA * PSTR + cb) = __nv_bfloat162(l0, l1);
            split_bf16(p2, h0, l0); split_bf16(p3, h1, l1);
            *(__nv_bfloat162*)(phi_s + rowB * PSTR + cb) = __nv_bfloat162(h0, h1);
            *(__nv_bfloat162*)(plo_s + rowB * PSTR + cb) = __nv_bfloat162(l0, l1);
        }
        sumA += __shfl_xor_sync(0xFFFFFFFF, sumA, 1);
        sumA += __shfl_xor_sync(0xFFFFFFFF, sumA, 2);
        sumB += __shfl_xor_sync(0xFFFFFFFF, sumB, 1);
        sumB += __shfl_xor_sync(0xFFFFFFFF, sumB, 2);
        if ((lane & 3) == 0) { psumw[rowA][nh] = sumA; psumw[rowB][nh] = sumB; }
        __syncthreads();
        if (nh == 0 && (lane & 3) == 0) {
#pragma unroll
            for (int rr = 0; rr < 2; rr++) {
                int rw = rr ? rowB : rowA;
                l_state[rw] = l_state[rw] * fac[rw] + psumw[rw][0] + psumw[rw][1];
                m_state[rw] = m_next[rw];
            }
        }

        // ---- phase C: O += P @ V via 3-term HMMA ----
        float fA = fac[rowA], fB = fac[rowB];
#pragma unroll
        for (int gq = 0; gq < NG; gq++) {
            o[gq][0] *= fA; o[gq][1] *= fA; o[gq][2] *= fB; o[gq][3] *= fB;
        }
#pragma unroll
        for (int ksv = 0; ksv < 4; ksv++) {
            uint32_t pH[4], pL[4];
            ldsm_x4(pH[0], pH[1], pH[2], pH[3],
                    smem_u32(phi_s + (mt * 16 + rofs) * PSTR + ksv * 16 + kofs));
            ldsm_x4(pL[0], pL[1], pL[2], pL[3],
                    smem_u32(plo_s + (mt * 16 + rofs) * PSTR + ksv * 16 + kofs));
            int vrow = ksv * 16 + rr8 + ((lane >> 4) << 3);
            int vcb = nh * (DH / 2) + ((lane >> 3) & 1) * 8;
#pragma unroll
            for (int vg = 0; vg < NG / 2; vg++) {
                uint32_t r0, r1, r2, r3;
                ldsm_x4t(r0, r1, r2, r3,
                         smem_u32(vhi_s + vrow * SSTRA + vcb + vg * 16));
                uint32_t bH0[2] = {r0, r2}, bH1[2] = {r1, r3};
                ldsm_x4t(r0, r1, r2, r3,
                         smem_u32(vlo_s + vrow * SSTRA + vcb + vg * 16));
                uint32_t bL0[2] = {r0, r2}, bL1[2] = {r1, r3};
                int g0 = vg * 2, g1 = vg * 2 + 1;
                mma_bf16(o[g0][0], o[g0][1], o[g0][2], o[g0][3],
                         pH[0], pH[1], pH[2], pH[3], bH0[0], bH0[1]);
                mma_bf16(o[g1][0], o[g1][1], o[g1][2], o[g1][3],
                         pH[0], pH[1], pH[2], pH[3], bH1[0], bH1[1]);
                mma_bf16(o[g0][0], o[g0][1], o[g0][2], o[g0][3],
                         pL[0], pL[1], pL[2], pL[3], bH0[0], bH0[1]);
                mma_bf16(o[g1][0], o[g1][1], o[g1][2], o[g1][3],
                         pL[0], pL[1], pL[2], pL[3], bH1[0], bH1[1]);
                mma_bf16(o[g0][0], o[g0][1], o[g0][2], o[g0][3],
                         pH[0], pH[1], pH[2], pH[3], bL0[0], bL0[1]);
                mma_bf16(o[g1][0], o[g1][1], o[g1][2], o[g1][3],
                         pH[0], pH[1], pH[2], pH[3], bL1[0], bL1[1]);
            }
        }
    }
    __syncthreads();

    float invA = 1.0f / fmaxf(l_state[rowA], 1e-20f);
    float invB = 1.0f / fmaxf(l_state[rowB], 1e-20f);
    size_t bA = (size_t)(b * SEQ + q0 + rowA) * DMODEL;
    size_t bB = (size_t)(b * SEQ + q0 + rowB) * DMODEL;
#pragma unroll
    for (int gq = 0; gq < NG; gq++) {
        int cb = h * DH + nh * (DH / 2) + gq * 8 + colq;
        float v0 = o[gq][0] * invA, v1 = o[gq][1] * invA;
        float v2 = o[gq][2] * invB, v3 = o[gq][3] * invB;
        __nv_bfloat16 h0, l0, h1, l1;
        split_bf16(v0, h0, l0); split_bf16(v1, h1, l1);
        *(__nv_bfloat162*)(Ohi + bA + cb) = __nv_bfloat162(h0, h1);
        *(__nv_bfloat162*)(Olo + bA + cb) = __nv_bfloat162(l0, l1);
        split_bf16(v2, h0, l0); split_bf16(v3, h1, l1);
        *(__nv_bfloat162*)(Ohi + bB + cb) = __nv_bfloat162(h0, h1);
        *(__nv_bfloat162*)(Olo + bB + cb) = __nv_bfloat162(l0, l1);
    }
}

// ---------------- masked mean pooling of (g_h2 + g_emb) ----------------
__global__ void pool_kernel(const void* __restrict__ xids) {
    int b = blockIdx.y;
    int col = blockIdx.x * 128 + threadIdx.x;
    __shared__ int smask[SEQ];
    int is64 = g_is64;
    for (int s = threadIdx.x; s < SEQ; s += 128) {
        long long idv = is64 ? ((const long long*)xids)[b * SEQ + s]
                             : (long long)((const int*)xids)[b * SEQ + s];
        smask[s] = (idv != 0) ? 1 : 0;
    }
    __syncthreads();
    float acc = 0.f;
    int cnt = 0;
    for (int s = 0; s < SEQ; s++) {
        if (smask[s]) {
            size_t idx = (size_t)(b * SEQ + s) * DMODEL + col;
            acc += g_h2[idx] + g_emb[idx];
            cnt++;
        }
    }
    g_pooled[b * DMODEL + col] = acc / (float)cnt;
}

// ---------------- LayerNorm + linear head ----------------
__global__ void lnlin_kernel(const float* __restrict__ ng, const float* __restrict__ nb,
                             const float* __restrict__ lw, const float* __restrict__ lb,
                             float* __restrict__ out) {
    int b = blockIdx.x, tid = threadIdx.x;
    __shared__ float red[256];
    float x[4];
    float s = 0.f;
#pragma unroll
    for (int k = 0; k < 4; k++) {
        x[k] = g_pooled[b * DMODEL + tid + k * 256];
        s += x[k];
    }
    red[tid] = s; __syncthreads();
    for (int st = 128; st > 0; st >>= 1) { if (tid < st) red[tid] += red[tid + st]; __syncthreads(); }
    float mu = red[0] / (float)DMODEL;
    __syncthreads();
    float s2 = 0.f;
#pragma unroll
    for (int k = 0; k < 4; k++) { float d = x[k] - mu; s2 += d * d; }
    red[tid] = s2; __syncthreads();
    for (int st = 128; st > 0; st >>= 1) { if (tid < st) red[tid] += red[tid + st]; __syncthreads(); }
    float var = red[0] / (float)DMODEL;
    float rstd = rsqrtf(var + 1e-5f);
    __syncthreads();
    float acc = 0.f;
#pragma unroll
    for (int k = 0; k < 4; k++) {
        int col = tid + k * 256;
        acc += ((x[k] - mu) * rstd * ng[col] + nb[col]) * lw[col];
    }
    red[tid] = acc; __syncthreads();
    for (int st = 128; st > 0; st >>= 1) { if (tid < st) red[tid] += red[tid + st]; __syncthreads(); }
    if (tid == 0) out[b] = red[0] + lb[0];
}

// ---------------- launch ----------------
extern "C" void kernel_launch(void* const* d_in, const int* in_sizes, int n_in,
                              void* d_out, int out_size) {
    const void*  x      = d_in[0];
    const float* emb_w  = (const float*)d_in[1];
    const float* pos_w  = (const float*)d_in[2];
    const float* a1_qw  = (const float*)d_in[3];
    const float* a1_qb  = (const float*)d_in[4];
    const float* a1_kw  = (const float*)d_in[5];
    const float* a1_kb  = (const float*)d_in[6];
    const float* a1_vw  = (const float*)d_in[7];
    const float* a1_vb  = (const float*)d_in[8];
    const float* a1_pw  = (const float*)d_in[9];
    const float* a1_pb  = (const float*)d_in[10];
    const float* a2_qw  = (const float*)d_in[11];
    const float* a2_qb  = (const float*)d_in[12];
    const float* a2_kw  = (const float*)d_in[13];
    const float* a2_kb  = (const float*)d_in[14];
    const float* a2_vw  = (const float*)d_in[15];
    const float* a2_vb  = (const float*)d_in[16];
    const float* a2_pw  = (const float*)d_in[17];
    const float* a2_pb  = (const float*)d_in[18];
    const float* norm_g = (const float*)d_in[19];
    const float* norm_b = (const float*)d_in[20];
    const float* lin_w  = (const float*)d_in[21];
    const float* lin_b  = (const float*)d_in[22];
    float* out = (float*)d_out;

    float *p_emb, *p_h1, *p_h2, *p_q, *p_k, *p_v;
    __nv_bfloat16 *p_ahi, *p_alo, *p_bhi, *p_blo, *p_whi, *p_wlo;
    cudaGetSymbolAddress((void**)&p_emb, g_emb);
    cudaGetSymbolAddress((void**)&p_h1,  g_h1);
    cudaGetSymbolAddress((void**)&p_h2,  g_h2);
    cudaGetSymbolAddress((void**)&p_q,   g_q);
    cudaGetSymbolAddress((void**)&p_k,   g_k);
    cudaGetSymbolAddress((void**)&p_v,   g_v);
    cudaGetSymbolAddress((void**)&p_ahi, g_ahi);
    cudaGetSymbolAddress((void**)&p_alo, g_alo);
    cudaGetSymbolAddress((void**)&p_bhi, g_bhi);
    cudaGetSymbolAddress((void**)&p_blo, g_blo);
    cudaGetSymbolAddress((void**)&p_whi, g_whi);
    cudaGetSymbolAddress((void**)&p_wlo, g_wlo);

    __nv_bfloat16* qhi = (__nv_bfloat16*)p_q;
    __nv_bfloat16* qlo = qhi + (size_t)NTOK * DMODEL;
    __nv_bfloat16* khi = (__nv_bfloat16*)p_k;
    __nv_bfloat16* klo = khi + (size_t)NTOK * DMODEL;
    __nv_bfloat16* vhi = (__nv_bfloat16*)p_v;
    __nv_bfloat16* vlo = vhi + (size_t)NTOK * DMODEL;

    const size_t WSZ = (size_t)DMODEL * DMODEL;
    const int GEMM_SMEM = 8 * TILE_E * 2;   // 81920 bytes
    cudaFuncSetAttribute(gemm_split, cudaFuncAttributeMaxDynamicSharedMemorySize, GEMM_SMEM);
    const int asm128 = (6 * 64 * (128 + 8) + 2 * 64 * 72) * 2;   // 122880
    const int asm256 = (6 * 64 * (256 + 8) + 2 * 64 * 72) * 2;   // 221184
    cudaFuncSetAttribute(attn_tc<128>, cudaFuncAttributeMaxDynamicSharedMemorySize, asm128);
    cudaFuncSetAttribute(attn_tc<256>, cudaFuncAttributeMaxDynamicSharedMemorySize, asm256);

    detect_kernel<<<1, 256>>>((const int*)x);
    wtrans_all_kernel<<<dim3(32, 32, 8), dim3(32, 8)>>>(
        a1_qw, a1_kw, a1_vw, a1_pw, a2_qw, a2_kw, a2_vw, a2_pw, p_whi, p_wlo);
    embed_kernel<<<NTOK, 256>>>(x, emb_w, pos_w);

    dim3 gg(DMODEL / 128, NTOK / 128);

    // Layer 1 (8 heads, dh=128)
    gemm_split<<<gg, 256, GEMM_SMEM>>>(p_ahi, p_alo, p_whi + 0 * WSZ, p_wlo + 0 * WSZ,
                                       a1_qb, nullptr, nullptr, qhi, qlo);
    gemm_split<<<gg, 256, GEMM_SMEM>>>(p_ahi, p_alo, p_whi + 1 * WSZ, p_wlo + 1 * WSZ,
                                       a1_kb, nullptr, nullptr, khi, klo);
    gemm_split<<<gg, 256, GEMM_SMEM>>>(p_ahi, p_alo, p_whi + 2 * WSZ, p_wlo + 2 * WSZ,
                                       a1_vb, nullptr, nullptr, vhi, vlo);
    attn_tc<128><<<dim3(SEQ / 64, 8, BATCH), 256, asm128>>>(qhi, qlo, khi, klo, vhi, vlo,
                                                            x, p_bhi, p_blo);
    gemm_split<<<gg, 256, GEMM_SMEM>>>(p_bhi, p_blo, p_whi + 3 * WSZ, p_wlo + 3 * WSZ,
                                       a1_pb, p_emb, p_h1, p_ahi, p_alo);

    // Layer 2 (4 heads, dh=256)
    gemm_split<<<gg, 256, GEMM_SMEM>>>(p_ahi, p_alo, p_whi + 4 * WSZ, p_wlo + 4 * WSZ,
                                       a2_qb, nullptr, nullptr, qhi, qlo);
    gemm_split<<<gg, 256, GEMM_SMEM>>>(p_ahi, p_alo, p_whi + 5 * WSZ, p_wlo + 5 * WSZ,
                                       a2_kb, nullptr, nullptr, khi, klo);
    gemm_split<<<gg, 256, GEMM_SMEM>>>(p_ahi, p_alo, p_whi + 6 * WSZ, p_wlo + 6 * WSZ,
                                       a2_vb, nullptr, nullptr, vhi, vlo);
    attn_tc<256><<<dim3(SEQ / 64, 4, BATCH), 256, asm256>>>(qhi, qlo, khi, klo, vhi, vlo,
                                                            x, p_bhi, p_blo);
    gemm_split<<<gg, 256, GEMM_SMEM>>>(p_bhi, p_blo, p_whi + 7 * WSZ, p_wlo + 7 * WSZ,
                                       a2_pb, p_h1, p_h2, nullptr, nullptr);

    pool_kernel<<<dim3(DMODEL / 128, BATCH), 128>>>(x);
    lnlin_kernel<<<BATCH, 256>>>(norm_g, norm_b, lin_w, lin_b, out);
}

// round 10
// speedup vs baseline: 1.6266x; 1.6266x over previous
#include <cuda_runtime.h>
#include <cuda_bf16.h>
#include <cstdint>
#include <math.h>

#define DMODEL 1024
#define SEQ 512
#define BATCH 64
#define NTOK (BATCH * SEQ)

// ---------------- scratch (static device globals; no allocation) ----------------
__device__ float g_emb[(size_t)NTOK * DMODEL];
__device__ float g_h1[(size_t)NTOK * DMODEL];
__device__ float g_h2[(size_t)NTOK * DMODEL];
__device__ float g_q[(size_t)NTOK * DMODEL];   // reused as bf16 qhi/qlo halves
__device__ float g_k[(size_t)NTOK * DMODEL];   // khi/klo
__device__ float g_v[(size_t)NTOK * DMODEL];   // vhi/vlo
__device__ __nv_bfloat16 g_ahi[(size_t)NTOK * DMODEL];
__device__ __nv_bfloat16 g_alo[(size_t)NTOK * DMODEL];
__device__ __nv_bfloat16 g_bhi[(size_t)NTOK * DMODEL];
__device__ __nv_bfloat16 g_blo[(size_t)NTOK * DMODEL];
__device__ __nv_bfloat16 g_whi[(size_t)8 * DMODEL * DMODEL];
__device__ __nv_bfloat16 g_wlo[(size_t)8 * DMODEL * DMODEL];
__device__ float g_pooled[BATCH * DMODEL];
__device__ int g_is64;

// ---------------- helpers ----------------
__device__ __forceinline__ uint32_t smem_u32(const void* p) {
    uint32_t a;
    asm("{ .reg .u64 t; cvta.to.shared.u64 t, %1; cvt.u32.u64 %0, t; }" : "=r"(a) : "l"(p));
    return a;
}
__device__ __forceinline__ void cp_async16(uint32_t dst, const void* src) {
    asm volatile("cp.async.cg.shared.global [%0], [%1], 16;" :: "r"(dst), "l"(src));
}
__device__ __forceinline__ void ldsm_x4(uint32_t& r0, uint32_t& r1, uint32_t& r2, uint32_t& r3,
                                        uint32_t addr) {
    asm volatile("ldmatrix.sync.aligned.m8n8.x4.shared.b16 {%0,%1,%2,%3}, [%4];"
                 : "=r"(r0), "=r"(r1), "=r"(r2), "=r"(r3) : "r"(addr));
}
__device__ __forceinline__ void ldsm_x4t(uint32_t& r0, uint32_t& r1, uint32_t& r2, uint32_t& r3,
                                         uint32_t addr) {
    asm volatile("ldmatrix.sync.aligned.m8n8.x4.trans.shared.b16 {%0,%1,%2,%3}, [%4];"
                 : "=r"(r0), "=r"(r1), "=r"(r2), "=r"(r3) : "r"(addr));
}
__device__ __forceinline__ void mma_bf16(float& c0, float& c1, float& c2, float& c3,
                                         uint32_t a0, uint32_t a1, uint32_t a2, uint32_t a3,
                                         uint32_t b0, uint32_t b1) {
    asm volatile("mma.sync.aligned.m16n8k16.row.col.f32.bf16.bf16.f32 "
                 "{%0,%1,%2,%3}, {%4,%5,%6,%7}, {%8,%9}, {%0,%1,%2,%3};"
                 : "+f"(c0), "+f"(c1), "+f"(c2), "+f"(c3)
                 : "r"(a0), "r"(a1), "r"(a2), "r"(a3), "r"(b0), "r"(b1));
}
__device__ __forceinline__ void split_bf16(float v, __nv_bfloat16& hi, __nv_bfloat16& lo) {
    hi = __float2bfloat16_rn(v);
    lo = __float2bfloat16_rn(v - __bfloat162float(hi));
}
__device__ __forceinline__ float fast_exp(float x) {
    if (x < -80.f) return 0.f;
    float t = x * 1.4426950408889634f;
    float n = floorf(t + 0.5f);
    float g = (t - n) * 0.6931471805599453f;
    float p = 1.f + g * (1.f + g * (0.5f + g * (0.16666667f + g * (0.041666667f + g * 0.0083333f))));
    return __uint_as_float((uint32_t)(((int)n + 127) << 23)) * p;
}

// ---------------- dtype detection ----------------
__global__ void detect_kernel(const int* __restrict__ x) {
    __shared__ int any;
    if (threadIdx.x == 0) any = 0;
    __syncthreads();
    int local = 0;
    for (int i = threadIdx.x * 2 + 1; i < NTOK; i += blockDim.x * 2) local |= x[i];
    if (local) atomicOr(&any, 1);
    __syncthreads();
    if (threadIdx.x == 0) g_is64 = (any == 0) ? 1 : 0;
}
__device__ __forceinline__ long long get_id(const void* x, int i) {
    return g_is64 ? ((const long long*)x)[i] : (long long)((const int*)x)[i];
}

// ---------------- fused 8x weight transpose + bf16 hi/lo ----------------
__global__ void wtrans_all_kernel(
    const float* __restrict__ W0, const float* __restrict__ W1,
    const float* __restrict__ W2, const float* __restrict__ W3,
    const float* __restrict__ W4, const float* __restrict__ W5,
    const float* __restrict__ W6, const float* __restrict__ W7,
    __nv_bfloat16* __restrict__ WThi, __nv_bfloat16* __restrict__ WTlo) {
    __shared__ float t[32][33];
    int w = blockIdx.z;
    const float* W = (w == 0) ? W0 : (w == 1) ? W1 : (w == 2) ? W2 : (w == 3) ? W3
                   : (w == 4) ? W4 : (w == 5) ? W5 : (w == 6) ? W6 : W7;
    size_t wofs = (size_t)w * DMODEL * DMODEL;
    int n0 = blockIdx.x * 32, k0 = blockIdx.y * 32;
    int tx = threadIdx.x, ty = threadIdx.y;
#pragma unroll
    for (int i = 0; i < 4; i++)
        t[ty + 8 * i][tx] = W[(size_t)(k0 + ty + 8 * i) * DMODEL + n0 + tx];
    __syncthreads();
#pragma unroll
    for (int i = 0; i < 4; i++) {
        float v = t[tx][ty + 8 * i];
        __nv_bfloat16 hi, lo;
        split_bf16(v, hi, lo);
        size_t idx = wofs + (size_t)(n0 + ty + 8 * i) * DMODEL + k0 + tx;
        WThi[idx] = hi;
        WTlo[idx] = lo;
    }
}

// ---------------- embedding ----------------
__global__ void embed_kernel(const void* __restrict__ x,
                             const float* __restrict__ emb_w,
                             const float* __restrict__ pos_w) {
    int tok = blockIdx.x;
    int s = tok & (SEQ - 1);
    long long id = get_id(x, tok);
    const float4* ew = (const float4*)(emb_w + (size_t)id * DMODEL);
    const float4* pw = (const float4*)(pos_w + (size_t)s * DMODEL);
    float4* out = (float4*)(g_emb + (size_t)tok * DMODEL);
    __nv_bfloat16* ohi = g_ahi + (size_t)tok * DMODEL;
    __nv_bfloat16* olo = g_alo + (size_t)tok * DMODEL;
    for (int i = threadIdx.x; i < DMODEL / 4; i += blockDim.x) {
        float4 a = ew[i], b = pw[i];
        float4 o = make_float4(a.x + b.x, a.y + b.y, a.z + b.z, a.w + b.w);
        out[i] = o;
        __nv_bfloat16 h0, l0, h1, l1, h2, l2, h3, l3;
        split_bf16(o.x, h0, l0); split_bf16(o.y, h1, l1);
        split_bf16(o.z, h2, l2); split_bf16(o.w, h3, l3);
        ohi[4 * i + 0] = h0; ohi[4 * i + 1] = h1; ohi[4 * i + 2] = h2; ohi[4 * i + 3] = h3;
        olo[4 * i + 0] = l0; olo[4 * i + 1] = l1; olo[4 * i + 2] = l2; olo[4 * i + 3] = l3;
    }
}

// ---------------- 3-term split HMMA GEMM (R7 config: BK=32, per-call addressing) ----------------
#define BKD 32
#define SSTR 40
#define TILE_E (128 * SSTR)
__global__ __launch_bounds__(256) void gemm_split(
    const __nv_bfloat16* __restrict__ Ahi, const __nv_bfloat16* __restrict__ Alo,
    const __nv_bfloat16* __restrict__ Bhi, const __nv_bfloat16* __restrict__ Blo,
    const float* __restrict__ bias, const float* __restrict__ res,
    float* __restrict__ C, __nv_bfloat16* __restrict__ Chi, __nv_bfloat16* __restrict__ Clo) {
    extern __shared__ __nv_bfloat16 smem[];
    __nv_bfloat16* sAhi[2] = {smem + 0 * TILE_E, smem + 1 * TILE_E};
    __nv_bfloat16* sAlo[2] = {smem + 2 * TILE_E, smem + 3 * TILE_E};
    __nv_bfloat16* sBhi[2] = {smem + 4 * TILE_E, smem + 5 * TILE_E};
    __nv_bfloat16* sBlo[2] = {smem + 6 * TILE_E, smem + 7 * TILE_E};

    int tid = threadIdx.x, wid = tid >> 5, lane = tid & 31;
    int bn = blockIdx.x, bm = blockIdx.y;
    int wm = (wid >> 1) * 32;
    int wn = (wid & 1) * 64;

    float acc[2][8][4];
#pragma unroll
    for (int i = 0; i < 2; i++)
#pragma unroll
        for (int j = 0; j < 8; j++)
#pragma unroll
            for (int k = 0; k < 4; k++) acc[i][j][k] = 0.f;

    int lrow = tid >> 1;
    int lc0 = (tid & 1) * 2;
    const __nv_bfloat16* gAhi = Ahi + (size_t)(bm * 128 + lrow) * DMODEL;
    const __nv_bfloat16* gAlo = Alo + (size_t)(bm * 128 + lrow) * DMODEL;
    const __nv_bfloat16* gBhi = Bhi + (size_t)(bn * 128 + lrow) * DMODEL;
    const __nv_bfloat16* gBlo = Blo + (size_t)(bn * 128 + lrow) * DMODEL;
    uint32_t rowoff = lrow * SSTR * 2;
    uint32_t dAhi[2], dAlo[2], dBhi[2], dBlo[2];
#pragma unroll
    for (int b = 0; b < 2; b++) {
        dAhi[b] = smem_u32(sAhi[b]) + rowoff;
        dAlo[b] = smem_u32(sAlo[b]) + rowoff;
        dBhi[b] = smem_u32(sBhi[b]) + rowoff;
        dBlo[b] = smem_u32(sBlo[b]) + rowoff;
    }

#define LOAD_TILE(buf, k0) do { \
    cp_async16(dAhi[buf] + (lc0 + 0) * 16, gAhi + (k0) + (lc0 + 0) * 8); \
    cp_async16(dAhi[buf] + (lc0 + 1) * 16, gAhi + (k0) + (lc0 + 1) * 8); \
    cp_async16(dAlo[buf] + (lc0 + 0) * 16, gAlo + (k0) + (lc0 + 0) * 8); \
    cp_async16(dAlo[buf] + (lc0 + 1) * 16, gAlo + (k0) + (lc0 + 1) * 8); \
    cp_async16(dBhi[buf] + (lc0 + 0) * 16, gBhi + (k0) + (lc0 + 0) * 8); \
    cp_async16(dBhi[buf] + (lc0 + 1) * 16, gBhi + (k0) + (lc0 + 1) * 8); \
    cp_async16(dBlo[buf] + (lc0 + 0) * 16, gBlo + (k0) + (lc0 + 0) * 8); \
    cp_async16(dBlo[buf] + (lc0 + 1) * 16, gBlo + (k0) + (lc0 + 1) * 8); \
    asm volatile("cp.async.commit_group;"); \
} while (0)

    LOAD_TILE(0, 0);
    LOAD_TILE(1, BKD);

    int g = lane >> 3, r = lane & 7;
    int rofs = (g & 1) * 8 + r;
    int kofs = (g >> 1) * 8;

    const int NIT = DMODEL / BKD;
    for (int it = 0; it < NIT; it++) {
        int buf = it & 1;
        if (it + 2 < NIT)
            asm volatile("cp.async.wait_group 1;" ::: "memory");
        else
            asm volatile("cp.async.wait_group 0;" ::: "memory");
        __syncthreads();

#pragma unroll
        for (int kk = 0; kk < 2; kk++) {
            int kb = kk * 16 + kofs;
            uint32_t aH[2][4];
#pragma unroll
            for (int mt = 0; mt < 2; mt++)
                ldsm_x4(aH[mt][0], aH[mt][1], aH[mt][2], aH[mt][3],
                        smem_u32(sAhi[buf] + (wm + mt * 16 + rofs) * SSTR + kb));
            uint32_t bF[8][2];
#pragma unroll
            for (int np = 0; np < 4; np++) {
                uint32_t r0, r1, r2, r3;
                ldsm_x4(r0, r1, r2, r3,
                        smem_u32(sBhi[buf] + (wn + np * 16 + rofs) * SSTR + kb));
                bF[np * 2 + 0][0] = r0; bF[np * 2 + 0][1] = r2;
                bF[np * 2 + 1][0] = r1; bF[np * 2 + 1][1] = r3;
            }
#pragma unroll
            for (int mt = 0; mt < 2; mt++)
#pragma unroll
                for (int nt = 0; nt < 8; nt++)
                    mma_bf16(acc[mt][nt][0], acc[mt][nt][1], acc[mt][nt][2], acc[mt][nt][3],
                             aH[mt][0], aH[mt][1], aH[mt][2], aH[mt][3],
                             bF[nt][0], bF[nt][1]);
            {
                uint32_t aL[2][4];
#pragma unroll
                for (int mt = 0; mt < 2; mt++)
                    ldsm_x4(aL[mt][0], aL[mt][1], aL[mt][2], aL[mt][3],
                            smem_u32(sAlo[buf] + (wm + mt * 16 + rofs) * SSTR + kb));
#pragma unroll
                for (int mt = 0; mt < 2; mt++)
#pragma unroll
                    for (int nt = 0; nt < 8; nt++)
                        mma_bf16(acc[mt][nt][0], acc[mt][nt][1], acc[mt][nt][2], acc[mt][nt][3],
                                 aL[mt][0], aL[mt][1], aL[mt][2], aL[mt][3],
                                 bF[nt][0], bF[nt][1]);
            }
#pragma unroll
            for (int np = 0; np < 4; np++) {
                uint32_t r0, r1, r2, r3;
                ldsm_x4(r0, r1, r2, r3,
                        smem_u32(sBlo[buf] + (wn + np * 16 + rofs) * SSTR + kb));
                bF[np * 2 + 0][0] = r0; bF[np * 2 + 0][1] = r2;
                bF[np * 2 + 1][0] = r1; bF[np * 2 + 1][1] = r3;
            }
#pragma unroll
            for (int mt = 0; mt < 2; mt++)
#pragma unroll
                for (int nt = 0; nt < 8; nt++)
                    mma_bf16(acc[mt][nt][0], acc[mt][nt][1], acc[mt][nt][2], acc[mt][nt][3],
                             aH[mt][0], aH[mt][1], aH[mt][2], aH[mt][3],
                             bF[nt][0], bF[nt][1]);
        }
        __syncthreads();
        if (it + 2 < NIT) LOAD_TILE(buf, (it + 2) * BKD);
    }
#undef LOAD_TILE

    int gid = lane >> 2, tig = lane & 3;
#pragma unroll
    for (int mt = 0; mt < 2; mt++) {
#pragma unroll
        for (int half = 0; half < 2; half++) {
            int m = bm * 128 + wm + mt * 16 + gid + half * 8;
            float* crow = C ? C + (size_t)m * DMODEL : nullptr;
            const float* rrow = res ? res + (size_t)m * DMODEL : nullptr;
            __nv_bfloat16* hrow = Chi ? Chi + (size_t)m * DMODEL : nullptr;
            __nv_bfloat16* lrow2 = Clo ? Clo + (size_t)m * DMODEL : nullptr;
#pragma unroll
            for (int nt = 0; nt < 8; nt++) {
                int ncol = bn * 128 + wn + nt * 8 + tig * 2;
                float v0 = acc[mt][nt][half * 2 + 0] + bias[ncol];
                float v1 = acc[mt][nt][half * 2 + 1] + bias[ncol + 1];
                if (rrow) { v0 += rrow[ncol]; v1 += rrow[ncol + 1]; }
                if (crow) *(float2*)(crow + ncol) = make_float2(v0, v1);
                if (hrow) {
                    __nv_bfloat16 h0, l0, h1, l1;
                    split_bf16(v0, h0, l0);
                    split_bf16(v1, h1, l1);
                    hrow[ncol] = h0; hrow[ncol + 1] = h1;
                    lrow2[ncol] = l0; lrow2[ncol + 1] = l1;
                }
            }
        }
    }
}

// ---------------- tensor-core flash attention (3-term bf16 split) ----------------
template <int DH>
__global__ __launch_bounds__(256) void attn_tc(
    const __nv_bfloat16* __restrict__ Qhi, const __nv_bfloat16* __restrict__ Qlo,
    const __nv_bfloat16* __restrict__ Khi, const __nv_bfloat16* __restrict__ Klo,
    const __nv_bfloat16* __restrict__ Vhi, const __nv_bfloat16* __restrict__ Vlo,
    const void* __restrict__ xids,
    __nv_bfloat16* __restrict__ Ohi, __nv_bfloat16* __restrict__ Olo) {
    extern __shared__ __nv_bfloat16 smb[];
    const int SSTRA = DH + 8;
    const int PSTR = 72;
    __nv_bfloat16* qhi_s = smb;
    __nv_bfloat16* qlo_s = qhi_s + 64 * SSTRA;
    __nv_bfloat16* khi_s = qlo_s + 64 * SSTRA;
    __nv_bfloat16* klo_s = khi_s + 64 * SSTRA;
    __nv_bfloat16* vhi_s = klo_s + 64 * SSTRA;
    __nv_bfloat16* vlo_s = vhi_s + 64 * SSTRA;
    __nv_bfloat16* phi_s = vlo_s + 64 * SSTRA;
    __nv_bfloat16* plo_s = phi_s + 64 * PSTR;
    __shared__ int msk[64];
    __shared__ float rmaxs[64][2], psumw[64][2];
    __shared__ float m_state[64], m_next[64], l_state[64], fac[64];

    int qt = blockIdx.x, h = blockIdx.y, b = blockIdx.z;
    int tid = threadIdx.x, wid = tid >> 5, lane = tid & 31;
    int mt = wid >> 1, nh = wid & 1;
    float scale = rsqrtf((float)DH);
    int q0 = qt * 64;
    int gg = lane >> 3, rr8 = lane & 7;
    int rofs = (gg & 1) * 8 + rr8, kofs = (gg >> 1) * 8;
    int rowA = mt * 16 + (lane >> 2), rowB = rowA + 8;
    int colq = (lane & 3) * 2;
    const int CHK = DH / 8;
    const int NG = DH / 16;

    for (int i = tid; i < 64 * CHK; i += 256) {
        int r = i / CHK, c = i % CHK;
        size_t gi = (size_t)(b * SEQ + q0 + r) * DMODEL + h * DH + c * 8;
        *(uint4*)(qhi_s + r * SSTRA + c * 8) = *(const uint4*)(Qhi + gi);
        *(uint4*)(qlo_s + r * SSTRA + c * 8) = *(const uint4*)(Qlo + gi);
    }
    if (tid < 64) { m_state[tid] = -1e30f; l_state[tid] = 0.f; }

    float o[NG][4];
#pragma unroll
    for (int i = 0; i < NG; i++) { o[i][0] = 0.f; o[i][1] = 0.f; o[i][2] = 0.f; o[i][3] = 0.f; }

    int is64 = g_is64;

    for (int kt = 0; kt < SEQ / 64; kt++) {
        int k0 = kt * 64;
        __syncthreads();
        for (int i = tid; i < 64 * CHK; i += 256) {
            int r = i / CHK, c = i % CHK;
            size_t gi = (size_t)(b * SEQ + k0 + r) * DMODEL + h * DH + c * 8;
            *(uint4*)(khi_s + r * SSTRA + c * 8) = *(const uint4*)(Khi + gi);
            *(uint4*)(klo_s + r * SSTRA + c * 8) = *(const uint4*)(Klo + gi);
            *(uint4*)(vhi_s + r * SSTRA + c * 8) = *(const uint4*)(Vhi + gi);
            *(uint4*)(vlo_s + r * SSTRA + c * 8) = *(const uint4*)(Vlo + gi);
        }
        if (tid < 64) {
            long long idv = is64 ? ((const long long*)xids)[b * SEQ + k0 + tid]
                                 : (long long)((const int*)xids)[b * SEQ + k0 + tid];
            msk[tid] = (idv != 0) ? 1 : 0;
        }
        __syncthreads();

        // ---- phase A: scores via 3-term HMMA ----
        float sc[4][4];
#pragma unroll
        for (int gq = 0; gq < 4; gq++) { sc[gq][0] = 0.f; sc[gq][1] = 0.f; sc[gq][2] = 0.f; sc[gq][3] = 0.f; }
#pragma unroll
        for (int ks = 0; ks < DH / 16; ks++) {
            uint32_t aH[4], aL[4];
            ldsm_x4(aH[0], aH[1], aH[2], aH[3],
                    smem_u32(qhi_s + (mt * 16 + rofs) * SSTRA + ks * 16 + kofs));
            ldsm_x4(aL[0], aL[1], aL[2], aL[3],
                    smem_u32(qlo_s + (mt * 16 + rofs) * SSTRA + ks * 16 + kofs));
            uint32_t bH[4][2], bL[4][2];
#pragma unroll
            for (int kg = 0; kg < 2; kg++) {
                uint32_t r0, r1, r2, r3;
                ldsm_x4(r0, r1, r2, r3,
                        smem_u32(khi_s + (nh * 32 + kg * 16 + rofs) * SSTRA + ks * 16 + kofs));
                bH[kg * 2 + 0][0] = r0; bH[kg * 2 + 0][1] = r2;
                bH[kg * 2 + 1][0] = r1; bH[kg * 2 + 1][1] = r3;
                ldsm_x4(r0, r1, r2, r3,
                        smem_u32(klo_s + (nh * 32 + kg * 16 + rofs) * SSTRA + ks * 16 + kofs));
                bL[kg * 2 + 0][0] = r0; bL[kg * 2 + 0][1] = r2;
                bL[kg * 2 + 1][0] = r1; bL[kg * 2 + 1][1] = r3;
            }
#pragma unroll
            for (int gq = 0; gq < 4; gq++) {
                mma_bf16(sc[gq][0], sc[gq][1], sc[gq][2], sc[gq][3],
                         aH[0], aH[1], aH[2], aH[3], bH[gq][0], bH[gq][1]);
                mma_bf16(sc[gq][0], sc[gq][1], sc[gq][2], sc[gq][3],
                         aL[0], aL[1], aL[2], aL[3], bH[gq][0], bH[gq][1]);
                mma_bf16(sc[gq][0], sc[gq][1], sc[gq][2], sc[gq][3],
                         aH[0], aH[1], aH[2], aH[3], bL[gq][0], bL[gq][1]);
            }
        }

        // mask + scale, row max
        float mA = -1e30f, mB = -1e30f;
#pragma unroll
        for (int gq = 0; gq < 4; gq++) {
            int cb = nh * 32 + gq * 8 + colq;
            bool k0m = msk[cb] != 0, k1m = msk[cb + 1] != 0;
            sc[gq][0] = k0m ? sc[gq][0] * scale : -1e30f;
            sc[gq][1] = k1m ? sc[gq][1] * scale : -1e30f;
            sc[gq][2] = k0m ? sc[gq][2] * scale : -1e30f;
            sc[gq][3] = k1m ? sc[gq][3] * scale : -1e30f;
            mA = fmaxf(mA, fmaxf(sc[gq][0], sc[gq][1]));
            mB = fmaxf(mB, fmaxf(sc[gq][2], sc[gq][3]));
        }
        mA = fmaxf(mA, __shfl_xor_sync(0xFFFFFFFF, mA, 1));
        mA = fmaxf(mA, __shfl_xor_sync(0xFFFFFFFF, mA, 2));
        mB = fmaxf(mB, __shfl_xor_sync(0xFFFFFFFF, mB, 1));
        mB = fmaxf(mB, __shfl_xor_sync(0xFFFFFFFF, mB, 2));
        if ((lane & 3) == 0) { rmaxs[rowA][nh] = mA; rmaxs[rowB][nh] = mB; }
        __syncthreads();
        if (nh == 0 && (lane & 3) == 0) {
#pragma unroll
            for (int rr = 0; rr < 2; rr++) {
                int rw = rr ? rowB : rowA;
                float rm = fmaxf(rmaxs[rw][0], rmaxs[rw][1]);
                float mold = m_state[rw];
                float mnew = fmaxf(mold, rm);
                m_next[rw] = mnew;
                fac[rw] = (mold < -1e29f) ? 0.f : fast_exp(mold - mnew);
            }
        }
        __syncthreads();

        // exp + P hi/lo write + partial sums
        float mnA = m_next[rowA], mnB = m_next[rowB];
        float sumA = 0.f, sumB = 0.f;
#pragma unroll
        for (int gq = 0; gq < 4; gq++) {
            int cb = nh * 32 + gq * 8 + colq;
            float p0 = (sc[gq][0] > -1e29f) ? fast_exp(sc[gq][0] - mnA) : 0.f;
            float p1 = (sc[gq][1] > -1e29f) ? fast_exp(sc[gq][1] - mnA) : 0.f;
            float p2 = (sc[gq][2] > -1e29f) ? fast_exp(sc[gq][2] - mnB) : 0.f;
            float p3 = (sc[gq][3] > -1e29f) ? fast_exp(sc[gq][3] - mnB) : 0.f;
            sumA += p0 + p1; sumB += p2 + p3;
            __nv_bfloat16 h0, l0, h1, l1;
            split_bf16(p0, h0, l0); split_bf16(p1, h1, l1);
            *(__nv_bfloat162*)(phi_s + rowA * PSTR + cb) = __nv_bfloat162(h0, h1);
            *(__nv_bfloat162*)(plo_s + rowA * PSTR + cb) = __nv_bfloat162(l0, l1);
            split_bf16(p2, h0, l0); split_bf16(p3, h1, l1);
            *(__nv_bfloat162*)(phi_s + rowB * PSTR + cb) = __nv_bfloat162(h0, h1);
            *(__nv_bfloat162*)(plo_s + rowB * PSTR + cb) = __nv_bfloat162(l0, l1);
        }
        sumA += __shfl_xor_sync(0xFFFFFFFF, sumA, 1);
        sumA += __shfl_xor_sync(0xFFFFFFFF, sumA, 2);
        sumB += __shfl_xor_sync(0xFFFFFFFF, sumB, 1);
        sumB += __shfl_xor_sync(0xFFFFFFFF, sumB, 2);
        if ((lane & 3) == 0) { psumw[rowA][nh] = sumA; psumw[rowB][nh] = sumB; }
        __syncthreads();
        if (nh == 0 && (lane & 3) == 0) {
#pragma unroll
            for (int rr = 0; rr < 2; rr++) {
                int rw = rr ? rowB : rowA;
                l_state[rw] = l_state[rw] * fac[rw] + psumw[rw][0] + psumw[rw][1];
                m_state[rw] = m_next[rw];
            }
        }

        // ---- phase C: O += P @ V via 3-term HMMA ----
        float fA = fac[rowA], fB = fac[rowB];
#pragma unroll
        for (int gq = 0; gq < NG; gq++) {
            o[gq][0] *= fA; o[gq][1] *= fA; o[gq][2] *= fB; o[gq][3] *= fB;
        }
#pragma unroll
        for (int ksv = 0; ksv < 4; ksv++) {
            uint32_t pH[4], pL[4];
            ldsm_x4(pH[0], pH[1], pH[2], pH[3],
                    smem_u32(phi_s + (mt * 16 + rofs) * PSTR + ksv * 16 + kofs));
            ldsm_x4(pL[0], pL[1], pL[2], pL[3],
                    smem_u32(plo_s + (mt * 16 + rofs) * PSTR + ksv * 16 + kofs));
            int vrow = ksv * 16 + rr8 + ((lane >> 4) << 3);
            int vcb = nh * (DH / 2) + ((lane >> 3) & 1) * 8;
#pragma unroll
            for (int vg = 0; vg < NG / 2; vg++) {
                uint32_t r0, r1, r2, r3;
                ldsm_x4t(r0, r1, r2, r3,
                         smem_u32(vhi_s + vrow * SSTRA + vcb + vg * 16));
                uint32_t bH0[2] = {r0, r2}, bH1[2] = {r1, r3};
                ldsm_x4t(r0, r1, r2, r3,
                         smem_u32(vlo_s + vrow * SSTRA + vcb + vg * 16));
                uint32_t bL0[2] = {r0, r2}, bL1[2] = {r1, r3};
                int g0 = vg * 2, g1 = vg * 2 + 1;
                mma_bf16(o[g0][0], o[g0][1], o[g0][2], o[g0][3],
                         pH[0], pH[1], pH[2], pH[3], bH0[0], bH0[1]);
                mma_bf16(o[g1][0], o[g1][1], o[g1][2], o[g1][3],
                         pH[0], pH[1], pH[2], pH[3], bH1[0], bH1[1]);
                mma_bf16(o[g0][0], o[g0][1], o[g0][2], o[g0][3],
                         pL[0], pL[1], pL[2], pL[3], bH0[0], bH0[1]);
                mma_bf16(o[g1][0], o[g1][1], o[g1][2], o[g1][3],
                         pL[0], pL[1], pL[2], pL[3], bH1[0], bH1[1]);
                mma_bf16(o[g0][0], o[g0][1], o[g0][2], o[g0][3],
                         pH[0], pH[1], pH[2], pH[3], bL0[0], bL0[1]);
                mma_bf16(o[g1][0], o[g1][1], o[g1][2], o[g1][3],
                         pH[0], pH[1], pH[2], pH[3], bL1[0], bL1[1]);
            }
        }
    }
    __syncthreads();

    float invA = 1.0f / fmaxf(l_state[rowA], 1e-20f);
    float invB = 1.0f / fmaxf(l_state[rowB], 1e-20f);
    size_t bA = (size_t)(b * SEQ + q0 + rowA) * DMODEL;
    size_t bB = (size_t)(b * SEQ + q0 + rowB) * DMODEL;
#pragma unroll
    for (int gq = 0; gq < NG; gq++) {
        int cb = h * DH + nh * (DH / 2) + gq * 8 + colq;
        float v0 = o[gq][0] * invA, v1 = o[gq][1] * invA;
        float v2 = o[gq][2] * invB, v3 = o[gq][3] * invB;
        __nv_bfloat16 h0, l0, h1, l1;
        split_bf16(v0, h0, l0); split_bf16(v1, h1, l1);
        *(__nv_bfloat162*)(Ohi + bA + cb) = __nv_bfloat162(h0, h1);
        *(__nv_bfloat162*)(Olo + bA + cb) = __nv_bfloat162(l0, l1);
        split_bf16(v2, h0, l0); split_bf16(v3, h1, l1);
        *(__nv_bfloat162*)(Ohi + bB + cb) = __nv_bfloat162(h0, h1);
        *(__nv_bfloat162*)(Olo + bB + cb) = __nv_bfloat162(l0, l1);
    }
}

// ---------------- masked mean pooling of (g_h2 + g_emb) ----------------
__global__ void pool_kernel(const void* __restrict__ xids) {
    int b = blockIdx.y;
    int col = blockIdx.x * 128 + threadIdx.x;
    __shared__ int smask[SEQ];
    int is64 = g_is64;
    for (int s = threadIdx.x; s < SEQ; s += 128) {
        long long idv = is64 ? ((const long long*)xids)[b * SEQ + s]
                             : (long long)((const int*)xids)[b * SEQ + s];
        smask[s] = (idv != 0) ? 1 : 0;
    }
    __syncthreads();
    float acc = 0.f;
    int cnt = 0;
    for (int s = 0; s < SEQ; s++) {
        if (smask[s]) {
            size_t idx = (size_t)(b * SEQ + s) * DMODEL + col;
            acc += g_h2[idx] + g_emb[idx];
            cnt++;
        }
    }
    g_pooled[b * DMODEL + col] = acc / (float)cnt;
}

// ---------------- LayerNorm + linear head ----------------
__global__ void lnlin_kernel(const float* __restrict__ ng, const float* __restrict__ nb,
                             const float* __restrict__ lw, const float* __restrict__ lb,
                             float* __restrict__ out) {
    int b = blockIdx.x, tid = threadIdx.x;
    __shared__ float red[256];
    float x[4];
    float s = 0.f;
#pragma unroll
    for (int k = 0; k < 4; k++) {
        x[k] = g_pooled[b * DMODEL + tid + k * 256];
        s += x[k];
    }
    red[tid] = s; __syncthreads();
    for (int st = 128; st > 0; st >>= 1) { if (tid < st) red[tid] += red[tid + st]; __syncthreads(); }
    float mu = red[0] / (float)DMODEL;
    __syncthreads();
    float s2 = 0.f;
#pragma unroll
    for (int k = 0; k < 4; k++) { float d = x[k] - mu; s2 += d * d; }
    red[tid] = s2; __syncthreads();
    for (int st = 128; st > 0; st >>= 1) { if (tid < st) red[tid] += red[tid + st]; __syncthreads(); }
    float var = red[0] / (float)DMODEL;
    float rstd = rsqrtf(var + 1e-5f);
    __syncthreads();
    float acc = 0.f;
#pragma unroll
    for (int k = 0; k < 4; k++) {
        int col = tid + k * 256;
        acc += ((x[k] - mu) * rstd * ng[col] + nb[col]) * lw[col];
    }
    red[tid] = acc; __syncthreads();
    for (int st = 128; st > 0; st >>= 1) { if (tid < st) red[tid] += red[tid + st]; __syncthreads(); }
    if (tid == 0) out[b] = red[0] + lb[0];
}

// ---------------- launch ----------------
extern "C" void kernel_launch(void* const* d_in, const int* in_sizes, int n_in,
                              void* d_out, int out_size) {
    const void*  x      = d_in[0];
    const float* emb_w  = (const float*)d_in[1];
    const float* pos_w  = (const float*)d_in[2];
    const float* a1_qw  = (const float*)d_in[3];
    const float* a1_qb  = (const float*)d_in[4];
    const float* a1_kw  = (const float*)d_in[5];
    const float* a1_kb  = (const float*)d_in[6];
    const float* a1_vw  = (const float*)d_in[7];
    const float* a1_vb  = (const float*)d_in[8];
    const float* a1_pw  = (const float*)d_in[9];
    const float* a1_pb  = (const float*)d_in[10];
    const float* a2_qw  = (const float*)d_in[11];
    const float* a2_qb  = (const float*)d_in[12];
    const float* a2_kw  = (const float*)d_in[13];
    const float* a2_kb  = (const float*)d_in[14];
    const float* a2_vw  = (const float*)d_in[15];
    const float* a2_vb  = (const float*)d_in[16];
    const float* a2_pw  = (const float*)d_in[17];
    const float* a2_pb  = (const float*)d_in[18];
    const float* norm_g = (const float*)d_in[19];
    const float* norm_b = (const float*)d_in[20];
    const float* lin_w  = (const float*)d_in[21];
    const float* lin_b  = (const float*)d_in[22];
    float* out = (float*)d_out;

    float *p_emb, *p_h1, *p_h2, *p_q, *p_k, *p_v;
    __nv_bfloat16 *p_ahi, *p_alo, *p_bhi, *p_blo, *p_whi, *p_wlo;
    cudaGetSymbolAddress((void**)&p_emb, g_emb);
    cudaGetSymbolAddress((void**)&p_h1,  g_h1);
    cudaGetSymbolAddress((void**)&p_h2,  g_h2);
    cudaGetSymbolAddress((void**)&p_q,   g_q);
    cudaGetSymbolAddress((void**)&p_k,   g_k);
    cudaGetSymbolAddress((void**)&p_v,   g_v);
    cudaGetSymbolAddress((void**)&p_ahi, g_ahi);
    cudaGetSymbolAddress((void**)&p_alo, g_alo);
    cudaGetSymbolAddress((void**)&p_bhi, g_bhi);
    cudaGetSymbolAddress((void**)&p_blo, g_blo);
    cudaGetSymbolAddress((void**)&p_whi, g_whi);
    cudaGetSymbolAddress((void**)&p_wlo, g_wlo);

    __nv_bfloat16* qhi = (__nv_bfloat16*)p_q;
    __nv_bfloat16* qlo = qhi + (size_t)NTOK * DMODEL;
    __nv_bfloat16* khi = (__nv_bfloat16*)p_k;
    __nv_bfloat16* klo = khi + (size_t)NTOK * DMODEL;
    __nv_bfloat16* vhi = (__nv_bfloat16*)p_v;
    __nv_bfloat16* vlo = vhi + (size_t)NTOK * DMODEL;

    const size_t WSZ = (size_t)DMODEL * DMODEL;
    const int GEMM_SMEM = 8 * TILE_E * 2;   // 81920 bytes
    cudaFuncSetAttribute(gemm_split, cudaFuncAttributeMaxDynamicSharedMemorySize, GEMM_SMEM);
    const int asm128 = (6 * 64 * (128 + 8) + 2 * 64 * 72) * 2;   // 122880
    const int asm256 = (6 * 64 * (256 + 8) + 2 * 64 * 72) * 2;   // 221184
    cudaFuncSetAttribute(attn_tc<128>, cudaFuncAttributeMaxDynamicSharedMemorySize, asm128);
    cudaFuncSetAttribute(attn_tc<256>, cudaFuncAttributeMaxDynamicSharedMemorySize, asm256);

    detect_kernel<<<1, 256>>>((const int*)x);
    wtrans_all_kernel<<<dim3(32, 32, 8), dim3(32, 8)>>>(
        a1_qw, a1_kw, a1_vw, a1_pw, a2_qw, a2_kw, a2_vw, a2_pw, p_whi, p_wlo);
    embed_kernel<<<NTOK, 256>>>(x, emb_w, pos_w);

    dim3 gg(DMODEL / 128, NTOK / 128);

    // Layer 1 (8 heads, dh=128)
    gemm_split<<<gg, 256, GEMM_SMEM>>>(p_ahi, p_alo, p_whi + 0 * WSZ, p_wlo + 0 * WSZ,
                                       a1_qb, nullptr, nullptr, qhi, qlo);
    gemm_split<<<gg, 256, GEMM_SMEM>>>(p_ahi, p_alo, p_whi + 1 * WSZ, p_wlo + 1 * WSZ,
                                       a1_kb, nullptr, nullptr, khi, klo);
    gemm_split<<<gg, 256, GEMM_SMEM>>>(p_ahi, p_alo, p_whi + 2 * WSZ, p_wlo + 2 * WSZ,
                                       a1_vb, nullptr, nullptr, vhi, vlo);
    attn_tc<128><<<dim3(SEQ / 64, 8, BATCH), 256, asm128>>>(qhi, qlo, khi, klo, vhi, vlo,
                                                            x, p_bhi, p_blo);
    gemm_split<<<gg, 256, GEMM_SMEM>>>(p_bhi, p_blo, p_whi + 3 * WSZ, p_wlo + 3 * WSZ,
                                       a1_pb, p_emb, p_h1, p_ahi, p_alo);

    // Layer 2 (4 heads, dh=256)
    gemm_split<<<gg, 256, GEMM_SMEM>>>(p_ahi, p_alo, p_whi + 4 * WSZ, p_wlo + 4 * WSZ,
                                       a2_qb, nullptr, nullptr, qhi, qlo);
    gemm_split<<<gg, 256, GEMM_SMEM>>>(p_ahi, p_alo, p_whi + 5 * WSZ, p_wlo + 5 * WSZ,
                                       a2_kb, nullptr, nullptr, khi, klo);
    gemm_split<<<gg, 256, GEMM_SMEM>>>(p_ahi, p_alo, p_whi + 6 * WSZ, p_wlo + 6 * WSZ,
                                       a2_vb, nullptr, nullptr, vhi, vlo);
    attn_tc<256><<<dim3(SEQ / 64, 4, BATCH), 256, asm256>>>(qhi, qlo, khi, klo, vhi, vlo,
                                                            x, p_bhi, p_blo);
    gemm_split<<<gg, 256, GEMM_SMEM>>>(p_bhi, p_blo, p_whi + 7 * WSZ, p_wlo + 7 * WSZ,
                                       a2_pb, p_h1, p_h2, nullptr, nullptr);

    pool_kernel<<<dim3(DMODEL / 128, BATCH), 128>>>(x);
    lnlin_kernel<<<BATCH, 256>>>(norm_g, norm_b, lin_w, lin_b, out);
}

// round 11
// speedup vs baseline: 1.7722x; 1.0895x over previous
#include <cuda_runtime.h>
#include <cuda_bf16.h>
#include <cstdint>
#include <math.h>

#define DMODEL 1024
#define DPAIR (2 * DMODEL)          // paired-row stride: [hi 1024 | lo 1024]
#define SEQ 512
#define BATCH 64
#define NTOK (BATCH * SEQ)

// ---------------- scratch (static device globals; no allocation) ----------------
__device__ float g_emb[(size_t)NTOK * DMODEL];
__device__ float g_h1[(size_t)NTOK * DMODEL];
__device__ float g_h2[(size_t)NTOK * DMODEL];
__device__ float g_q[(size_t)NTOK * DMODEL];   // bf16 paired rows (NTOK x DPAIR)
__device__ float g_k[(size_t)NTOK * DMODEL];
__device__ float g_v[(size_t)NTOK * DMODEL];
__device__ __nv_bfloat16 g_abuf[(size_t)NTOK * DPAIR];   // activation pairs (A operand)
__device__ __nv_bfloat16 g_bbuf[(size_t)NTOK * DPAIR];   // activation pairs (attn out)
__device__ __nv_bfloat16 g_wbuf[(size_t)8 * DMODEL * DPAIR];  // 8 weight slots, paired rows
__device__ float g_pooled[BATCH * DMODEL];
__device__ int g_is64;

// ---------------- helpers ----------------
__device__ __forceinline__ uint32_t smem_u32(const void* p) {
    uint32_t a;
    asm("{ .reg .u64 t; cvta.to.shared.u64 t, %1; cvt.u32.u64 %0, t; }" : "=r"(a) : "l"(p));
    return a;
}
__device__ __forceinline__ void cp_async16(uint32_t dst, const void* src) {
    asm volatile("cp.async.cg.shared.global [%0], [%1], 16;" :: "r"(dst), "l"(src));
}
__device__ __forceinline__ void ldsm_x4(uint32_t& r0, uint32_t& r1, uint32_t& r2, uint32_t& r3,
                                        uint32_t addr) {
    asm volatile("ldmatrix.sync.aligned.m8n8.x4.shared.b16 {%0,%1,%2,%3}, [%4];"
                 : "=r"(r0), "=r"(r1), "=r"(r2), "=r"(r3) : "r"(addr));
}
__device__ __forceinline__ void ldsm_x4t(uint32_t& r0, uint32_t& r1, uint32_t& r2, uint32_t& r3,
                                         uint32_t addr) {
    asm volatile("ldmatrix.sync.aligned.m8n8.x4.trans.shared.b16 {%0,%1,%2,%3}, [%4];"
                 : "=r"(r0), "=r"(r1), "=r"(r2), "=r"(r3) : "r"(addr));
}
__device__ __forceinline__ void mma_bf16(float& c0, float& c1, float& c2, float& c3,
                                         uint32_t a0, uint32_t a1, uint32_t a2, uint32_t a3,
                                         uint32_t b0, uint32_t b1) {
    asm volatile("mma.sync.aligned.m16n8k16.row.col.f32.bf16.bf16.f32 "
                 "{%0,%1,%2,%3}, {%4,%5,%6,%7}, {%8,%9}, {%0,%1,%2,%3};"
                 : "+f"(c0), "+f"(c1), "+f"(c2), "+f"(c3)
                 : "r"(a0), "r"(a1), "r"(a2), "r"(a3), "r"(b0), "r"(b1));
}
__device__ __forceinline__ void split_bf16(float v, __nv_bfloat16& hi, __nv_bfloat16& lo) {
    hi = __float2bfloat16_rn(v);
    lo = __float2bfloat16_rn(v - __bfloat162float(hi));
}
__device__ __forceinline__ float fast_exp(float x) {
    if (x < -80.f) return 0.f;
    float t = x * 1.4426950408889634f;
    float n = floorf(t + 0.5f);
    float g = (t - n) * 0.6931471805599453f;
    float p = 1.f + g * (1.f + g * (0.5f + g * (0.16666667f + g * (0.041666667f + g * 0.0083333f))));
    return __uint_as_float((uint32_t)(((int)n + 127) << 23)) * p;
}

// ---------------- dtype detection ----------------
__global__ void detect_kernel(const int* __restrict__ x) {
    __shared__ int any;
    if (threadIdx.x == 0) any = 0;
    __syncthreads();
    int local = 0;
    for (int i = threadIdx.x * 2 + 1; i < NTOK; i += blockDim.x * 2) local |= x[i];
    if (local) atomicOr(&any, 1);
    __syncthreads();
    if (threadIdx.x == 0) g_is64 = (any == 0) ? 1 : 0;
}
__device__ __forceinline__ long long get_id(const void* x, int i) {
    return g_is64 ? ((const long long*)x)[i] : (long long)((const int*)x)[i];
}

// ---------------- fused 8x weight transpose + bf16 hi/lo (paired rows) ----------------
__global__ void wtrans_all_kernel(
    const float* __restrict__ W0, const float* __restrict__ W1,
    const float* __restrict__ W2, const float* __restrict__ W3,
    const float* __restrict__ W4, const float* __restrict__ W5,
    const float* __restrict__ W6, const float* __restrict__ W7,
    __nv_bfloat16* __restrict__ WT) {
    __shared__ float t[32][33];
    int w = blockIdx.z;
    const float* W = (w == 0) ? W0 : (w == 1) ? W1 : (w == 2) ? W2 : (w == 3) ? W3
                   : (w == 4) ? W4 : (w == 5) ? W5 : (w == 6) ? W6 : W7;
    size_t wofs = (size_t)w * DMODEL * DPAIR;
    int n0 = blockIdx.x * 32, k0 = blockIdx.y * 32;
    int tx = threadIdx.x, ty = threadIdx.y;
#pragma unroll
    for (int i = 0; i < 4; i++)
        t[ty + 8 * i][tx] = W[(size_t)(k0 + ty + 8 * i) * DMODEL + n0 + tx];
    __syncthreads();
#pragma unroll
    for (int i = 0; i < 4; i++) {
        float v = t[tx][ty + 8 * i];
        __nv_bfloat16 hi, lo;
        split_bf16(v, hi, lo);
        size_t idx = wofs + (size_t)(n0 + ty + 8 * i) * DPAIR + k0 + tx;
        WT[idx] = hi;
        WT[idx + DMODEL] = lo;
    }
}

// ---------------- embedding: fp32 + paired bf16 hi/lo ----------------
__global__ void embed_kernel(const void* __restrict__ x,
                             const float* __restrict__ emb_w,
                             const float* __restrict__ pos_w) {
    int tok = blockIdx.x;
    int s = tok & (SEQ - 1);
    long long id = get_id(x, tok);
    const float4* ew = (const float4*)(emb_w + (size_t)id * DMODEL);
    const float4* pw = (const float4*)(pos_w + (size_t)s * DMODEL);
    float4* out = (float4*)(g_emb + (size_t)tok * DMODEL);
    __nv_bfloat16* op = g_abuf + (size_t)tok * DPAIR;
    for (int i = threadIdx.x; i < DMODEL / 4; i += blockDim.x) {
        float4 a = ew[i], b = pw[i];
        float4 o = make_float4(a.x + b.x, a.y + b.y, a.z + b.z, a.w + b.w);
        out[i] = o;
        __nv_bfloat16 h0, l0, h1, l1, h2, l2, h3, l3;
        split_bf16(o.x, h0, l0); split_bf16(o.y, h1, l1);
        split_bf16(o.z, h2, l2); split_bf16(o.w, h3, l3);
        op[4 * i + 0] = h0; op[4 * i + 1] = h1; op[4 * i + 2] = h2; op[4 * i + 3] = h3;
        op[DMODEL + 4 * i + 0] = l0; op[DMODEL + 4 * i + 1] = l1;
        op[DMODEL + 4 * i + 2] = l2; op[DMODEL + 4 * i + 3] = l3;
    }
}

// ---------------- 3-term split HMMA GEMM (paired rows, hoisted ldsm bases, 2 CTA/SM) ----------------
#define BKD 32
#define SSTR 40
#define TILE_E (128 * SSTR)
#define ROWB (SSTR * 2)
__global__ __launch_bounds__(256, 2) void gemm_split(
    const __nv_bfloat16* __restrict__ A,   // paired rows, stride DPAIR, lo at +DMODEL
    const __nv_bfloat16* __restrict__ B,   // paired rows, stride DPAIR, lo at +DMODEL
    const float* __restrict__ bias, const float* __restrict__ res,
    float* __restrict__ C, __nv_bfloat16* __restrict__ Cbf) {
    extern __shared__ __nv_bfloat16 smem[];
    __nv_bfloat16* sAhi[2] = {smem + 0 * TILE_E, smem + 1 * TILE_E};
    __nv_bfloat16* sAlo[2] = {smem + 2 * TILE_E, smem + 3 * TILE_E};
    __nv_bfloat16* sBhi[2] = {smem + 4 * TILE_E, smem + 5 * TILE_E};
    __nv_bfloat16* sBlo[2] = {smem + 6 * TILE_E, smem + 7 * TILE_E};

    int tid = threadIdx.x, wid = tid >> 5, lane = tid & 31;
    int bn = blockIdx.x, bm = blockIdx.y;
    int wm = (wid >> 1) * 32;
    int wn = (wid & 1) * 64;

    float acc[2][8][4];
#pragma unroll
    for (int i = 0; i < 2; i++)
#pragma unroll
        for (int j = 0; j < 8; j++)
#pragma unroll
            for (int k = 0; k < 4; k++) acc[i][j][k] = 0.f;

    int lrow = tid >> 1;
    int lc0 = (tid & 1) * 2;
    const __nv_bfloat16* gA = A + (size_t)(bm * 128 + lrow) * DPAIR;
    const __nv_bfloat16* gB = B + (size_t)(bn * 128 + lrow) * DPAIR;
    uint32_t rowoff = lrow * ROWB;
    uint32_t dAhi[2], dAlo[2], dBhi[2], dBlo[2];
#pragma unroll
    for (int b = 0; b < 2; b++) {
        dAhi[b] = smem_u32(sAhi[b]) + rowoff;
        dAlo[b] = smem_u32(sAlo[b]) + rowoff;
        dBhi[b] = smem_u32(sBhi[b]) + rowoff;
        dBlo[b] = smem_u32(sBlo[b]) + rowoff;
    }

    int g = lane >> 3, r = lane & 7;
    int rofs = (g & 1) * 8 + r;
    int kofs = (g >> 1) * 8;

    // hoisted ldsm bases (lo offsets +DMODEL fold into the global loads; here
    // the smem tiles are distinct, so 8 bases)
    uint32_t aHb[2], aLb[2], bHb[2], bLb[2];
    {
        uint32_t aoff = (uint32_t)((wm + rofs) * SSTR + kofs) * 2;
        uint32_t boff = (uint32_t)((wn + rofs) * SSTR + kofs) * 2;
#pragma unroll
        for (int b = 0; b < 2; b++) {
            aHb[b] = smem_u32(sAhi[b]) + aoff;
            aLb[b] = smem_u32(sAlo[b]) + aoff;
            bHb[b] = smem_u32(sBhi[b]) + boff;
            bLb[b] = smem_u32(sBlo[b]) + boff;
        }
    }

#define LOAD_TILE(buf, k0) do { \
    cp_async16(dAhi[buf] + (lc0 + 0) * 16, gA + (k0) + (lc0 + 0) * 8); \
    cp_async16(dAhi[buf] + (lc0 + 1) * 16, gA + (k0) + (lc0 + 1) * 8); \
    cp_async16(dAlo[buf] + (lc0 + 0) * 16, gA + DMODEL + (k0) + (lc0 + 0) * 8); \
    cp_async16(dAlo[buf] + (lc0 + 1) * 16, gA + DMODEL + (k0) + (lc0 + 1) * 8); \
    cp_async16(dBhi[buf] + (lc0 + 0) * 16, gB + (k0) + (lc0 + 0) * 8); \
    cp_async16(dBhi[buf] + (lc0 + 1) * 16, gB + (k0) + (lc0 + 1) * 8); \
    cp_async16(dBlo[buf] + (lc0 + 0) * 16, gB + DMODEL + (k0) + (lc0 + 0) * 8); \
    cp_async16(dBlo[buf] + (lc0 + 1) * 16, gB + DMODEL + (k0) + (lc0 + 1) * 8); \
    asm volatile("cp.async.commit_group;"); \
} while (0)

    LOAD_TILE(0, 0);
    LOAD_TILE(1, BKD);

    const int NIT = DMODEL / BKD;
    for (int it = 0; it < NIT; it++) {
        int buf = it & 1;
        if (it + 2 < NIT)
            asm volatile("cp.async.wait_group 1;" ::: "memory");
        else
            asm volatile("cp.async.wait_group 0;" ::: "memory");
        __syncthreads();

        uint32_t aHx = aHb[buf], aLx = aLb[buf], bHx = bHb[buf], bLx = bLb[buf];
#pragma unroll
        for (int kk = 0; kk < 2; kk++) {
            const uint32_t ko = kk * 32;
            uint32_t aH[2][4];
#pragma unroll
            for (int mt = 0; mt < 2; mt++)
                ldsm_x4(aH[mt][0], aH[mt][1], aH[mt][2], aH[mt][3],
                        aHx + mt * (16 * ROWB) + ko);
            uint32_t bF[8][2];
#pragma unroll
            for (int np = 0; np < 4; np++) {
                uint32_t r0, r1, r2, r3;
                ldsm_x4(r0, r1, r2, r3, bHx + np * (16 * ROWB) + ko);
                bF[np * 2 + 0][0] = r0; bF[np * 2 + 0][1] = r2;
                bF[np * 2 + 1][0] = r1; bF[np * 2 + 1][1] = r3;
            }
#pragma unroll
            for (int mt = 0; mt < 2; mt++)
#pragma unroll
                for (int nt = 0; nt < 8; nt++)
                    mma_bf16(acc[mt][nt][0], acc[mt][nt][1], acc[mt][nt][2], acc[mt][nt][3],
                             aH[mt][0], aH[mt][1], aH[mt][2], aH[mt][3],
                             bF[nt][0], bF[nt][1]);
            {
                uint32_t aL[2][4];
#pragma unroll
                for (int mt = 0; mt < 2; mt++)
                    ldsm_x4(aL[mt][0], aL[mt][1], aL[mt][2], aL[mt][3],
                            aLx + mt * (16 * ROWB) + ko);
#pragma unroll
                for (int mt = 0; mt < 2; mt++)
#pragma unroll
                    for (int nt = 0; nt < 8; nt++)
                        mma_bf16(acc[mt][nt][0], acc[mt][nt][1], acc[mt][nt][2], acc[mt][nt][3],
                                 aL[mt][0], aL[mt][1], aL[mt][2], aL[mt][3],
                                 bF[nt][0], bF[nt][1]);
            }
#pragma unroll
            for (int np = 0; np < 4; np++) {
                uint32_t r0, r1, r2, r3;
                ldsm_x4(r0, r1, r2, r3, bLx + np * (16 * ROWB) + ko);
                bF[np * 2 + 0][0] = r0; bF[np * 2 + 0][1] = r2;
                bF[np * 2 + 1][0] = r1; bF[np * 2 + 1][1] = r3;
            }
#pragma unroll
            for (int mt = 0; mt < 2; mt++)
#pragma unroll
                for (int nt = 0; nt < 8; nt++)
                    mma_bf16(acc[mt][nt][0], acc[mt][nt][1], acc[mt][nt][2], acc[mt][nt][3],
                             aH[mt][0], aH[mt][1], aH[mt][2], aH[mt][3],
                             bF[nt][0], bF[nt][1]);
        }
        __syncthreads();
        if (it + 2 < NIT) LOAD_TILE(buf, (it + 2) * BKD);
    }
#undef LOAD_TILE

    int gid = lane >> 2, tig = lane & 3;
#pragma unroll
    for (int mt = 0; mt < 2; mt++) {
#pragma unroll
        for (int half = 0; half < 2; half++) {
            int m = bm * 128 + wm + mt * 16 + gid + half * 8;
            float* crow = C ? C + (size_t)m * DMODEL : nullptr;
            const float* rrow = res ? res + (size_t)m * DMODEL : nullptr;
            __nv_bfloat16* prow = Cbf ? Cbf + (size_t)m * DPAIR : nullptr;
#pragma unroll
            for (int nt = 0; nt < 8; nt++) {
                int ncol = bn * 128 + wn + nt * 8 + tig * 2;
                float v0 = acc[mt][nt][half * 2 + 0] + bias[ncol];
                float v1 = acc[mt][nt][half * 2 + 1] + bias[ncol + 1];
                if (rrow) { v0 += rrow[ncol]; v1 += rrow[ncol + 1]; }
                if (crow) *(float2*)(crow + ncol) = make_float2(v0, v1);
                if (prow) {
                    __nv_bfloat16 h0, l0, h1, l1;
                    split_bf16(v0, h0, l0);
                    split_bf16(v1, h1, l1);
                    *(__nv_bfloat162*)(prow + ncol) = __nv_bfloat162(h0, h1);
                    *(__nv_bfloat162*)(prow + DMODEL + ncol) = __nv_bfloat162(l0, l1);
                }
            }
        }
    }
}

// ---------------- tensor-core flash attention (paired rows, 3-term bf16) ----------------
template <int DH>
__global__ __launch_bounds__(256) void attn_tc(
    const __nv_bfloat16* __restrict__ Q, const __nv_bfloat16* __restrict__ K,
    const __nv_bfloat16* __restrict__ V, const void* __restrict__ xids,
    __nv_bfloat16* __restrict__ O) {
    extern __shared__ __nv_bfloat16 smb[];
    const int SSTRA = DH + 8;
    const int PSTR = 72;
    __nv_bfloat16* qhi_s = smb;
    __nv_bfloat16* qlo_s = qhi_s + 64 * SSTRA;
    __nv_bfloat16* khi_s = qlo_s + 64 * SSTRA;
    __nv_bfloat16* klo_s = khi_s + 64 * SSTRA;
    __nv_bfloat16* vhi_s = klo_s + 64 * SSTRA;
    __nv_bfloat16* vlo_s = vhi_s + 64 * SSTRA;
    __nv_bfloat16* phi_s = vlo_s + 64 * SSTRA;
    __nv_bfloat16* plo_s = phi_s + 64 * PSTR;
    __shared__ int msk[64];
    __shared__ float rmaxs[64][2], psumw[64][2];
    __shared__ float m_state[64], m_next[64], l_state[64], fac[64];

    int qt = blockIdx.x, h = blockIdx.y, b = blockIdx.z;
    int tid = threadIdx.x, wid = tid >> 5, lane = tid & 31;
    int mt = wid >> 1, nh = wid & 1;
    float scale = rsqrtf((float)DH);
    int q0 = qt * 64;
    int gg = lane >> 3, rr8 = lane & 7;
    int rofs = (gg & 1) * 8 + rr8, kofs = (gg >> 1) * 8;
    int rowA = mt * 16 + (lane >> 2), rowB = rowA + 8;
    int colq = (lane & 3) * 2;
    const int CHK = DH / 8;
    const int NG = DH / 16;

    for (int i = tid; i < 64 * CHK; i += 256) {
        int r = i / CHK, c = i % CHK;
        size_t gi = (size_t)(b * SEQ + q0 + r) * DPAIR + h * DH + c * 8;
        *(uint4*)(qhi_s + r * SSTRA + c * 8) = *(const uint4*)(Q + gi);
        *(uint4*)(qlo_s + r * SSTRA + c * 8) = *(const uint4*)(Q + gi + DMODEL);
    }
    if (tid < 64) { m_state[tid] = -1e30f; l_state[tid] = 0.f; }

    float o[NG][4];
#pragma unroll
    for (int i = 0; i < NG; i++) { o[i][0] = 0.f; o[i][1] = 0.f; o[i][2] = 0.f; o[i][3] = 0.f; }

    int is64 = g_is64;

    for (int kt = 0; kt < SEQ / 64; kt++) {
        int k0 = kt * 64;
        __syncthreads();
        for (int i = tid; i < 64 * CHK; i += 256) {
            int r = i / CHK, c = i % CHK;
            size_t gi = (size_t)(b * SEQ + k0 + r) * DPAIR + h * DH + c * 8;
            *(uint4*)(khi_s + r * SSTRA + c * 8) = *(const uint4*)(K + gi);
            *(uint4*)(klo_s + r * SSTRA + c * 8) = *(const uint4*)(K + gi + DMODEL);
            *(uint4*)(vhi_s + r * SSTRA + c * 8) = *(const uint4*)(V + gi);
            *(uint4*)(vlo_s + r * SSTRA + c * 8) = *(const uint4*)(V + gi + DMODEL);
        }
        if (tid < 64) {
            long long idv = is64 ? ((const long long*)xids)[b * SEQ + k0 + tid]
                                 : (long long)((const int*)xids)[b * SEQ + k0 + tid];
            msk[tid] = (idv != 0) ? 1 : 0;
        }
        __syncthreads();

        // ---- phase A: scores via 3-term HMMA ----
        float sc[4][4];
#pragma unroll
        for (int gq = 0; gq < 4; gq++) { sc[gq][0] = 0.f; sc[gq][1] = 0.f; sc[gq][2] = 0.f; sc[gq][3] = 0.f; }
#pragma unroll
        for (int ks = 0; ks < DH / 16; ks++) {
            uint32_t aH[4], aL[4];
            ldsm_x4(aH[0], aH[1], aH[2], aH[3],
                    smem_u32(qhi_s + (mt * 16 + rofs) * SSTRA + ks * 16 + kofs));
            ldsm_x4(aL[0], aL[1], aL[2], aL[3],
                    smem_u32(qlo_s + (mt * 16 + rofs) * SSTRA + ks * 16 + kofs));
            uint32_t bH[4][2], bL[4][2];
#pragma unroll
            for (int kg = 0; kg < 2; kg++) {
                uint32_t r0, r1, r2, r3;
                ldsm_x4(r0, r1, r2, r3,
                        smem_u32(khi_s + (nh * 32 + kg * 16 + rofs) * SSTRA + ks * 16 + kofs));
                bH[kg * 2 + 0][0] = r0; bH[kg * 2 + 0][1] = r2;
                bH[kg * 2 + 1][0] = r1; bH[kg * 2 + 1][1] = r3;
                ldsm_x4(r0, r1, r2, r3,
                        smem_u32(klo_s + (nh * 32 + kg * 16 + rofs) * SSTRA + ks * 16 + kofs));
                bL[kg * 2 + 0][0] = r0; bL[kg * 2 + 0][1] = r2;
                bL[kg * 2 + 1][0] = r1; bL[kg * 2 + 1][1] = r3;
            }
#pragma unroll
            for (int gq = 0; gq < 4; gq++) {
                mma_bf16(sc[gq][0], sc[gq][1], sc[gq][2], sc[gq][3],
                         aH[0], aH[1], aH[2], aH[3], bH[gq][0], bH[gq][1]);
                mma_bf16(sc[gq][0], sc[gq][1], sc[gq][2], sc[gq][3],
                         aL[0], aL[1], aL[2], aL[3], bH[gq][0], bH[gq][1]);
                mma_bf16(sc[gq][0], sc[gq][1], sc[gq][2], sc[gq][3],
                         aH[0], aH[1], aH[2], aH[3], bL[gq][0], bL[gq][1]);
            }
        }

        // mask + scale, row max
        float mA = -1e30f, mB = -1e30f;
#pragma unroll
        for (int gq = 0; gq < 4; gq++) {
            int cb = nh * 32 + gq * 8 + colq;
            bool k0m = msk[cb] != 0, k1m = msk[cb + 1] != 0;
            sc[gq][0] = k0m ? sc[gq][0] * scale : -1e30f;
            sc[gq][1] = k1m ? sc[gq][1] * scale : -1e30f;
            sc[gq][2] = k0m ? sc[gq][2] * scale : -1e30f;
            sc[gq][3] = k1m ? sc[gq][3] * scale : -1e30f;
            mA = fmaxf(mA, fmaxf(sc[gq][0], sc[gq][1]));
            mB = fmaxf(mB, fmaxf(sc[gq][2], sc[gq][3]));
        }
        mA = fmaxf(mA, __shfl_xor_sync(0xFFFFFFFF, mA, 1));
        mA = fmaxf(mA, __shfl_xor_sync(0xFFFFFFFF, mA, 2));
        mB = fmaxf(mB, __shfl_xor_sync(0xFFFFFFFF, mB, 1));
        mB = fmaxf(mB, __shfl_xor_sync(0xFFFFFFFF, mB, 2));
        if ((lane & 3) == 0) { rmaxs[rowA][nh] = mA; rmaxs[rowB][nh] = mB; }
        __syncthreads();
        if (nh == 0 && (lane & 3) == 0) {
#pragma unroll
            for (int rr = 0; rr < 2; rr++) {
                int rw = rr ? rowB : rowA;
                float rm = fmaxf(rmaxs[rw][0], rmaxs[rw][1]);
                float mold = m_state[rw];
                float mnew = fmaxf(mold, rm);
                m_next[rw] = mnew;
                fac[rw] = (mold < -1e29f) ? 0.f : fast_exp(mold - mnew);
            }
        }
        __syncthreads();

        // exp + P hi/lo write + partial sums
        float mnA = m_next[rowA], mnB = m_next[rowB];
        float sumA = 0.f, sumB = 0.f;
#pragma unroll
        for (int gq = 0; gq < 4; gq++) {
            int cb = nh * 32 + gq * 8 + colq;
            float p0 = (sc[gq][0] > -1e29f) ? fast_exp(sc[gq][0] - mnA) : 0.f;
            float p1 = (sc[gq][1] > -1e29f) ? fast_exp(sc[gq][1] - mnA) : 0.f;
            float p2 = (sc[gq][2] > -1e29f) ? fast_exp(sc[gq][2] - mnB) : 0.f;
            float p3 = (sc[gq][3] > -1e29f) ? fast_exp(sc[gq][3] - mnB) : 0.f;
            sumA += p0 + p1; sumB += p2 + p3;
            __nv_bfloat16 h0, l0, h1, l1;
            split_bf16(p0, h0, l0); split_bf16(p1, h1, l1);
            *(__nv_bfloat162*)(phi_s + rowA * PSTR + cb) = __nv_bfloat162(h0, h1);
            *(__nv_bfloat162*)(plo_s + rowA * PSTR + cb) = __nv_bfloat162(l0, l1);
            split_bf16(p2, h0, l0); split_bf16(p3, h1, l1);
            *(__nv_bfloat162*)(phi_s + rowB * PSTR + cb) = __nv_bfloat162(h0, h1);
            *(__nv_bfloat162*)(plo_s + rowB * PSTR + cb) = __nv_bfloat162(l0, l1);
        }
        sumA += __shfl_xor_sync(0xFFFFFFFF, sumA, 1);
        sumA += __shfl_xor_sync(0xFFFFFFFF, sumA, 2);
        sumB += __shfl_xor_sync(0xFFFFFFFF, sumB, 1);
        sumB += __shfl_xor_sync(0xFFFFFFFF, sumB, 2);
        if ((lane & 3) == 0) { psumw[rowA][nh] = sumA; psumw[rowB][nh] = sumB; }
        __syncthreads();
        if (nh == 0 && (lane & 3) == 0) {
#pragma unroll
            for (int rr = 0; rr < 2; rr++) {
                int rw = rr ? rowB : rowA;
                l_state[rw] = l_state[rw] * fac[rw] + psumw[rw][0] + psumw[rw][1];
                m_state[rw] = m_next[rw];
            }
        }

        // ---- phase C: O += P @ V via 3-term HMMA ----
        float fA = fac[rowA], fB = fac[rowB];
#pragma unroll
        for (int gq = 0; gq < NG; gq++) {
            o[gq][0] *= fA; o[gq][1] *= fA; o[gq][2] *= fB; o[gq][3] *= fB;
        }
#pragma unroll
        for (int ksv = 0; ksv < 4; ksv++) {
            uint32_t pH[4], pL[4];
            ldsm_x4(pH[0], pH[1], pH[2], pH[3],
                    smem_u32(phi_s + (mt * 16 + rofs) * PSTR + ksv * 16 + kofs));
            ldsm_x4(pL[0], pL[1], pL[2], pL[3],
                    smem_u32(plo_s + (mt * 16 + rofs) * PSTR + ksv * 16 + kofs));
            int vrow = ksv * 16 + rr8 + ((lane >> 4) << 3);
            int vcb = nh * (DH / 2) + ((lane >> 3) & 1) * 8;
#pragma unroll
            for (int vg = 0; vg < NG / 2; vg++) {
                uint32_t r0, r1, r2, r3;
                ldsm_x4t(r0, r1, r2, r3,
                         smem_u32(vhi_s + vrow * SSTRA + vcb + vg * 16));
                uint32_t bH0[2] = {r0, r2}, bH1[2] = {r1, r3};
                ldsm_x4t(r0, r1, r2, r3,
                         smem_u32(vlo_s + vrow * SSTRA + vcb + vg * 16));
                uint32_t bL0[2] = {r0, r2}, bL1[2] = {r1, r3};
                int g0 = vg * 2, g1 = vg * 2 + 1;
                mma_bf16(o[g0][0], o[g0][1], o[g0][2], o[g0][3],
                         pH[0], pH[1], pH[2], pH[3], bH0[0], bH0[1]);
                mma_bf16(o[g1][0], o[g1][1], o[g1][2], o[g1][3],
                         pH[0], pH[1], pH[2], pH[3], bH1[0], bH1[1]);
                mma_bf16(o[g0][0], o[g0][1], o[g0][2], o[g0][3],
                         pL[0], pL[1], pL[2], pL[3], bH0[0], bH0[1]);
                mma_bf16(o[g1][0], o[g1][1], o[g1][2], o[g1][3],
                         pL[0], pL[1], pL[2], pL[3], bH1[0], bH1[1]);
                mma_bf16(o[g0][0], o[g0][1], o[g0][2], o[g0][3],
                         pH[0], pH[1], pH[2], pH[3], bL0[0], bL0[1]);
                mma_bf16(o[g1][0], o[g1][1], o[g1][2], o[g1][3],
                         pH[0], pH[1], pH[2], pH[3], bL1[0], bL1[1]);
            }
        }
    }
    __syncthreads();

    float invA = 1.0f / fmaxf(l_state[rowA], 1e-20f);
    float invB = 1.0f / fmaxf(l_state[rowB], 1e-20f);
    size_t bA = (size_t)(b * SEQ + q0 + rowA) * DPAIR;
    size_t bB = (size_t)(b * SEQ + q0 + rowB) * DPAIR;
#pragma unroll
    for (int gq = 0; gq < NG; gq++) {
        int cb = h * DH + nh * (DH / 2) + gq * 8 + colq;
        float v0 = o[gq][0] * invA, v1 = o[gq][1] * invA;
        float v2 = o[gq][2] * invB, v3 = o[gq][3] * invB;
        __nv_bfloat16 h0, l0, h1, l1;
        split_bf16(v0, h0, l0); split_bf16(v1, h1, l1);
        *(__nv_bfloat162*)(O + bA + cb) = __nv_bfloat162(h0, h1);
        *(__nv_bfloat162*)(O + bA + DMODEL + cb) = __nv_bfloat162(l0, l1);
        split_bf16(v2, h0, l0); split_bf16(v3, h1, l1);
        *(__nv_bfloat162*)(O + bB + cb) = __nv_bfloat162(h0, h1);
        *(__nv_bfloat162*)(O + bB + DMODEL + cb) = __nv_bfloat162(l0, l1);
    }
}

// ---------------- masked mean pooling of (g_h2 + g_emb) ----------------
__global__ void pool_kernel(const void* __restrict__ xids) {
    int b = blockIdx.y;
    int col = blockIdx.x * 128 + threadIdx.x;
    __shared__ int smask[SEQ];
    int is64 = g_is64;
    for (int s = threadIdx.x; s < SEQ; s += 128) {
        long long idv = is64 ? ((const long long*)xids)[b * SEQ + s]
                             : (long long)((const int*)xids)[b * SEQ + s];
        smask[s] = (idv != 0) ? 1 : 0;
    }
    __syncthreads();
    float acc = 0.f;
    int cnt = 0;
    for (int s = 0; s < SEQ; s++) {
        if (smask[s]) {
            size_t idx = (size_t)(b * SEQ + s) * DMODEL + col;
            acc += g_h2[idx] + g_emb[idx];
            cnt++;
        }
    }
    g_pooled[b * DMODEL + col] = acc / (float)cnt;
}

// ---------------- LayerNorm + linear head ----------------
__global__ void lnlin_kernel(const float* __restrict__ ng, const float* __restrict__ nb,
                             const float* __restrict__ lw, const float* __restrict__ lb,
                             float* __restrict__ out) {
    int b = blockIdx.x, tid = threadIdx.x;
    __shared__ float red[256];
    float x[4];
    float s = 0.f;
#pragma unroll
    for (int k = 0; k < 4; k++) {
        x[k] = g_pooled[b * DMODEL + tid + k * 256];
        s += x[k];
    }
    red[tid] = s; __syncthreads();
    for (int st = 128; st > 0; st >>= 1) { if (tid < st) red[tid] += red[tid + st]; __syncthreads(); }
    float mu = red[0] / (float)DMODEL;
    __syncthreads();
    float s2 = 0.f;
#pragma unroll
    for (int k = 0; k < 4; k++) { float d = x[k] - mu; s2 += d * d; }
    red[tid] = s2; __syncthreads();
    for (int st = 128; st > 0; st >>= 1) { if (tid < st) red[tid] += red[tid + st]; __syncthreads(); }
    float var = red[0] / (float)DMODEL;
    float rstd = rsqrtf(var + 1e-5f);
    __syncthreads();
    float acc = 0.f;
#pragma unroll
    for (int k = 0; k < 4; k++) {
        int col = tid + k * 256;
        acc += ((x[k] - mu) * rstd * ng[col] + nb[col]) * lw[col];
    }
    red[tid] = acc; __syncthreads();
    for (int st = 128; st > 0; st >>= 1) { if (tid < st) red[tid] += red[tid + st]; __syncthreads(); }
    if (tid == 0) out[b] = red[0] + lb[0];
}

// ---------------- launch ----------------
extern "C" void kernel_launch(void* const* d_in, const int* in_sizes, int n_in,
                              void* d_out, int out_size) {
    const void*  x      = d_in[0];
    const float* emb_w  = (const float*)d_in[1];
    const float* pos_w  = (const float*)d_in[2];
    const float* a1_qw  = (const float*)d_in[3];
    const float* a1_qb  = (const float*)d_in[4];
    const float* a1_kw  = (const float*)d_in[5];
    const float* a1_kb  = (const float*)d_in[6];
    const float* a1_vw  = (const float*)d_in[7];
    const float* a1_vb  = (const float*)d_in[8];
    const float* a1_pw  = (const float*)d_in[9];
    const float* a1_pb  = (const float*)d_in[10];
    const float* a2_qw  = (const float*)d_in[11];
    const float* a2_qb  = (const float*)d_in[12];
    const float* a2_kw  = (const float*)d_in[13];
    const float* a2_kb  = (const float*)d_in[14];
    const float* a2_vw  = (const float*)d_in[15];
    const float* a2_vb  = (const float*)d_in[16];
    const float* a2_pw  = (const float*)d_in[17];
    const float* a2_pb  = (const float*)d_in[18];
    const float* norm_g = (const float*)d_in[19];
    const float* norm_b = (const float*)d_in[20];
    const float* lin_w  = (const float*)d_in[21];
    const float* lin_b  = (const float*)d_in[22];
    float* out = (float*)d_out;

    float *p_emb, *p_h1, *p_h2, *p_q, *p_k, *p_v;
    __nv_bfloat16 *p_a, *p_b, *p_w;
    cudaGetSymbolAddress((void**)&p_emb, g_emb);
    cudaGetSymbolAddress((void**)&p_h1,  g_h1);
    cudaGetSymbolAddress((void**)&p_h2,  g_h2);
    cudaGetSymbolAddress((void**)&p_q,   g_q);
    cudaGetSymbolAddress((void**)&p_k,   g_k);
    cudaGetSymbolAddress((void**)&p_v,   g_v);
    cudaGetSymbolAddress((void**)&p_a,   g_abuf);
    cudaGetSymbolAddress((void**)&p_b,   g_bbuf);
    cudaGetSymbolAddress((void**)&p_w,   g_wbuf);

    __nv_bfloat16* qp = (__nv_bfloat16*)p_q;
    __nv_bfloat16* kp = (__nv_bfloat16*)p_k;
    __nv_bfloat16* vp = (__nv_bfloat16*)p_v;
    const size_t WSLOT = (size_t)DMODEL * DPAIR;

    const int GEMM_SMEM = 8 * TILE_E * 2;   // 81920 bytes
    cudaFuncSetAttribute(gemm_split, cudaFuncAttributeMaxDynamicSharedMemorySize, GEMM_SMEM);
    const int asm128 = (6 * 64 * (128 + 8) + 2 * 64 * 72) * 2;   // 122880
    const int asm256 = (6 * 64 * (256 + 8) + 2 * 64 * 72) * 2;   // 221184
    cudaFuncSetAttribute(attn_tc<128>, cudaFuncAttributeMaxDynamicSharedMemorySize, asm128);
    cudaFuncSetAttribute(attn_tc<256>, cudaFuncAttributeMaxDynamicSharedMemorySize, asm256);

    detect_kernel<<<1, 256>>>((const int*)x);
    wtrans_all_kernel<<<dim3(32, 32, 8), dim3(32, 8)>>>(
        a1_qw, a1_kw, a1_vw, a1_pw, a2_qw, a2_kw, a2_vw, a2_pw, p_w);
    embed_kernel<<<NTOK, 256>>>(x, emb_w, pos_w);   // g_emb + g_abuf pairs

    dim3 gg(DMODEL / 128, NTOK / 128);

    // Layer 1 (8 heads, dh=128)
    gemm_split<<<gg, 256, GEMM_SMEM>>>(p_a, p_w + 0 * WSLOT, a1_qb, nullptr, nullptr, qp);
    gemm_split<<<gg, 256, GEMM_SMEM>>>(p_a, p_w + 1 * WSLOT, a1_kb, nullptr, nullptr, kp);
    gemm_split<<<gg, 256, GEMM_SMEM>>>(p_a, p_w + 2 * WSLOT, a1_vb, nullptr, nullptr, vp);
    attn_tc<128><<<dim3(SEQ / 64, 8, BATCH), 256, asm128>>>(qp, kp, vp, x, p_b);
    gemm_split<<<gg, 256, GEMM_SMEM>>>(p_b, p_w + 3 * WSLOT, a1_pb, p_emb, p_h1, p_a);

    // Layer 2 (4 heads, dh=256)
    gemm_split<<<gg, 256, GEMM_SMEM>>>(p_a, p_w + 4 * WSLOT, a2_qb, nullptr, nullptr, qp);
    gemm_split<<<gg, 256, GEMM_SMEM>>>(p_a, p_w + 5 * WSLOT, a2_kb, nullptr, nullptr, kp);
    gemm_split<<<gg, 256, GEMM_SMEM>>>(p_a, p_w + 6 * WSLOT, a2_vb, nullptr, nullptr, vp);
    attn_tc<256><<<dim3(SEQ / 64, 4, BATCH), 256, asm256>>>(qp, kp, vp, x, p_b);
    gemm_split<<<gg, 256, GEMM_SMEM>>>(p_b, p_w + 7 * WSLOT, a2_pb, p_h1, p_h2, nullptr);

    pool_kernel<<<dim3(DMODEL / 128, BATCH), 128>>>(x);
    lnlin_kernel<<<BATCH, 256>>>(norm_g, norm_b, lin_w, lin_b, out);
}

// round 12
// speedup vs baseline: 1.7984x; 1.0148x over previous
#include <cuda_runtime.h>
#include <cuda_bf16.h>
#include <cstdint>
#include <math.h>

#define DMODEL 1024
#define DPAIR (2 * DMODEL)          // paired-row stride: [hi 1024 | lo 1024]
#define SEQ 512
#define BATCH 64
#define NTOK (BATCH * SEQ)

// ---------------- scratch (static device globals; no allocation) ----------------
__device__ float g_emb[(size_t)NTOK * DMODEL];
__device__ float g_h1[(size_t)NTOK * DMODEL];
__device__ float g_h2[(size_t)NTOK * DMODEL];
__device__ float g_q[(size_t)NTOK * DMODEL];   // bf16 paired rows (NTOK x DPAIR)
__device__ float g_k[(size_t)NTOK * DMODEL];
__device__ float g_v[(size_t)NTOK * DMODEL];
__device__ __nv_bfloat16 g_abuf[(size_t)NTOK * DPAIR];
__device__ __nv_bfloat16 g_bbuf[(size_t)NTOK * DPAIR];
__device__ __nv_bfloat16 g_wbuf[(size_t)8 * DMODEL * DPAIR];
__device__ float g_pooled[BATCH * DMODEL];
__device__ int g_is64;

// ---------------- helpers ----------------
__device__ __forceinline__ uint32_t smem_u32(const void* p) {
    uint32_t a;
    asm("{ .reg .u64 t; cvta.to.shared.u64 t, %1; cvt.u32.u64 %0, t; }" : "=r"(a) : "l"(p));
    return a;
}
__device__ __forceinline__ void cp_async16(uint32_t dst, const void* src) {
    asm volatile("cp.async.cg.shared.global [%0], [%1], 16;" :: "r"(dst), "l"(src));
}
__device__ __forceinline__ void ldsm_x4(uint32_t& r0, uint32_t& r1, uint32_t& r2, uint32_t& r3,
                                        uint32_t addr) {
    asm volatile("ldmatrix.sync.aligned.m8n8.x4.shared.b16 {%0,%1,%2,%3}, [%4];"
                 : "=r"(r0), "=r"(r1), "=r"(r2), "=r"(r3) : "r"(addr));
}
__device__ __forceinline__ void ldsm_x4t(uint32_t& r0, uint32_t& r1, uint32_t& r2, uint32_t& r3,
                                         uint32_t addr) {
    asm volatile("ldmatrix.sync.aligned.m8n8.x4.trans.shared.b16 {%0,%1,%2,%3}, [%4];"
                 : "=r"(r0), "=r"(r1), "=r"(r2), "=r"(r3) : "r"(addr));
}
__device__ __forceinline__ void mma_bf16(float& c0, float& c1, float& c2, float& c3,
                                         uint32_t a0, uint32_t a1, uint32_t a2, uint32_t a3,
                                         uint32_t b0, uint32_t b1) {
    asm volatile("mma.sync.aligned.m16n8k16.row.col.f32.bf16.bf16.f32 "
                 "{%0,%1,%2,%3}, {%4,%5,%6,%7}, {%8,%9}, {%0,%1,%2,%3};"
                 : "+f"(c0), "+f"(c1), "+f"(c2), "+f"(c3)
                 : "r"(a0), "r"(a1), "r"(a2), "r"(a3), "r"(b0), "r"(b1));
}
__device__ __forceinline__ void split_bf16(float v, __nv_bfloat16& hi, __nv_bfloat16& lo) {
    hi = __float2bfloat16_rn(v);
    lo = __float2bfloat16_rn(v - __bfloat162float(hi));
}
__device__ __forceinline__ float fast_exp(float x) {
    if (x < -80.f) return 0.f;
    float t = x * 1.4426950408889634f;
    float n = floorf(t + 0.5f);
    float g = (t - n) * 0.6931471805599453f;
    float p = 1.f + g * (1.f + g * (0.5f + g * (0.16666667f + g * (0.041666667f + g * 0.0083333f))));
    return __uint_as_float((uint32_t)(((int)n + 127) << 23)) * p;
}

// ---------------- dtype detection ----------------
__global__ void detect_kernel(const int* __restrict__ x) {
    __shared__ int any;
    if (threadIdx.x == 0) any = 0;
    __syncthreads();
    int local = 0;
    for (int i = threadIdx.x * 2 + 1; i < NTOK; i += blockDim.x * 2) local |= x[i];
    if (local) atomicOr(&any, 1);
    __syncthreads();
    if (threadIdx.x == 0) g_is64 = (any == 0) ? 1 : 0;
}
__device__ __forceinline__ long long get_id(const void* x, int i) {
    return g_is64 ? ((const long long*)x)[i] : (long long)((const int*)x)[i];
}

// ---------------- fused 8x weight transpose + bf16 hi/lo (paired rows) ----------------
__global__ void wtrans_all_kernel(
    const float* __restrict__ W0, const float* __restrict__ W1,
    const float* __restrict__ W2, const float* __restrict__ W3,
    const float* __restrict__ W4, const float* __restrict__ W5,
    const float* __restrict__ W6, const float* __restrict__ W7,
    __nv_bfloat16* __restrict__ WT) {
    __shared__ float t[32][33];
    int w = blockIdx.z;
    const float* W = (w == 0) ? W0 : (w == 1) ? W1 : (w == 2) ? W2 : (w == 3) ? W3
                   : (w == 4) ? W4 : (w == 5) ? W5 : (w == 6) ? W6 : W7;
    size_t wofs = (size_t)w * DMODEL * DPAIR;
    int n0 = blockIdx.x * 32, k0 = blockIdx.y * 32;
    int tx = threadIdx.x, ty = threadIdx.y;
#pragma unroll
    for (int i = 0; i < 4; i++)
        t[ty + 8 * i][tx] = W[(size_t)(k0 + ty + 8 * i) * DMODEL + n0 + tx];
    __syncthreads();
#pragma unroll
    for (int i = 0; i < 4; i++) {
        float v = t[tx][ty + 8 * i];
        __nv_bfloat16 hi, lo;
        split_bf16(v, hi, lo);
        size_t idx = wofs + (size_t)(n0 + ty + 8 * i) * DPAIR + k0 + tx;
        WT[idx] = hi;
        WT[idx + DMODEL] = lo;
    }
}

// ---------------- embedding: fp32 + paired bf16 hi/lo ----------------
__global__ void embed_kernel(const void* __restrict__ x,
                             const float* __restrict__ emb_w,
                             const float* __restrict__ pos_w) {
    int tok = blockIdx.x;
    int s = tok & (SEQ - 1);
    long long id = get_id(x, tok);
    const float4* ew = (const float4*)(emb_w + (size_t)id * DMODEL);
    const float4* pw = (const float4*)(pos_w + (size_t)s * DMODEL);
    float4* out = (float4*)(g_emb + (size_t)tok * DMODEL);
    __nv_bfloat16* op = g_abuf + (size_t)tok * DPAIR;
    for (int i = threadIdx.x; i < DMODEL / 4; i += blockDim.x) {
        float4 a = ew[i], b = pw[i];
        float4 o = make_float4(a.x + b.x, a.y + b.y, a.z + b.z, a.w + b.w);
        out[i] = o;
        __nv_bfloat16 h0, l0, h1, l1, h2, l2, h3, l3;
        split_bf16(o.x, h0, l0); split_bf16(o.y, h1, l1);
        split_bf16(o.z, h2, l2); split_bf16(o.w, h3, l3);
        op[4 * i + 0] = h0; op[4 * i + 1] = h1; op[4 * i + 2] = h2; op[4 * i + 3] = h3;
        op[DMODEL + 4 * i + 0] = l0; op[DMODEL + 4 * i + 1] = l1;
        op[DMODEL + 4 * i + 2] = l2; op[DMODEL + 4 * i + 3] = l3;
    }
}

// ---------------- 3-term split HMMA GEMM (paired rows, hoisted ldsm bases, 2 CTA/SM) ----------------
#define BKD 32
#define SSTR 40
#define TILE_E (128 * SSTR)
#define ROWB (SSTR * 2)
__global__ __launch_bounds__(256, 2) void gemm_split(
    const __nv_bfloat16* __restrict__ A,
    const __nv_bfloat16* __restrict__ B,
    const float* __restrict__ bias, const float* __restrict__ res,
    float* __restrict__ C, __nv_bfloat16* __restrict__ Cbf) {
    extern __shared__ __nv_bfloat16 smem[];
    __nv_bfloat16* sAhi[2] = {smem + 0 * TILE_E, smem + 1 * TILE_E};
    __nv_bfloat16* sAlo[2] = {smem + 2 * TILE_E, smem + 3 * TILE_E};
    __nv_bfloat16* sBhi[2] = {smem + 4 * TILE_E, smem + 5 * TILE_E};
    __nv_bfloat16* sBlo[2] = {smem + 6 * TILE_E, smem + 7 * TILE_E};

    int tid = threadIdx.x, wid = tid >> 5, lane = tid & 31;
    int bn = blockIdx.x, bm = blockIdx.y;
    int wm = (wid >> 1) * 32;
    int wn = (wid & 1) * 64;

    float acc[2][8][4];
#pragma unroll
    for (int i = 0; i < 2; i++)
#pragma unroll
        for (int j = 0; j < 8; j++)
#pragma unroll
            for (int k = 0; k < 4; k++) acc[i][j][k] = 0.f;

    int lrow = tid >> 1;
    int lc0 = (tid & 1) * 2;
    const __nv_bfloat16* gA = A + (size_t)(bm * 128 + lrow) * DPAIR;
    const __nv_bfloat16* gB = B + (size_t)(bn * 128 + lrow) * DPAIR;
    uint32_t rowoff = lrow * ROWB;
    uint32_t dAhi[2], dAlo[2], dBhi[2], dBlo[2];
#pragma unroll
    for (int b = 0; b < 2; b++) {
        dAhi[b] = smem_u32(sAhi[b]) + rowoff;
        dAlo[b] = smem_u32(sAlo[b]) + rowoff;
        dBhi[b] = smem_u32(sBhi[b]) + rowoff;
        dBlo[b] = smem_u32(sBlo[b]) + rowoff;
    }

    int g = lane >> 3, r = lane & 7;
    int rofs = (g & 1) * 8 + r;
    int kofs = (g >> 1) * 8;

    uint32_t aHb[2], aLb[2], bHb[2], bLb[2];
    {
        uint32_t aoff = (uint32_t)((wm + rofs) * SSTR + kofs) * 2;
        uint32_t boff = (uint32_t)((wn + rofs) * SSTR + kofs) * 2;
#pragma unroll
        for (int b = 0; b < 2; b++) {
            aHb[b] = smem_u32(sAhi[b]) + aoff;
            aLb[b] = smem_u32(sAlo[b]) + aoff;
            bHb[b] = smem_u32(sBhi[b]) + boff;
            bLb[b] = smem_u32(sBlo[b]) + boff;
        }
    }

#define LOAD_TILE(buf, k0) do { \
    cp_async16(dAhi[buf] + (lc0 + 0) * 16, gA + (k0) + (lc0 + 0) * 8); \
    cp_async16(dAhi[buf] + (lc0 + 1) * 16, gA + (k0) + (lc0 + 1) * 8); \
    cp_async16(dAlo[buf] + (lc0 + 0) * 16, gA + DMODEL + (k0) + (lc0 + 0) * 8); \
    cp_async16(dAlo[buf] + (lc0 + 1) * 16, gA + DMODEL + (k0) + (lc0 + 1) * 8); \
    cp_async16(dBhi[buf] + (lc0 + 0) * 16, gB + (k0) + (lc0 + 0) * 8); \
    cp_async16(dBhi[buf] + (lc0 + 1) * 16, gB + (k0) + (lc0 + 1) * 8); \
    cp_async16(dBlo[buf] + (lc0 + 0) * 16, gB + DMODEL + (k0) + (lc0 + 0) * 8); \
    cp_async16(dBlo[buf] + (lc0 + 1) * 16, gB + DMODEL + (k0) + (lc0 + 1) * 8); \
    asm volatile("cp.async.commit_group;"); \
} while (0)

    LOAD_TILE(0, 0);
    LOAD_TILE(1, BKD);

    const int NIT = DMODEL / BKD;
    for (int it = 0; it < NIT; it++) {
        int buf = it & 1;
        if (it + 2 < NIT)
            asm volatile("cp.async.wait_group 1;" ::: "memory");
        else
            asm volatile("cp.async.wait_group 0;" ::: "memory");
        __syncthreads();

        uint32_t aHx = aHb[buf], aLx = aLb[buf], bHx = bHb[buf], bLx = bLb[buf];
#pragma unroll
        for (int kk = 0; kk < 2; kk++) {
            const uint32_t ko = kk * 32;
            uint32_t aH[2][4];
#pragma unroll
            for (int mt = 0; mt < 2; mt++)
                ldsm_x4(aH[mt][0], aH[mt][1], aH[mt][2], aH[mt][3],
                        aHx + mt * (16 * ROWB) + ko);
            uint32_t bF[8][2];
#pragma unroll
            for (int np = 0; np < 4; np++) {
                uint32_t r0, r1, r2, r3;
                ldsm_x4(r0, r1, r2, r3, bHx + np * (16 * ROWB) + ko);
                bF[np * 2 + 0][0] = r0; bF[np * 2 + 0][1] = r2;
                bF[np * 2 + 1][0] = r1; bF[np * 2 + 1][1] = r3;
            }
#pragma unroll
            for (int mt = 0; mt < 2; mt++)
#pragma unroll
                for (int nt = 0; nt < 8; nt++)
                    mma_bf16(acc[mt][nt][0], acc[mt][nt][1], acc[mt][nt][2], acc[mt][nt][3],
                             aH[mt][0], aH[mt][1], aH[mt][2], aH[mt][3],
                             bF[nt][0], bF[nt][1]);
            {
                uint32_t aL[2][4];
#pragma unroll
                for (int mt = 0; mt < 2; mt++)
                    ldsm_x4(aL[mt][0], aL[mt][1], aL[mt][2], aL[mt][3],
                            aLx + mt * (16 * ROWB) + ko);
#pragma unroll
                for (int mt = 0; mt < 2; mt++)
#pragma unroll
                    for (int nt = 0; nt < 8; nt++)
                        mma_bf16(acc[mt][nt][0], acc[mt][nt][1], acc[mt][nt][2], acc[mt][nt][3],
                                 aL[mt][0], aL[mt][1], aL[mt][2], aL[mt][3],
                                 bF[nt][0], bF[nt][1]);
            }
#pragma unroll
            for (int np = 0; np < 4; np++) {
                uint32_t r0, r1, r2, r3;
                ldsm_x4(r0, r1, r2, r3, bLx + np * (16 * ROWB) + ko);
                bF[np * 2 + 0][0] = r0; bF[np * 2 + 0][1] = r2;
                bF[np * 2 + 1][0] = r1; bF[np * 2 + 1][1] = r3;
            }
#pragma unroll
            for (int mt = 0; mt < 2; mt++)
#pragma unroll
                for (int nt = 0; nt < 8; nt++)
                    mma_bf16(acc[mt][nt][0], acc[mt][nt][1], acc[mt][nt][2], acc[mt][nt][3],
                             aH[mt][0], aH[mt][1], aH[mt][2], aH[mt][3],
                             bF[nt][0], bF[nt][1]);
        }
        __syncthreads();
        if (it + 2 < NIT) LOAD_TILE(buf, (it + 2) * BKD);
    }
#undef LOAD_TILE

    int gid = lane >> 2, tig = lane & 3;
#pragma unroll
    for (int mt = 0; mt < 2; mt++) {
#pragma unroll
        for (int half = 0; half < 2; half++) {
            int m = bm * 128 + wm + mt * 16 + gid + half * 8;
            float* crow = C ? C + (size_t)m * DMODEL : nullptr;
            const float* rrow = res ? res + (size_t)m * DMODEL : nullptr;
            __nv_bfloat16* prow = Cbf ? Cbf + (size_t)m * DPAIR : nullptr;
#pragma unroll
            for (int nt = 0; nt < 8; nt++) {
                int ncol = bn * 128 + wn + nt * 8 + tig * 2;
                float v0 = acc[mt][nt][half * 2 + 0] + bias[ncol];
                float v1 = acc[mt][nt][half * 2 + 1] + bias[ncol + 1];
                if (rrow) { v0 += rrow[ncol]; v1 += rrow[ncol + 1]; }
                if (crow) *(float2*)(crow + ncol) = make_float2(v0, v1);
                if (prow) {
                    __nv_bfloat16 h0, l0, h1, l1;
                    split_bf16(v0, h0, l0);
                    split_bf16(v1, h1, l1);
                    *(__nv_bfloat162*)(prow + ncol) = __nv_bfloat162(h0, h1);
                    *(__nv_bfloat162*)(prow + DMODEL + ncol) = __nv_bfloat162(l0, l1);
                }
            }
        }
    }
}

// ---------------- tensor-core flash attention: no-max softmax (tiny logits) ----------------
template <int DH>
__global__ __launch_bounds__(256) void attn_tc(
    const __nv_bfloat16* __restrict__ Q, const __nv_bfloat16* __restrict__ K,
    const __nv_bfloat16* __restrict__ V, const void* __restrict__ xids,
    __nv_bfloat16* __restrict__ O) {
    extern __shared__ __nv_bfloat16 smb[];
    const int SSTRA = DH + 8;
    const int PSTR = 72;
    __nv_bfloat16* qhi_s = smb;
    __nv_bfloat16* qlo_s = qhi_s + 64 * SSTRA;
    __nv_bfloat16* khi_s = qlo_s + 64 * SSTRA;
    __nv_bfloat16* klo_s = khi_s + 64 * SSTRA;
    __nv_bfloat16* vhi_s = klo_s + 64 * SSTRA;
    __nv_bfloat16* vlo_s = vhi_s + 64 * SSTRA;
    __nv_bfloat16* phi_s = vlo_s + 64 * SSTRA;
    __nv_bfloat16* plo_s = phi_s + 64 * PSTR;
    __shared__ int msk[64];
    __shared__ float psumw[64][2];

    int qt = blockIdx.x, h = blockIdx.y, b = blockIdx.z;
    int tid = threadIdx.x, wid = tid >> 5, lane = tid & 31;
    int mt = wid >> 1, nh = wid & 1;
    float scale = rsqrtf((float)DH);
    int q0 = qt * 64;
    int gg = lane >> 3, rr8 = lane & 7;
    int rofs = (gg & 1) * 8 + rr8, kofs = (gg >> 1) * 8;
    int rowA = mt * 16 + (lane >> 2), rowB = rowA + 8;
    int colq = (lane & 3) * 2;
    const int CHK = DH / 8;
    const int NG = DH / 16;

    for (int i = tid; i < 64 * CHK; i += 256) {
        int r = i / CHK, c = i % CHK;
        size_t gi = (size_t)(b * SEQ + q0 + r) * DPAIR + h * DH + c * 8;
        *(uint4*)(qhi_s + r * SSTRA + c * 8) = *(const uint4*)(Q + gi);
        *(uint4*)(qlo_s + r * SSTRA + c * 8) = *(const uint4*)(Q + gi + DMODEL);
    }

    float o[NG][4];
#pragma unroll
    for (int i = 0; i < NG; i++) { o[i][0] = 0.f; o[i][1] = 0.f; o[i][2] = 0.f; o[i][3] = 0.f; }
    float sumA = 0.f, sumB = 0.f;   // per-thread row sums accumulated over all tiles

    int is64 = g_is64;

    for (int kt = 0; kt < SEQ / 64; kt++) {
        int k0 = kt * 64;
        __syncthreads();   // previous iteration's K/V/P fully consumed
        for (int i = tid; i < 64 * CHK; i += 256) {
            int r = i / CHK, c = i % CHK;
            size_t gi = (size_t)(b * SEQ + k0 + r) * DPAIR + h * DH + c * 8;
            *(uint4*)(khi_s + r * SSTRA + c * 8) = *(const uint4*)(K + gi);
            *(uint4*)(klo_s + r * SSTRA + c * 8) = *(const uint4*)(K + gi + DMODEL);
            *(uint4*)(vhi_s + r * SSTRA + c * 8) = *(const uint4*)(V + gi);
            *(uint4*)(vlo_s + r * SSTRA + c * 8) = *(const uint4*)(V + gi + DMODEL);
        }
        if (tid < 64) {
            long long idv = is64 ? ((const long long*)xids)[b * SEQ + k0 + tid]
                                 : (long long)((const int*)xids)[b * SEQ + k0 + tid];
            msk[tid] = (idv != 0) ? 1 : 0;
        }
        __syncthreads();

        // ---- phase A: scores via 3-term HMMA ----
        float sc[4][4];
#pragma unroll
        for (int gq = 0; gq < 4; gq++) { sc[gq][0] = 0.f; sc[gq][1] = 0.f; sc[gq][2] = 0.f; sc[gq][3] = 0.f; }
#pragma unroll
        for (int ks = 0; ks < DH / 16; ks++) {
            uint32_t aH[4], aL[4];
            ldsm_x4(aH[0], aH[1], aH[2], aH[3],
                    smem_u32(qhi_s + (mt * 16 + rofs) * SSTRA + ks * 16 + kofs));
            ldsm_x4(aL[0], aL[1], aL[2], aL[3],
                    smem_u32(qlo_s + (mt * 16 + rofs) * SSTRA + ks * 16 + kofs));
            uint32_t bH[4][2], bL[4][2];
#pragma unroll
            for (int kg = 0; kg < 2; kg++) {
                uint32_t r0, r1, r2, r3;
                ldsm_x4(r0, r1, r2, r3,
                        smem_u32(khi_s + (nh * 32 + kg * 16 + rofs) * SSTRA + ks * 16 + kofs));
                bH[kg * 2 + 0][0] = r0; bH[kg * 2 + 0][1] = r2;
                bH[kg * 2 + 1][0] = r1; bH[kg * 2 + 1][1] = r3;
                ldsm_x4(r0, r1, r2, r3,
                        smem_u32(klo_s + (nh * 32 + kg * 16 + rofs) * SSTRA + ks * 16 + kofs));
                bL[kg * 2 + 0][0] = r0; bL[kg * 2 + 0][1] = r2;
                bL[kg * 2 + 1][0] = r1; bL[kg * 2 + 1][1] = r3;
            }
#pragma unroll
            for (int gq = 0; gq < 4; gq++) {
                mma_bf16(sc[gq][0], sc[gq][1], sc[gq][2], sc[gq][3],
                         aH[0], aH[1], aH[2], aH[3], bH[gq][0], bH[gq][1]);
                mma_bf16(sc[gq][0], sc[gq][1], sc[gq][2], sc[gq][3],
                         aL[0], aL[1], aL[2], aL[3], bH[gq][0], bH[gq][1]);
                mma_bf16(sc[gq][0], sc[gq][1], sc[gq][2], sc[gq][3],
                         aH[0], aH[1], aH[2], aH[3], bL[gq][0], bL[gq][1]);
            }
        }

        // mask + scale + exp (shift-free softmax: logits are tiny) + P hi/lo store
#pragma unroll
        for (int gq = 0; gq < 4; gq++) {
            int cb = nh * 32 + gq * 8 + colq;
            bool k0m = msk[cb] != 0, k1m = msk[cb + 1] != 0;
            float p0 = k0m ? fast_exp(sc[gq][0] * scale) : 0.f;
            float p1 = k1m ? fast_exp(sc[gq][1] * scale) : 0.f;
            float p2 = k0m ? fast_exp(sc[gq][2] * scale) : 0.f;
            float p3 = k1m ? fast_exp(sc[gq][3] * scale) : 0.f;
            sumA += p0 + p1; sumB += p2 + p3;
            __nv_bfloat16 h0, l0, h1, l1;
            split_bf16(p0, h0, l0); split_bf16(p1, h1, l1);
            *(__nv_bfloat162*)(phi_s + rowA * PSTR + cb) = __nv_bfloat162(h0, h1);
            *(__nv_bfloat162*)(plo_s + rowA * PSTR + cb) = __nv_bfloat162(l0, l1);
            split_bf16(p2, h0, l0); split_bf16(p3, h1, l1);
            *(__nv_bfloat162*)(phi_s + rowB * PSTR + cb) = __nv_bfloat162(h0, h1);
            *(__nv_bfloat162*)(plo_s + rowB * PSTR + cb) = __nv_bfloat162(l0, l1);
        }
        __syncthreads();   // P visible to all warps

        // ---- phase C: O += P @ V via 3-term HMMA (no rescale needed) ----
#pragma unroll
        for (int ksv = 0; ksv < 4; ksv++) {
            uint32_t pH[4], pL[4];
            ldsm_x4(pH[0], pH[1], pH[2], pH[3],
                    smem_u32(phi_s + (mt * 16 + rofs) * PSTR + ksv * 16 + kofs));
            ldsm_x4(pL[0], pL[1], pL[2], pL[3],
                    smem_u32(plo_s + (mt * 16 + rofs) * PSTR + ksv * 16 + kofs));
            int vrow = ksv * 16 + rr8 + ((lane >> 4) << 3);
            int vcb = nh * (DH / 2) + ((lane >> 3) & 1) * 8;
#pragma unroll
            for (int vg = 0; vg < NG / 2; vg++) {
                uint32_t r0, r1, r2, r3;
                ldsm_x4t(r0, r1, r2, r3,
                         smem_u32(vhi_s + vrow * SSTRA + vcb + vg * 16));
                uint32_t bH0[2] = {r0, r2}, bH1[2] = {r1, r3};
                ldsm_x4t(r0, r1, r2, r3,
                         smem_u32(vlo_s + vrow * SSTRA + vcb + vg * 16));
                uint32_t bL0[2] = {r0, r2}, bL1[2] = {r1, r3};
                int g0 = vg * 2, g1 = vg * 2 + 1;
                mma_bf16(o[g0][0], o[g0][1], o[g0][2], o[g0][3],
                         pH[0], pH[1], pH[2], pH[3], bH0[0], bH0[1]);
                mma_bf16(o[g1][0], o[g1][1], o[g1][2], o[g1][3],
                         pH[0], pH[1], pH[2], pH[3], bH1[0], bH1[1]);
                mma_bf16(o[g0][0], o[g0][1], o[g0][2], o[g0][3],
                         pL[0], pL[1], pL[2], pL[3], bH0[0], bH0[1]);
                mma_bf16(o[g1][0], o[g1][1], o[g1][2], o[g1][3],
                         pL[0], pL[1], pL[2], pL[3], bH1[0], bH1[1]);
                mma_bf16(o[g0][0], o[g0][1], o[g0][2], o[g0][3],
                         pH[0], pH[1], pH[2], pH[3], bL0[0], bL0[1]);
                mma_bf16(o[g1][0], o[g1][1], o[g1][2], o[g1][3],
                         pH[0], pH[1], pH[2], pH[3], bL1[0], bL1[1]);
            }
        }
    }

    // final row-sum reduce: quad lanes (same row, different cols), then cross-warp (nh)
    sumA += __shfl_xor_sync(0xFFFFFFFF, sumA, 1);
    sumA += __shfl_xor_sync(0xFFFFFFFF, sumA, 2);
    sumB += __shfl_xor_sync(0xFFFFFFFF, sumB, 1);
    sumB += __shfl_xor_sync(0xFFFFFFFF, sumB, 2);
    __syncthreads();
    if ((lane & 3) == 0) { psumw[rowA][nh] = sumA; psumw[rowB][nh] = sumB; }
    __syncthreads();

    float invA = 1.0f / fmaxf(psumw[rowA][0] + psumw[rowA][1], 1e-20f);
    float invB = 1.0f / fmaxf(psumw[rowB][0] + psumw[rowB][1], 1e-20f);
    size_t bA = (size_t)(b * SEQ + q0 + rowA) * DPAIR;
    size_t bB = (size_t)(b * SEQ + q0 + rowB) * DPAIR;
#pragma unroll
    for (int gq = 0; gq < NG; gq++) {
        int cb = h * DH + nh * (DH / 2) + gq * 8 + colq;
        float v0 = o[gq][0] * invA, v1 = o[gq][1] * invA;
        float v2 = o[gq][2] * invB, v3 = o[gq][3] * invB;
        __nv_bfloat16 h0, l0, h1, l1;
        split_bf16(v0, h0, l0); split_bf16(v1, h1, l1);
        *(__nv_bfloat162*)(O + bA + cb) = __nv_bfloat162(h0, h1);
        *(__nv_bfloat162*)(O + bA + DMODEL + cb) = __nv_bfloat162(l0, l1);
        split_bf16(v2, h0, l0); split_bf16(v3, h1, l1);
        *(__nv_bfloat162*)(O + bB + cb) = __nv_bfloat162(h0, h1);
        *(__nv_bfloat162*)(O + bB + DMODEL + cb) = __nv_bfloat162(l0, l1);
    }
}

// ---------------- masked mean pooling of (g_h2 + g_emb) ----------------
__global__ void pool_kernel(const void* __restrict__ xids) {
    int b = blockIdx.y;
    int col = blockIdx.x * 128 + threadIdx.x;
    __shared__ int smask[SEQ];
    int is64 = g_is64;
    for (int s = threadIdx.x; s < SEQ; s += 128) {
        long long idv = is64 ? ((const long long*)xids)[b * SEQ + s]
                             : (long long)((const int*)xids)[b * SEQ + s];
        smask[s] = (idv != 0) ? 1 : 0;
    }
    __syncthreads();
    float acc = 0.f;
    int cnt = 0;
    for (int s = 0; s < SEQ; s++) {
        if (smask[s]) {
            size_t idx = (size_t)(b * SEQ + s) * DMODEL + col;
            acc += g_h2[idx] + g_emb[idx];
            cnt++;
        }
    }
    g_pooled[b * DMODEL + col] = acc / (float)cnt;
}

// ---------------- LayerNorm + linear head ----------------
__global__ void lnlin_kernel(const float* __restrict__ ng, const float* __restrict__ nb,
                             const float* __restrict__ lw, const float* __restrict__ lb,
                             float* __restrict__ out) {
    int b = blockIdx.x, tid = threadIdx.x;
    __shared__ float red[256];
    float x[4];
    float s = 0.f;
#pragma unroll
    for (int k = 0; k < 4; k++) {
        x[k] = g_pooled[b * DMODEL + tid + k * 256];
        s += x[k];
    }
    red[tid] = s; __syncthreads();
    for (int st = 128; st > 0; st >>= 1) { if (tid < st) red[tid] += red[tid + st]; __syncthreads(); }
    float mu = red[0] / (float)DMODEL;
    __syncthreads();
    float s2 = 0.f;
#pragma unroll
    for (int k = 0; k < 4; k++) { float d = x[k] - mu; s2 += d * d; }
    red[tid] = s2; __syncthreads();
    for (int st = 128; st > 0; st >>= 1) { if (tid < st) red[tid] += red[tid + st]; __syncthreads(); }
    float var = red[0] / (float)DMODEL;
    float rstd = rsqrtf(var + 1e-5f);
    __syncthreads();
    float acc = 0.f;
#pragma unroll
    for (int k = 0; k < 4; k++) {
        int col = tid + k * 256;
        acc += ((x[k] - mu) * rstd * ng[col] + nb[col]) * lw[col];
    }
    red[tid] = acc; __syncthreads();
    for (int st = 128; st > 0; st >>= 1) { if (tid < st) red[tid] += red[tid + st]; __syncthreads(); }
    if (tid == 0) out[b] = red[0] + lb[0];
}

// ---------------- launch ----------------
extern "C" void kernel_launch(void* const* d_in, const int* in_sizes, int n_in,
                              void* d_out, int out_size) {
    const void*  x      = d_in[0];
    const float* emb_w  = (const float*)d_in[1];
    const float* pos_w  = (const float*)d_in[2];
    const float* a1_qw  = (const float*)d_in[3];
    const float* a1_qb  = (const float*)d_in[4];
    const float* a1_kw  = (const float*)d_in[5];
    const float* a1_kb  = (const float*)d_in[6];
    const float* a1_vw  = (const float*)d_in[7];
    const float* a1_vb  = (const float*)d_in[8];
    const float* a1_pw  = (const float*)d_in[9];
    const float* a1_pb  = (const float*)d_in[10];
    const float* a2_qw  = (const float*)d_in[11];
    const float* a2_qb  = (const float*)d_in[12];
    const float* a2_kw  = (const float*)d_in[13];
    const float* a2_kb  = (const float*)d_in[14];
    const float* a2_vw  = (const float*)d_in[15];
    const float* a2_vb  = (const float*)d_in[16];
    const float* a2_pw  = (const float*)d_in[17];
    const float* a2_pb  = (const float*)d_in[18];
    const float* norm_g = (const float*)d_in[19];
    const float* norm_b = (const float*)d_in[20];
    const float* lin_w  = (const float*)d_in[21];
    const float* lin_b  = (const float*)d_in[22];
    float* out = (float*)d_out;

    float *p_emb, *p_h1, *p_h2, *p_q, *p_k, *p_v;
    __nv_bfloat16 *p_a, *p_b, *p_w;
    cudaGetSymbolAddress((void**)&p_emb, g_emb);
    cudaGetSymbolAddress((void**)&p_h1,  g_h1);
    cudaGetSymbolAddress((void**)&p_h2,  g_h2);
    cudaGetSymbolAddress((void**)&p_q,   g_q);
    cudaGetSymbolAddress((void**)&p_k,   g_k);
    cudaGetSymbolAddress((void**)&p_v,   g_v);
    cudaGetSymbolAddress((void**)&p_a,   g_abuf);
    cudaGetSymbolAddress((void**)&p_b,   g_bbuf);
    cudaGetSymbolAddress((void**)&p_w,   g_wbuf);

    __nv_bfloat16* qp = (__nv_bfloat16*)p_q;
    __nv_bfloat16* kp = (__nv_bfloat16*)p_k;
    __nv_bfloat16* vp = (__nv_bfloat16*)p_v;
    const size_t WSLOT = (size_t)DMODEL * DPAIR;

    const int GEMM_SMEM = 8 * TILE_E * 2;   // 81920 bytes
    cudaFuncSetAttribute(gemm_split, cudaFuncAttributeMaxDynamicSharedMemorySize, GEMM_SMEM);
    const int asm128 = (6 * 64 * (128 + 8) + 2 * 64 * 72) * 2;   // 122880
    const int asm256 = (6 * 64 * (256 + 8) + 2 * 64 * 72) * 2;   // 221184
    cudaFuncSetAttribute(attn_tc<128>, cudaFuncAttributeMaxDynamicSharedMemorySize, asm128);
    cudaFuncSetAttribute(attn_tc<256>, cudaFuncAttributeMaxDynamicSharedMemorySize, asm256);

    detect_kernel<<<1, 256>>>((const int*)x);
    wtrans_all_kernel<<<dim3(32, 32, 8), dim3(32, 8)>>>(
        a1_qw, a1_kw, a1_vw, a1_pw, a2_qw, a2_kw, a2_vw, a2_pw, p_w);
    embed_kernel<<<NTOK, 256>>>(x, emb_w, pos_w);

    dim3 gg(DMODEL / 128, NTOK / 128);

    // Layer 1 (8 heads, dh=128)
    gemm_split<<<gg, 256, GEMM_SMEM>>>(p_a, p_w + 0 * WSLOT, a1_qb, nullptr, nullptr, qp);
    gemm_split<<<gg, 256, GEMM_SMEM>>>(p_a, p_w + 1 * WSLOT, a1_kb, nullptr, nullptr, kp);
    gemm_split<<<gg, 256, GEMM_SMEM>>>(p_a, p_w + 2 * WSLOT, a1_vb, nullptr, nullptr, vp);
    attn_tc<128><<<dim3(SEQ / 64, 8, BATCH), 256, asm128>>>(qp, kp, vp, x, p_b);
    gemm_split<<<gg, 256, GEMM_SMEM>>>(p_b, p_w + 3 * WSLOT, a1_pb, p_emb, p_h1, p_a);

    // Layer 2 (4 heads, dh=256)
    gemm_split<<<gg, 256, GEMM_SMEM>>>(p_a, p_w + 4 * WSLOT, a2_qb, nullptr, nullptr, qp);
    gemm_split<<<gg, 256, GEMM_SMEM>>>(p_a, p_w + 5 * WSLOT, a2_kb, nullptr, nullptr, kp);
    gemm_split<<<gg, 256, GEMM_SMEM>>>(p_a, p_w + 6 * WSLOT, a2_vb, nullptr, nullptr, vp);
    attn_tc<256><<<dim3(SEQ / 64, 4, BATCH), 256, asm256>>>(qp, kp, vp, x, p_b);
    gemm_split<<<gg, 256, GEMM_SMEM>>>(p_b, p_w + 7 * WSLOT, a2_pb, p_h1, p_h2, nullptr);

    pool_kernel<<<dim3(DMODEL / 128, BATCH), 128>>>(x);
    lnlin_kernel<<<BATCH, 256>>>(norm_g, norm_b, lin_w, lin_b, out);
}

// round 15
// speedup vs baseline: 1.8182x; 1.0110x over previous
#include <cuda_runtime.h>
#include <cuda_bf16.h>
#include <cstdint>
#include <math.h>

#define DMODEL 1024
#define DPAIR (2 * DMODEL)          // paired-row stride: [hi 1024 | lo 1024]
#define SEQ 512
#define BATCH 64
#define NTOK (BATCH * SEQ)

// ---------------- scratch (static device globals; no allocation) ----------------
__device__ float g_emb[(size_t)NTOK * DMODEL];
__device__ float g_h1[(size_t)NTOK * DMODEL];
__device__ float g_h2[(size_t)NTOK * DMODEL];
__device__ float g_q[(size_t)NTOK * DMODEL];   // bf16 paired rows (NTOK x DPAIR)
__device__ float g_k[(size_t)NTOK * DMODEL];
__device__ float g_v[(size_t)NTOK * DMODEL];
__device__ __nv_bfloat16 g_abuf[(size_t)NTOK * DPAIR];
__device__ __nv_bfloat16 g_bbuf[(size_t)NTOK * DPAIR];
__device__ __nv_bfloat16 g_wbuf[(size_t)8 * DMODEL * DPAIR];
__device__ float g_pooled[BATCH * DMODEL];
__device__ int g_is64;

struct QKVPtrs {
    const float* bias[3];
    __nv_bfloat16* out[3];
};

// ---------------- helpers ----------------
__device__ __forceinline__ uint32_t smem_u32(const void* p) {
    uint32_t a;
    asm("{ .reg .u64 t; cvta.to.shared.u64 t, %1; cvt.u32.u64 %0, t; }" : "=r"(a) : "l"(p));
    return a;
}
__device__ __forceinline__ void cp_async16(uint32_t dst, const void* src) {
    asm volatile("cp.async.cg.shared.global [%0], [%1], 16;" :: "r"(dst), "l"(src));
}
__device__ __forceinline__ void ldsm_x4(uint32_t& r0, uint32_t& r1, uint32_t& r2, uint32_t& r3,
                                        uint32_t addr) {
    asm volatile("ldmatrix.sync.aligned.m8n8.x4.shared.b16 {%0,%1,%2,%3}, [%4];"
                 : "=r"(r0), "=r"(r1), "=r"(r2), "=r"(r3) : "r"(addr));
}
__device__ __forceinline__ void ldsm_x4t(uint32_t& r0, uint32_t& r1, uint32_t& r2, uint32_t& r3,
                                         uint32_t addr) {
    asm volatile("ldmatrix.sync.aligned.m8n8.x4.trans.shared.b16 {%0,%1,%2,%3}, [%4];"
                 : "=r"(r0), "=r"(r1), "=r"(r2), "=r"(r3) : "r"(addr));
}
__device__ __forceinline__ void mma_bf16(float& c0, float& c1, float& c2, float& c3,
                                         uint32_t a0, uint32_t a1, uint32_t a2, uint32_t a3,
                                         uint32_t b0, uint32_t b1) {
    asm volatile("mma.sync.aligned.m16n8k16.row.col.f32.bf16.bf16.f32 "
                 "{%0,%1,%2,%3}, {%4,%5,%6,%7}, {%8,%9}, {%0,%1,%2,%3};"
                 : "+f"(c0), "+f"(c1), "+f"(c2), "+f"(c3)
                 : "r"(a0), "r"(a1), "r"(a2), "r"(a3), "r"(b0), "r"(b1));
}
__device__ __forceinline__ void split_bf16(float v, __nv_bfloat16& hi, __nv_bfloat16& lo) {
    hi = __float2bfloat16_rn(v);
    lo = __float2bfloat16_rn(v - __bfloat162float(hi));
}
__device__ __forceinline__ float fast_exp(float x) {
    if (x < -80.f) return 0.f;
    float t = x * 1.4426950408889634f;
    float n = floorf(t + 0.5f);
    float g = (t - n) * 0.6931471805599453f;
    float p = 1.f + g * (1.f + g * (0.5f + g * (0.16666667f + g * (0.041666667f + g * 0.0083333f))));
    return __uint_as_float((uint32_t)(((int)n + 127) << 23)) * p;
}

// ---------------- dtype detection ----------------
__global__ void detect_kernel(const int* __restrict__ x) {
    __shared__ int any;
    if (threadIdx.x == 0) any = 0;
    __syncthreads();
    int local = 0;
    for (int i = threadIdx.x * 2 + 1; i < NTOK; i += blockDim.x * 2) local |= x[i];
    if (local) atomicOr(&any, 1);
    __syncthreads();
    if (threadIdx.x == 0) g_is64 = (any == 0) ? 1 : 0;
}
__device__ __forceinline__ long long get_id(const void* x, int i) {
    return g_is64 ? ((const long long*)x)[i] : (long long)((const int*)x)[i];
}

// ---------------- fused 8x weight transpose + bf16 hi/lo (paired rows) ----------------
__global__ void wtrans_all_kernel(
    const float* __restrict__ W0, const float* __restrict__ W1,
    const float* __restrict__ W2, const float* __restrict__ W3,
    const float* __restrict__ W4, const float* __restrict__ W5,
    const float* __restrict__ W6, const float* __restrict__ W7,
    __nv_bfloat16* __restrict__ WT) {
    __shared__ float t[32][33];
    int w = blockIdx.z;
    const float* W = (w == 0) ? W0 : (w == 1) ? W1 : (w == 2) ? W2 : (w == 3) ? W3
                   : (w == 4) ? W4 : (w == 5) ? W5 : (w == 6) ? W6 : W7;
    size_t wofs = (size_t)w * DMODEL * DPAIR;
    int n0 = blockIdx.x * 32, k0 = blockIdx.y * 32;
    int tx = threadIdx.x, ty = threadIdx.y;
#pragma unroll
    for (int i = 0; i < 4; i++)
        t[ty + 8 * i][tx] = W[(size_t)(k0 + ty + 8 * i) * DMODEL + n0 + tx];
    __syncthreads();
#pragma unroll
    for (int i = 0; i < 4; i++) {
        float v = t[tx][ty + 8 * i];
        __nv_bfloat16 hi, lo;
        split_bf16(v, hi, lo);
        size_t idx = wofs + (size_t)(n0 + ty + 8 * i) * DPAIR + k0 + tx;
        WT[idx] = hi;
        WT[idx + DMODEL] = lo;
    }
}

// ---------------- embedding: fp32 + paired bf16 hi/lo ----------------
__global__ void embed_kernel(const void* __restrict__ x,
                             const float* __restrict__ emb_w,
                             const float* __restrict__ pos_w) {
    int tok = blockIdx.x;
    int s = tok & (SEQ - 1);
    long long id = get_id(x, tok);
    const float4* ew = (const float4*)(emb_w + (size_t)id * DMODEL);
    const float4* pw = (const float4*)(pos_w + (size_t)s * DMODEL);
    float4* out = (float4*)(g_emb + (size_t)tok * DMODEL);
    __nv_bfloat16* op = g_abuf + (size_t)tok * DPAIR;
    for (int i = threadIdx.x; i < DMODEL / 4; i += blockDim.x) {
        float4 a = ew[i], b = pw[i];
        float4 o = make_float4(a.x + b.x, a.y + b.y, a.z + b.z, a.w + b.w);
        out[i] = o;
        __nv_bfloat16 h0, l0, h1, l1, h2, l2, h3, l3;
        split_bf16(o.x, h0, l0); split_bf16(o.y, h1, l1);
        split_bf16(o.z, h2, l2); split_bf16(o.w, h3, l3);
        op[4 * i + 0] = h0; op[4 * i + 1] = h1; op[4 * i + 2] = h2; op[4 * i + 3] = h3;
        op[DMODEL + 4 * i + 0] = l0; op[DMODEL + 4 * i + 1] = l1;
        op[DMODEL + 4 * i + 2] = l2; op[DMODEL + 4 * i + 3] = l3;
    }
}

// ---------------- shared GEMM mainloop (3-term split HMMA, paired rows) ----------------
#define BKD 32
#define SSTR 40
#define TILE_E (128 * SSTR)
#define ROWB (SSTR * 2)

// Computes the 128x128 accumulator for block (bm, bn). Shared by both GEMM entry points.
__device__ __forceinline__ void gemm_mainloop(
    const __nv_bfloat16* A, const __nv_bfloat16* B,
    __nv_bfloat16* smem, int bm, int bn, float acc[2][8][4]) {
    __nv_bfloat16* sAhi[2] = {smem + 0 * TILE_E, smem + 1 * TILE_E};
    __nv_bfloat16* sAlo[2] = {smem + 2 * TILE_E, smem + 3 * TILE_E};
    __nv_bfloat16* sBhi[2] = {smem + 4 * TILE_E, smem + 5 * TILE_E};
    __nv_bfloat16* sBlo[2] = {smem + 6 * TILE_E, smem + 7 * TILE_E};

    int tid = threadIdx.x, wid = tid >> 5, lane = tid & 31;
    int wm = (wid >> 1) * 32;
    int wn = (wid & 1) * 64;

    int lrow = tid >> 1;
    int lc0 = (tid & 1) * 2;
    const __nv_bfloat16* gA = A + (size_t)(bm * 128 + lrow) * DPAIR;
    const __nv_bfloat16* gB = B + (size_t)(bn * 128 + lrow) * DPAIR;
    uint32_t rowoff = lrow * ROWB;
    uint32_t dAhi[2], dAlo[2], dBhi[2], dBlo[2];
#pragma unroll
    for (int b = 0; b < 2; b++) {
        dAhi[b] = smem_u32(sAhi[b]) + rowoff;
        dAlo[b] = smem_u32(sAlo[b]) + rowoff;
        dBhi[b] = smem_u32(sBhi[b]) + rowoff;
        dBlo[b] = smem_u32(sBlo[b]) + rowoff;
    }

    int g = lane >> 3, r = lane & 7;
    int rofs = (g & 1) * 8 + r;
    int kofs = (g >> 1) * 8;

    uint32_t aHb[2], aLb[2], bHb[2], bLb[2];
    {
        uint32_t aoff = (uint32_t)((wm + rofs) * SSTR + kofs) * 2;
        uint32_t boff = (uint32_t)((wn + rofs) * SSTR + kofs) * 2;
#pragma unroll
        for (int b = 0; b < 2; b++) {
            aHb[b] = smem_u32(sAhi[b]) + aoff;
            aLb[b] = smem_u32(sAlo[b]) + aoff;
            bHb[b] = smem_u32(sBhi[b]) + boff;
            bLb[b] = smem_u32(sBlo[b]) + boff;
        }
    }

#define LOAD_TILE(buf, k0) do { \
    cp_async16(dAhi[buf] + (lc0 + 0) * 16, gA + (k0) + (lc0 + 0) * 8); \
    cp_async16(dAhi[buf] + (lc0 + 1) * 16, gA + (k0) + (lc0 + 1) * 8); \
    cp_async16(dAlo[buf] + (lc0 + 0) * 16, gA + DMODEL + (k0) + (lc0 + 0) * 8); \
    cp_async16(dAlo[buf] + (lc0 + 1) * 16, gA + DMODEL + (k0) + (lc0 + 1) * 8); \
    cp_async16(dBhi[buf] + (lc0 + 0) * 16, gB + (k0) + (lc0 + 0) * 8); \
    cp_async16(dBhi[buf] + (lc0 + 1) * 16, gB + (k0) + (lc0 + 1) * 8); \
    cp_async16(dBlo[buf] + (lc0 + 0) * 16, gB + DMODEL + (k0) + (lc0 + 0) * 8); \
    cp_async16(dBlo[buf] + (lc0 + 1) * 16, gB + DMODEL + (k0) + (lc0 + 1) * 8); \
    asm volatile("cp.async.commit_group;"); \
} while (0)

    LOAD_TILE(0, 0);
    LOAD_TILE(1, BKD);

    const int NIT = DMODEL / BKD;
    for (int it = 0; it < NIT; it++) {
        int buf = it & 1;
        if (it + 2 < NIT)
            asm volatile("cp.async.wait_group 1;" ::: "memory");
        else
            asm volatile("cp.async.wait_group 0;" ::: "memory");
        __syncthreads();

        uint32_t aHx = aHb[buf], aLx = aLb[buf], bHx = bHb[buf], bLx = bLb[buf];
#pragma unroll
        for (int kk = 0; kk < 2; kk++) {
            const uint32_t ko = kk * 32;
            uint32_t aH[2][4];
#pragma unroll
            for (int mt = 0; mt < 2; mt++)
                ldsm_x4(aH[mt][0], aH[mt][1], aH[mt][2], aH[mt][3],
                        aHx + mt * (16 * ROWB) + ko);
            uint32_t bF[8][2];
#pragma unroll
            for (int np = 0; np < 4; np++) {
                uint32_t r0, r1, r2, r3;
                ldsm_x4(r0, r1, r2, r3, bHx + np * (16 * ROWB) + ko);
                bF[np * 2 + 0][0] = r0; bF[np * 2 + 0][1] = r2;
                bF[np * 2 + 1][0] = r1; bF[np * 2 + 1][1] = r3;
            }
#pragma unroll
            for (int mt = 0; mt < 2; mt++)
#pragma unroll
                for (int nt = 0; nt < 8; nt++)
                    mma_bf16(acc[mt][nt][0], acc[mt][nt][1], acc[mt][nt][2], acc[mt][nt][3],
                             aH[mt][0], aH[mt][1], aH[mt][2], aH[mt][3],
                             bF[nt][0], bF[nt][1]);
            {
                uint32_t aL[2][4];
#pragma unroll
                for (int mt = 0; mt < 2; mt++)
                    ldsm_x4(aL[mt][0], aL[mt][1], aL[mt][2], aL[mt][3],
                            aLx + mt * (16 * ROWB) + ko);
#pragma unroll
                for (int mt = 0; mt < 2; mt++)
#pragma unroll
                    for (int nt = 0; nt < 8; nt++)
                        mma_bf16(acc[mt][nt][0], acc[mt][nt][1], acc[mt][nt][2], acc[mt][nt][3],
                                 aL[mt][0], aL[mt][1], aL[mt][2], aL[mt][3],
                                 bF[nt][0], bF[nt][1]);
            }
#pragma unroll
            for (int np = 0; np < 4; np++) {
                uint32_t r0, r1, r2, r3;
                ldsm_x4(r0, r1, r2, r3, bLx + np * (16 * ROWB) + ko);
                bF[np * 2 + 0][0] = r0; bF[np * 2 + 0][1] = r2;
                bF[np * 2 + 1][0] = r1; bF[np * 2 + 1][1] = r3;
            }
#pragma unroll
            for (int mt = 0; mt < 2; mt++)
#pragma unroll
                for (int nt = 0; nt < 8; nt++)
                    mma_bf16(acc[mt][nt][0], acc[mt][nt][1], acc[mt][nt][2], acc[mt][nt][3],
                             aH[mt][0], aH[mt][1], aH[mt][2], aH[mt][3],
                             bF[nt][0], bF[nt][1]);
        }
        __syncthreads();
        if (it + 2 < NIT) LOAD_TILE(buf, (it + 2) * BKD);
    }
#undef LOAD_TILE
}

// ---------------- fused QKV GEMM: grid.z selects weight slot / bias / output ----------------
__global__ __launch_bounds__(256, 2) void gemm_qkv(
    const __nv_bfloat16* __restrict__ A, const __nv_bfloat16* __restrict__ Wbase,
    int wslot0, QKVPtrs P) {
    extern __shared__ __nv_bfloat16 smem[];
    int z = blockIdx.z;
    const __nv_bfloat16* B = Wbase + (size_t)(wslot0 + z) * DMODEL * DPAIR;
    const float* bias = P.bias[z];
    __nv_bfloat16* Cbf = P.out[z];

    float acc[2][8][4];
#pragma unroll
    for (int i = 0; i < 2; i++)
#pragma unroll
        for (int j = 0; j < 8; j++)
#pragma unroll
            for (int k = 0; k < 4; k++) acc[i][j][k] = 0.f;

    gemm_mainloop(A, B, smem, blockIdx.y, blockIdx.x, acc);

    int lane = threadIdx.x & 31, wid = threadIdx.x >> 5;
    int wm = (wid >> 1) * 32, wn = (wid & 1) * 64;
    int gid = lane >> 2, tig = lane & 3;
#pragma unroll
    for (int mt = 0; mt < 2; mt++) {
#pragma unroll
        for (int half = 0; half < 2; half++) {
            int m = blockIdx.y * 128 + wm + mt * 16 + gid + half * 8;
            __nv_bfloat16* prow = Cbf + (size_t)m * DPAIR;
#pragma unroll
            for (int nt = 0; nt < 8; nt++) {
                int ncol = blockIdx.x * 128 + wn + nt * 8 + tig * 2;
                float v0 = acc[mt][nt][half * 2 + 0] + bias[ncol];
                float v1 = acc[mt][nt][half * 2 + 1] + bias[ncol + 1];
                __nv_bfloat16 h0, l0, h1, l1;
                split_bf16(v0, h0, l0);
                split_bf16(v1, h1, l1);
                *(__nv_bfloat162*)(prow + ncol) = __nv_bfloat162(h0, h1);
                *(__nv_bfloat162*)(prow + DMODEL + ncol) = __nv_bfloat162(l0, l1);
            }
        }
    }
}

// ---------------- projection GEMM: bias + residual, fp32 C + optional bf16 pairs ----------------
__global__ __launch_bounds__(256, 2) void gemm_split(
    const __nv_bfloat16* __restrict__ A, const __nv_bfloat16* __restrict__ B,
    const float* __restrict__ bias, const float* __restrict__ res,
    float* __restrict__ C, __nv_bfloat16* __restrict__ Cbf) {
    extern __shared__ __nv_bfloat16 smem[];
    float acc[2][8][4];
#pragma unroll
    for (int i = 0; i < 2; i++)
#pragma unroll
        for (int j = 0; j < 8; j++)
#pragma unroll
            for (int k = 0; k < 4; k++) acc[i][j][k] = 0.f;

    gemm_mainloop(A, B, smem, blockIdx.y, blockIdx.x, acc);

    int lane = threadIdx.x & 31, wid = threadIdx.x >> 5;
    int wm = (wid >> 1) * 32, wn = (wid & 1) * 64;
    int gid = lane >> 2, tig = lane & 3;
#pragma unroll
    for (int mt = 0; mt < 2; mt++) {
#pragma unroll
        for (int half = 0; half < 2; half++) {
            int m = blockIdx.y * 128 + wm + mt * 16 + gid + half * 8;
            float* crow = C + (size_t)m * DMODEL;
            const float* rrow = res + (size_t)m * DMODEL;
            __nv_bfloat16* prow = Cbf ? Cbf + (size_t)m * DPAIR : nullptr;
#pragma unroll
            for (int nt = 0; nt < 8; nt++) {
                int ncol = blockIdx.x * 128 + wn + nt * 8 + tig * 2;
                float v0 = acc[mt][nt][half * 2 + 0] + bias[ncol] + rrow[ncol];
                float v1 = acc[mt][nt][half * 2 + 1] + bias[ncol + 1] + rrow[ncol + 1];
                *(float2*)(crow + ncol) = make_float2(v0, v1);
                if (prow) {
                    __nv_bfloat16 h0, l0, h1, l1;
                    split_bf16(v0, h0, l0);
                    split_bf16(v1, h1, l1);
                    *(__nv_bfloat162*)(prow + ncol) = __nv_bfloat162(h0, h1);
                    *(__nv_bfloat162*)(prow + DMODEL + ncol) = __nv_bfloat162(l0, l1);
                }
            }
        }
    }
}

// ---------------- tensor-core flash attention (R12-proven: 3-term A, P hi/lo, V hi/lo) ----------------
template <int DH>
__global__ __launch_bounds__(256) void attn_tc(
    const __nv_bfloat16* __restrict__ Q, const __nv_bfloat16* __restrict__ K,
    const __nv_bfloat16* __restrict__ V, const void* __restrict__ xids,
    __nv_bfloat16* __restrict__ O) {
    extern __shared__ __nv_bfloat16 smb[];
    const int SSTRA = DH + 8;
    const int PSTR = 72;
    __nv_bfloat16* qhi_s = smb;
    __nv_bfloat16* qlo_s = qhi_s + 64 * SSTRA;
    __nv_bfloat16* khi_s = qlo_s + 64 * SSTRA;
    __nv_bfloat16* klo_s = khi_s + 64 * SSTRA;
    __nv_bfloat16* vhi_s = klo_s + 64 * SSTRA;
    __nv_bfloat16* vlo_s = vhi_s + 64 * SSTRA;
    __nv_bfloat16* phi_s = vlo_s + 64 * SSTRA;
    __nv_bfloat16* plo_s = phi_s + 64 * PSTR;
    __shared__ int msk[64];
    __shared__ float psumw[64][2];

    int qt = blockIdx.x, h = blockIdx.y, b = blockIdx.z;
    int tid = threadIdx.x, wid = tid >> 5, lane = tid & 31;
    int mt = wid >> 1, nh = wid & 1;
    float scale = rsqrtf((float)DH);
    int q0 = qt * 64;
    int gg = lane >> 3, rr8 = lane & 7;
    int rofs = (gg & 1) * 8 + rr8, kofs = (gg >> 1) * 8;
    int rowA = mt * 16 + (lane >> 2), rowB = rowA + 8;
    int colq = (lane & 3) * 2;
    const int CHK = DH / 8;
    const int NG = DH / 16;

    for (int i = tid; i < 64 * CHK; i += 256) {
        int r = i / CHK, c = i % CHK;
        size_t gi = (size_t)(b * SEQ + q0 + r) * DPAIR + h * DH + c * 8;
        *(uint4*)(qhi_s + r * SSTRA + c * 8) = *(const uint4*)(Q + gi);
        *(uint4*)(qlo_s + r * SSTRA + c * 8) = *(const uint4*)(Q + gi + DMODEL);
    }

    float o[NG][4];
#pragma unroll
    for (int i = 0; i < NG; i++) { o[i][0] = 0.f; o[i][1] = 0.f; o[i][2] = 0.f; o[i][3] = 0.f; }
    float sumA = 0.f, sumB = 0.f;

    int is64 = g_is64;

    for (int kt = 0; kt < SEQ / 64; kt++) {
        int k0 = kt * 64;
        __syncthreads();
        for (int i = tid; i < 64 * CHK; i += 256) {
            int r = i / CHK, c = i % CHK;
            size_t gi = (size_t)(b * SEQ + k0 + r) * DPAIR + h * DH + c * 8;
            *(uint4*)(khi_s + r * SSTRA + c * 8) = *(const uint4*)(K + gi);
            *(uint4*)(klo_s + r * SSTRA + c * 8) = *(const uint4*)(K + gi + DMODEL);
            *(uint4*)(vhi_s + r * SSTRA + c * 8) = *(const uint4*)(V + gi);
            *(uint4*)(vlo_s + r * SSTRA + c * 8) = *(const uint4*)(V + gi + DMODEL);
        }
        if (tid < 64) {
            long long idv = is64 ? ((const long long*)xids)[b * SEQ + k0 + tid]
                                 : (long long)((const int*)xids)[b * SEQ + k0 + tid];
            msk[tid] = (idv != 0) ? 1 : 0;
        }
        __syncthreads();

        // ---- phase A: scores via 3-term HMMA ----
        float sc[4][4];
#pragma unroll
        for (int gq = 0; gq < 4; gq++) { sc[gq][0] = 0.f; sc[gq][1] = 0.f; sc[gq][2] = 0.f; sc[gq][3] = 0.f; }
#pragma unroll
        for (int ks = 0; ks < DH / 16; ks++) {
            uint32_t aH[4], aL[4];
            ldsm_x4(aH[0], aH[1], aH[2], aH[3],
                    smem_u32(qhi_s + (mt * 16 + rofs) * SSTRA + ks * 16 + kofs));
            ldsm_x4(aL[0], aL[1], aL[2], aL[3],
                    smem_u32(qlo_s + (mt * 16 + rofs) * SSTRA + ks * 16 + kofs));
            uint32_t bH[4][2], bL[4][2];
#pragma unroll
            for (int kg = 0; kg < 2; kg++) {
                uint32_t r0, r1, r2, r3;
                ldsm_x4(r0, r1, r2, r3,
                        smem_u32(khi_s + (nh * 32 + kg * 16 + rofs) * SSTRA + ks * 16 + kofs));
                bH[kg * 2 + 0][0] = r0; bH[kg * 2 + 0][1] = r2;
                bH[kg * 2 + 1][0] = r1; bH[kg * 2 + 1][1] = r3;
                ldsm_x4(r0, r1, r2, r3,
                        smem_u32(klo_s + (nh * 32 + kg * 16 + rofs) * SSTRA + ks * 16 + kofs));
                bL[kg * 2 + 0][0] = r0; bL[kg * 2 + 0][1] = r2;
                bL[kg * 2 + 1][0] = r1; bL[kg * 2 + 1][1] = r3;
            }
#pragma unroll
            for (int gq = 0; gq < 4; gq++) {
                mma_bf16(sc[gq][0], sc[gq][1], sc[gq][2], sc[gq][3],
                         aH[0], aH[1], aH[2], aH[3], bH[gq][0], bH[gq][1]);
                mma_bf16(sc[gq][0], sc[gq][1], sc[gq][2], sc[gq][3],
                         aL[0], aL[1], aL[2], aL[3], bH[gq][0], bH[gq][1]);
                mma_bf16(sc[gq][0], sc[gq][1], sc[gq][2], sc[gq][3],
                         aH[0], aH[1], aH[2], aH[3], bL[gq][0], bL[gq][1]);
            }
        }

        // mask + scale + exp (shift-free softmax) + P hi/lo store
#pragma unroll
        for (int gq = 0; gq < 4; gq++) {
            int cb = nh * 32 + gq * 8 + colq;
            bool k0m = msk[cb] != 0, k1m = msk[cb + 1] != 0;
            float p0 = k0m ? fast_exp(sc[gq][0] * scale) : 0.f;
            float p1 = k1m ? fast_exp(sc[gq][1] * scale) : 0.f;
            float p2 = k0m ? fast_exp(sc[gq][2] * scale) : 0.f;
            float p3 = k1m ? fast_exp(sc[gq][3] * scale) : 0.f;
            sumA += p0 + p1; sumB += p2 + p3;
            __nv_bfloat16 h0, l0, h1, l1;
            split_bf16(p0, h0, l0); split_bf16(p1, h1, l1);
            *(__nv_bfloat162*)(phi_s + rowA * PSTR + cb) = __nv_bfloat162(h0, h1);
            *(__nv_bfloat162*)(plo_s + rowA * PSTR + cb) = __nv_bfloat162(l0, l1);
            split_bf16(p2, h0, l0); split_bf16(p3, h1, l1);
            *(__nv_bfloat162*)(phi_s + rowB * PSTR + cb) = __nv_bfloat162(h0, h1);
            *(__nv_bfloat162*)(plo_s + rowB * PSTR + cb) = __nv_bfloat162(l0, l1);
        }
        __syncthreads();

        // ---- phase C: O += P @ V via 3-term HMMA ----
#pragma unroll
        for (int ksv = 0; ksv < 4; ksv++) {
            uint32_t pH[4], pL[4];
            ldsm_x4(pH[0], pH[1], pH[2], pH[3],
                    smem_u32(phi_s + (mt * 16 + rofs) * PSTR + ksv * 16 + kofs));
            ldsm_x4(pL[0], pL[1], pL[2], pL[3],
                    smem_u32(plo_s + (mt * 16 + rofs) * PSTR + ksv * 16 + kofs));
            int vrow = ksv * 16 + rr8 + ((lane >> 4) << 3);
            int vcb = nh * (DH / 2) + ((lane >> 3) & 1) * 8;
#pragma unroll
            for (int vg = 0; vg < NG / 2; vg++) {
                uint32_t r0, r1, r2, r3;
                ldsm_x4t(r0, r1, r2, r3,
                         smem_u32(vhi_s + vrow * SSTRA + vcb + vg * 16));
                uint32_t bH0[2] = {r0, r2}, bH1[2] = {r1, r3};
                ldsm_x4t(r0, r1, r2, r3,
                         smem_u32(vlo_s + vrow * SSTRA + vcb + vg * 16));
                uint32_t bL0[2] = {r0, r2}, bL1[2] = {r1, r3};
                int g0 = vg * 2, g1 = vg * 2 + 1;
                mma_bf16(o[g0][0], o[g0][1], o[g0][2], o[g0][3],
                         pH[0], pH[1], pH[2], pH[3], bH0[0], bH0[1]);
                mma_bf16(o[g1][0], o[g1][1], o[g1][2], o[g1][3],
                         pH[0], pH[1], pH[2], pH[3], bH1[0], bH1[1]);
                mma_bf16(o[g0][0], o[g0][1], o[g0][2], o[g0][3],
                         pL[0], pL[1], pL[2], pL[3], bH0[0], bH0[1]);
                mma_bf16(o[g1][0], o[g1][1], o[g1][2], o[g1][3],
                         pL[0], pL[1], pL[2], pL[3], bH1[0], bH1[1]);
                mma_bf16(o[g0][0], o[g0][1], o[g0][2], o[g0][3],
                         pH[0], pH[1], pH[2], pH[3], bL0[0], bL0[1]);
                mma_bf16(o[g1][0], o[g1][1], o[g1][2], o[g1][3],
                         pH[0], pH[1], pH[2], pH[3], bL1[0], bL1[1]);
            }
        }
    }

    sumA += __shfl_xor_sync(0xFFFFFFFF, sumA, 1);
    sumA += __shfl_xor_sync(0xFFFFFFFF, sumA, 2);
    sumB += __shfl_xor_sync(0xFFFFFFFF, sumB, 1);
    sumB += __shfl_xor_sync(0xFFFFFFFF, sumB, 2);
    __syncthreads();
    if ((lane & 3) == 0) { psumw[rowA][nh] = sumA; psumw[rowB][nh] = sumB; }
    __syncthreads();

    float invA = 1.0f / fmaxf(psumw[rowA][0] + psumw[rowA][1], 1e-20f);
    float invB = 1.0f / fmaxf(psumw[rowB][0] + psumw[rowB][1], 1e-20f);
    size_t bA = (size_t)(b * SEQ + q0 + rowA) * DPAIR;
    size_t bB = (size_t)(b * SEQ + q0 + rowB) * DPAIR;
#pragma unroll
    for (int gq = 0; gq < NG; gq++) {
        int cb = h * DH + nh * (DH / 2) + gq * 8 + colq;
        float v0 = o[gq][0] * invA, v1 = o[gq][1] * invA;
        float v2 = o[gq][2] * invB, v3 = o[gq][3] * invB;
        __nv_bfloat16 h0, l0, h1, l1;
        split_bf16(v0, h0, l0); split_bf16(v1, h1, l1);
        *(__nv_bfloat162*)(O + bA + cb) = __nv_bfloat162(h0, h1);
        *(__nv_bfloat162*)(O + bA + DMODEL + cb) = __nv_bfloat162(l0, l1);
        split_bf16(v2, h0, l0); split_bf16(v3, h1, l1);
        *(__nv_bfloat162*)(O + bB + cb) = __nv_bfloat162(h0, h1);
        *(__nv_bfloat162*)(O + bB + DMODEL + cb) = __nv_bfloat162(l0, l1);
    }
}

// ---------------- masked mean pooling of (g_h2 + g_emb) ----------------
__global__ void pool_kernel(const void* __restrict__ xids) {
    int b = blockIdx.y;
    int col = blockIdx.x * 128 + threadIdx.x;
    __shared__ int smask[SEQ];
    int is64 = g_is64;
    for (int s = threadIdx.x; s < SEQ; s += 128) {
        long long idv = is64 ? ((const long long*)xids)[b * SEQ + s]
                             : (long long)((const int*)xids)[b * SEQ + s];
        smask[s] = (idv != 0) ? 1 : 0;
    }
    __syncthreads();
    float acc = 0.f;
    int cnt = 0;
    for (int s = 0; s < SEQ; s++) {
        if (smask[s]) {
            size_t idx = (size_t)(b * SEQ + s) * DMODEL + col;
            acc += g_h2[idx] + g_emb[idx];
            cnt++;
        }
    }
    g_pooled[b * DMODEL + col] = acc / (float)cnt;
}

// ---------------- LayerNorm + linear head ----------------
__global__ void lnlin_kernel(const float* __restrict__ ng, const float* __restrict__ nb,
                             const float* __restrict__ lw, const float* __restrict__ lb,
                             float* __restrict__ out) {
    int b = blockIdx.x, tid = threadIdx.x;
    __shared__ float red[256];
    float x[4];
    float s = 0.f;
#pragma unroll
    for (int k = 0; k < 4; k++) {
        x[k] = g_pooled[b * DMODEL + tid + k * 256];
        s += x[k];
    }
    red[tid] = s; __syncthreads();
    for (int st = 128; st > 0; st >>= 1) { if (tid < st) red[tid] += red[tid + st]; __syncthreads(); }
    float mu = red[0] / (float)DMODEL;
    __syncthreads();
    float s2 = 0.f;
#pragma unroll
    for (int k = 0; k < 4; k++) { float d = x[k] - mu; s2 += d * d; }
    red[tid] = s2; __syncthreads();
    for (int st = 128; st > 0; st >>= 1) { if (tid < st) red[tid] += red[tid + st]; __syncthreads(); }
    float var = red[0] / (float)DMODEL;
    float rstd = rsqrtf(var + 1e-5f);
    __syncthreads();
    float acc = 0.f;
#pragma unroll
    for (int k = 0; k < 4; k++) {
        int col = tid + k * 256;
        acc += ((x[k] - mu) * rstd * ng[col] + nb[col]) * lw[col];
    }
    red[tid] = acc; __syncthreads();
    for (int st = 128; st > 0; st >>= 1) { if (tid < st) red[tid] += red[tid + st]; __syncthreads(); }
    if (tid == 0) out[b] = red[0] + lb[0];
}

// ---------------- launch ----------------
extern "C" void kernel_launch(void* const* d_in, const int* in_sizes, int n_in,
                              void* d_out, int out_size) {
    const void*  x      = d_in[0];
    const float* emb_w  = (const float*)d_in[1];
    const float* pos_w  = (const float*)d_in[2];
    const float* a1_qw  = (const float*)d_in[3];
    const float* a1_qb  = (const float*)d_in[4];
    const float* a1_kw  = (const float*)d_in[5];
    const float* a1_kb  = (const float*)d_in[6];
    const float* a1_vw  = (const float*)d_in[7];
    const float* a1_vb  = (const float*)d_in[8];
    const float* a1_pw  = (const float*)d_in[9];
    const float* a1_pb  = (const float*)d_in[10];
    const float* a2_qw  = (const float*)d_in[11];
    const float* a2_qb  = (const float*)d_in[12];
    const float* a2_kw  = (const float*)d_in[13];
    const float* a2_kb  = (const float*)d_in[14];
    const float* a2_vw  = (const float*)d_in[15];
    const float* a2_vb  = (const float*)d_in[16];
    const float* a2_pw  = (const float*)d_in[17];
    const float* a2_pb  = (const float*)d_in[18];
    const float* norm_g = (const float*)d_in[19];
    const float* norm_b = (const float*)d_in[20];
    const float* lin_w  = (const float*)d_in[21];
    const float* lin_b  = (const float*)d_in[22];
    float* out = (float*)d_out;

    float *p_emb, *p_h1, *p_h2, *p_q, *p_k, *p_v;
    __nv_bfloat16 *p_a, *p_b, *p_w;
    cudaGetSymbolAddress((void**)&p_emb, g_emb);
    cudaGetSymbolAddress((void**)&p_h1,  g_h1);
    cudaGetSymbolAddress((void**)&p_h2,  g_h2);
    cudaGetSymbolAddress((void**)&p_q,   g_q);
    cudaGetSymbolAddress((void**)&p_k,   g_k);
    cudaGetSymbolAddress((void**)&p_v,   g_v);
    cudaGetSymbolAddress((void**)&p_a,   g_abuf);
    cudaGetSymbolAddress((void**)&p_b,   g_bbuf);
    cudaGetSymbolAddress((void**)&p_w,   g_wbuf);

    __nv_bfloat16* qp = (__nv_bfloat16*)p_q;
    __nv_bfloat16* kp = (__nv_bfloat16*)p_k;
    __nv_bfloat16* vp = (__nv_bfloat16*)p_v;

    const int GEMM_SMEM = 8 * TILE_E * 2;   // 81920 bytes
    cudaFuncSetAttribute(gemm_split, cudaFuncAttributeMaxDynamicSharedMemorySize, GEMM_SMEM);
    cudaFuncSetAttribute(gemm_qkv,   cudaFuncAttributeMaxDynamicSharedMemorySize, GEMM_SMEM);
    const int asm128 = (6 * 64 * (128 + 8) + 2 * 64 * 72) * 2;   // 122880
    const int asm256 = (6 * 64 * (256 + 8) + 2 * 64 * 72) * 2;   // 221184
    cudaFuncSetAttribute(attn_tc<128>, cudaFuncAttributeMaxDynamicSharedMemorySize, asm128);
    cudaFuncSetAttribute(attn_tc<256>, cudaFuncAttributeMaxDynamicSharedMemorySize, asm256);

    detect_kernel<<<1, 256>>>((const int*)x);
    wtrans_all_kernel<<<dim3(32, 32, 8), dim3(32, 8)>>>(
        a1_qw, a1_kw, a1_vw, a1_pw, a2_qw, a2_kw, a2_vw, a2_pw, p_w);
    embed_kernel<<<NTOK, 256>>>(x, emb_w, pos_w);

    dim3 gq3(DMODEL / 128, NTOK / 128, 3);   // fused QKV
    dim3 gg(DMODEL / 128, NTOK / 128);

    // Layer 1 (8 heads, dh=128)
    QKVPtrs p1 = {{a1_qb, a1_kb, a1_vb}, {qp, kp, vp}};
    gemm_qkv<<<gq3, 256, GEMM_SMEM>>>(p_a, p_w, 0, p1);
    attn_tc<128><<<dim3(SEQ / 64, 8, BATCH), 256, asm128>>>(qp, kp, vp, x, p_b);
    gemm_split<<<gg, 256, GEMM_SMEM>>>(p_b, p_w + (size_t)3 * DMODEL * DPAIR,
                                       a1_pb, p_emb, p_h1, p_a);

    // Layer 2 (4 heads, dh=256)
    QKVPtrs p2 = {{a2_qb, a2_kb, a2_vb}, {qp, kp, vp}};
    gemm_qkv<<<gq3, 256, GEMM_SMEM>>>(p_a, p_w, 4, p2);
    attn_tc<256><<<dim3(SEQ / 64, 4, BATCH), 256, asm256>>>(qp, kp, vp, x, p_b);
    gemm_split<<<gg, 256, GEMM_SMEM>>>(p_b, p_w + (size_t)7 * DMODEL * DPAIR,
                                       a2_pb, p_h1, p_h2, nullptr);

    pool_kernel<<<dim3(DMODEL / 128, BATCH), 128>>>(x);
    lnlin_kernel<<<BATCH, 256>>>(norm_g, norm_b, lin_w, lin_b, out);
}

// round 16
// speedup vs baseline: 2.6852x; 1.4769x over previous
#include <cuda_runtime.h>
#include <cuda_bf16.h>
#include <cstdint>
#include <math.h>

#define DMODEL 1024
#define DPAIR (2 * DMODEL)          // paired-row stride: [hi 1024 | lo 1024]
#define SEQ 512
#define BATCH 64
#define NTOK (BATCH * SEQ)

// ---------------- scratch (static device globals; no allocation) ----------------
__device__ float g_emb[(size_t)NTOK * DMODEL];
__device__ float g_h1[(size_t)NTOK * DMODEL];
__device__ float g_h2[(size_t)NTOK * DMODEL];
__device__ float g_q[(size_t)NTOK * DMODEL];   // bf16 paired rows (NTOK x DPAIR)
__device__ float g_k[(size_t)NTOK * DMODEL];
__device__ float g_v[(size_t)NTOK * DMODEL];
__device__ __nv_bfloat16 g_abuf[(size_t)NTOK * DPAIR];
__device__ __nv_bfloat16 g_bbuf[(size_t)NTOK * DPAIR];
__device__ __nv_bfloat16 g_wbuf[(size_t)8 * DMODEL * DPAIR];
__device__ float g_pooled[BATCH * DMODEL];
__device__ int g_is64;

struct QKVPtrs {
    const float* bias[3];
    __nv_bfloat16* out[3];
};

// ---------------- helpers ----------------
__device__ __forceinline__ uint32_t smem_u32(const void* p) {
    uint32_t a;
    asm("{ .reg .u64 t; cvta.to.shared.u64 t, %1; cvt.u32.u64 %0, t; }" : "=r"(a) : "l"(p));
    return a;
}
__device__ __forceinline__ void cp_async16(uint32_t dst, const void* src) {
    asm volatile("cp.async.cg.shared.global [%0], [%1], 16;" :: "r"(dst), "l"(src));
}
__device__ __forceinline__ void ldsm_x4(uint32_t& r0, uint32_t& r1, uint32_t& r2, uint32_t& r3,
                                        uint32_t addr) {
    asm volatile("ldmatrix.sync.aligned.m8n8.x4.shared.b16 {%0,%1,%2,%3}, [%4];"
                 : "=r"(r0), "=r"(r1), "=r"(r2), "=r"(r3) : "r"(addr));
}
__device__ __forceinline__ void ldsm_x4t(uint32_t& r0, uint32_t& r1, uint32_t& r2, uint32_t& r3,
                                         uint32_t addr) {
    asm volatile("ldmatrix.sync.aligned.m8n8.x4.trans.shared.b16 {%0,%1,%2,%3}, [%4];"
                 : "=r"(r0), "=r"(r1), "=r"(r2), "=r"(r3) : "r"(addr));
}
__device__ __forceinline__ void mma_bf16(float& c0, float& c1, float& c2, float& c3,
                                         uint32_t a0, uint32_t a1, uint32_t a2, uint32_t a3,
                                         uint32_t b0, uint32_t b1) {
    asm volatile("mma.sync.aligned.m16n8k16.row.col.f32.bf16.bf16.f32 "
                 "{%0,%1,%2,%3}, {%4,%5,%6,%7}, {%8,%9}, {%0,%1,%2,%3};"
                 : "+f"(c0), "+f"(c1), "+f"(c2), "+f"(c3)
                 : "r"(a0), "r"(a1), "r"(a2), "r"(a3), "r"(b0), "r"(b1));
}
__device__ __forceinline__ void split_bf16(float v, __nv_bfloat16& hi, __nv_bfloat16& lo) {
    hi = __float2bfloat16_rn(v);
    lo = __float2bfloat16_rn(v - __bfloat162float(hi));
}
__device__ __forceinline__ float fast_exp(float x) {
    if (x < -80.f) return 0.f;
    float t = x * 1.4426950408889634f;
    float n = floorf(t + 0.5f);
    float g = (t - n) * 0.6931471805599453f;
    float p = 1.f + g * (1.f + g * (0.5f + g * (0.16666667f + g * (0.041666667f + g * 0.0083333f))));
    return __uint_as_float((uint32_t)(((int)n + 127) << 23)) * p;
}

// ---------------- dtype detection ----------------
__global__ void detect_kernel(const int* __restrict__ x) {
    __shared__ int any;
    if (threadIdx.x == 0) any = 0;
    __syncthreads();
    int local = 0;
    for (int i = threadIdx.x * 2 + 1; i < NTOK; i += blockDim.x * 2) local |= x[i];
    if (local) atomicOr(&any, 1);
    __syncthreads();
    if (threadIdx.x == 0) g_is64 = (any == 0) ? 1 : 0;
}
__device__ __forceinline__ long long get_id(const void* x, int i) {
    return g_is64 ? ((const long long*)x)[i] : (long long)((const int*)x)[i];
}

// ---------------- fused 8x weight transpose + bf16 hi/lo (paired rows) ----------------
__global__ void wtrans_all_kernel(
    const float* __restrict__ W0, const float* __restrict__ W1,
    const float* __restrict__ W2, const float* __restrict__ W3,
    const float* __restrict__ W4, const float* __restrict__ W5,
    const float* __restrict__ W6, const float* __restrict__ W7,
    __nv_bfloat16* __restrict__ WT) {
    __shared__ float t[32][33];
    int w = blockIdx.z;
    const float* W = (w == 0) ? W0 : (w == 1) ? W1 : (w == 2) ? W2 : (w == 3) ? W3
                   : (w == 4) ? W4 : (w == 5) ? W5 : (w == 6) ? W6 : W7;
    size_t wofs = (size_t)w * DMODEL * DPAIR;
    int n0 = blockIdx.x * 32, k0 = blockIdx.y * 32;
    int tx = threadIdx.x, ty = threadIdx.y;
#pragma unroll
    for (int i = 0; i < 4; i++)
        t[ty + 8 * i][tx] = W[(size_t)(k0 + ty + 8 * i) * DMODEL + n0 + tx];
    __syncthreads();
#pragma unroll
    for (int i = 0; i < 4; i++) {
        float v = t[tx][ty + 8 * i];
        __nv_bfloat16 hi, lo;
        split_bf16(v, hi, lo);
        size_t idx = wofs + (size_t)(n0 + ty + 8 * i) * DPAIR + k0 + tx;
        WT[idx] = hi;
        WT[idx + DMODEL] = lo;
    }
}

// ---------------- embedding: fp32 + paired bf16 hi/lo ----------------
__global__ void embed_kernel(const void* __restrict__ x,
                             const float* __restrict__ emb_w,
                             const float* __restrict__ pos_w) {
    int tok = blockIdx.x;
    int s = tok & (SEQ - 1);
    long long id = get_id(x, tok);
    const float4* ew = (const float4*)(emb_w + (size_t)id * DMODEL);
    const float4* pw = (const float4*)(pos_w + (size_t)s * DMODEL);
    float4* out = (float4*)(g_emb + (size_t)tok * DMODEL);
    __nv_bfloat16* op = g_abuf + (size_t)tok * DPAIR;
    for (int i = threadIdx.x; i < DMODEL / 4; i += blockDim.x) {
        float4 a = ew[i], b = pw[i];
        float4 o = make_float4(a.x + b.x, a.y + b.y, a.z + b.z, a.w + b.w);
        out[i] = o;
        __nv_bfloat16 h0, l0, h1, l1, h2, l2, h3, l3;
        split_bf16(o.x, h0, l0); split_bf16(o.y, h1, l1);
        split_bf16(o.z, h2, l2); split_bf16(o.w, h3, l3);
        op[4 * i + 0] = h0; op[4 * i + 1] = h1; op[4 * i + 2] = h2; op[4 * i + 3] = h3;
        op[DMODEL + 4 * i + 0] = l0; op[DMODEL + 4 * i + 1] = l1;
        op[DMODEL + 4 * i + 2] = l2; op[DMODEL + 4 * i + 3] = l3;
    }
}

// ---------------- GEMM mainloops (paired rows) ----------------
#define BKD 32
#define SSTR 40
#define TILE_E (128 * SSTR)
#define ROWB (SSTR * 2)

// 3-term split mainloop (proven precision)
__device__ __forceinline__ void gemm_mainloop(
    const __nv_bfloat16* A, const __nv_bfloat16* B,
    __nv_bfloat16* smem, int bm, int bn, float acc[2][8][4]) {
    __nv_bfloat16* sAhi[2] = {smem + 0 * TILE_E, smem + 1 * TILE_E};
    __nv_bfloat16* sAlo[2] = {smem + 2 * TILE_E, smem + 3 * TILE_E};
    __nv_bfloat16* sBhi[2] = {smem + 4 * TILE_E, smem + 5 * TILE_E};
    __nv_bfloat16* sBlo[2] = {smem + 6 * TILE_E, smem + 7 * TILE_E};

    int tid = threadIdx.x, wid = tid >> 5, lane = tid & 31;
    int wm = (wid >> 1) * 32;
    int wn = (wid & 1) * 64;

    int lrow = tid >> 1;
    int lc0 = (tid & 1) * 2;
    const __nv_bfloat16* gA = A + (size_t)(bm * 128 + lrow) * DPAIR;
    const __nv_bfloat16* gB = B + (size_t)(bn * 128 + lrow) * DPAIR;
    uint32_t rowoff = lrow * ROWB;
    uint32_t dAhi[2], dAlo[2], dBhi[2], dBlo[2];
#pragma unroll
    for (int b = 0; b < 2; b++) {
        dAhi[b] = smem_u32(sAhi[b]) + rowoff;
        dAlo[b] = smem_u32(sAlo[b]) + rowoff;
        dBhi[b] = smem_u32(sBhi[b]) + rowoff;
        dBlo[b] = smem_u32(sBlo[b]) + rowoff;
    }

    int g = lane >> 3, r = lane & 7;
    int rofs = (g & 1) * 8 + r;
    int kofs = (g >> 1) * 8;

    uint32_t aHb[2], aLb[2], bHb[2], bLb[2];
    {
        uint32_t aoff = (uint32_t)((wm + rofs) * SSTR + kofs) * 2;
        uint32_t boff = (uint32_t)((wn + rofs) * SSTR + kofs) * 2;
#pragma unroll
        for (int b = 0; b < 2; b++) {
            aHb[b] = smem_u32(sAhi[b]) + aoff;
            aLb[b] = smem_u32(sAlo[b]) + aoff;
            bHb[b] = smem_u32(sBhi[b]) + boff;
            bLb[b] = smem_u32(sBlo[b]) + boff;
        }
    }

#define LOAD_TILE(buf, k0) do { \
    cp_async16(dAhi[buf] + (lc0 + 0) * 16, gA + (k0) + (lc0 + 0) * 8); \
    cp_async16(dAhi[buf] + (lc0 + 1) * 16, gA + (k0) + (lc0 + 1) * 8); \
    cp_async16(dAlo[buf] + (lc0 + 0) * 16, gA + DMODEL + (k0) + (lc0 + 0) * 8); \
    cp_async16(dAlo[buf] + (lc0 + 1) * 16, gA + DMODEL + (k0) + (lc0 + 1) * 8); \
    cp_async16(dBhi[buf] + (lc0 + 0) * 16, gB + (k0) + (lc0 + 0) * 8); \
    cp_async16(dBhi[buf] + (lc0 + 1) * 16, gB + (k0) + (lc0 + 1) * 8); \
    cp_async16(dBlo[buf] + (lc0 + 0) * 16, gB + DMODEL + (k0) + (lc0 + 0) * 8); \
    cp_async16(dBlo[buf] + (lc0 + 1) * 16, gB + DMODEL + (k0) + (lc0 + 1) * 8); \
    asm volatile("cp.async.commit_group;"); \
} while (0)

    LOAD_TILE(0, 0);
    LOAD_TILE(1, BKD);

    const int NIT = DMODEL / BKD;
    for (int it = 0; it < NIT; it++) {
        int buf = it & 1;
        if (it + 2 < NIT)
            asm volatile("cp.async.wait_group 1;" ::: "memory");
        else
            asm volatile("cp.async.wait_group 0;" ::: "memory");
        __syncthreads();

        uint32_t aHx = aHb[buf], aLx = aLb[buf], bHx = bHb[buf], bLx = bLb[buf];
#pragma unroll
        for (int kk = 0; kk < 2; kk++) {
            const uint32_t ko = kk * 32;
            uint32_t aH[2][4];
#pragma unroll
            for (int mt = 0; mt < 2; mt++)
                ldsm_x4(aH[mt][0], aH[mt][1], aH[mt][2], aH[mt][3],
                        aHx + mt * (16 * ROWB) + ko);
            uint32_t bF[8][2];
#pragma unroll
            for (int np = 0; np < 4; np++) {
                uint32_t r0, r1, r2, r3;
                ldsm_x4(r0, r1, r2, r3, bHx + np * (16 * ROWB) + ko);
                bF[np * 2 + 0][0] = r0; bF[np * 2 + 0][1] = r2;
                bF[np * 2 + 1][0] = r1; bF[np * 2 + 1][1] = r3;
            }
#pragma unroll
            for (int mt = 0; mt < 2; mt++)
#pragma unroll
                for (int nt = 0; nt < 8; nt++)
                    mma_bf16(acc[mt][nt][0], acc[mt][nt][1], acc[mt][nt][2], acc[mt][nt][3],
                             aH[mt][0], aH[mt][1], aH[mt][2], aH[mt][3],
                             bF[nt][0], bF[nt][1]);
            {
                uint32_t aL[2][4];
#pragma unroll
                for (int mt = 0; mt < 2; mt++)
                    ldsm_x4(aL[mt][0], aL[mt][1], aL[mt][2], aL[mt][3],
                            aLx + mt * (16 * ROWB) + ko);
#pragma unroll
                for (int mt = 0; mt < 2; mt++)
#pragma unroll
                    for (int nt = 0; nt < 8; nt++)
                        mma_bf16(acc[mt][nt][0], acc[mt][nt][1], acc[mt][nt][2], acc[mt][nt][3],
                                 aL[mt][0], aL[mt][1], aL[mt][2], aL[mt][3],
                                 bF[nt][0], bF[nt][1]);
            }
#pragma unroll
            for (int np = 0; np < 4; np++) {
                uint32_t r0, r1, r2, r3;
                ldsm_x4(r0, r1, r2, r3, bLx + np * (16 * ROWB) + ko);
                bF[np * 2 + 0][0] = r0; bF[np * 2 + 0][1] = r2;
                bF[np * 2 + 1][0] = r1; bF[np * 2 + 1][1] = r3;
            }
#pragma unroll
            for (int mt = 0; mt < 2; mt++)
#pragma unroll
                for (int nt = 0; nt < 8; nt++)
                    mma_bf16(acc[mt][nt][0], acc[mt][nt][1], acc[mt][nt][2], acc[mt][nt][3],
                             aH[mt][0], aH[mt][1], aH[mt][2], aH[mt][3],
                             bF[nt][0], bF[nt][1]);
        }
        __syncthreads();
        if (it + 2 < NIT) LOAD_TILE(buf, (it + 2) * BKD);
    }
#undef LOAD_TILE
}

// single-term mainloop (hi x hi) — for Q/K projections (error cancels in softmax)
__device__ __forceinline__ void gemm_mainloop_single(
    const __nv_bfloat16* A, const __nv_bfloat16* B,
    __nv_bfloat16* smem, int bm, int bn, float acc[2][8][4]) {
    __nv_bfloat16* sA[2] = {smem + 0 * TILE_E, smem + 1 * TILE_E};
    __nv_bfloat16* sB[2] = {smem + 2 * TILE_E, smem + 3 * TILE_E};

    int tid = threadIdx.x, wid = tid >> 5, lane = tid & 31;
    int wm = (wid >> 1) * 32;
    int wn = (wid & 1) * 64;

    int lrow = tid >> 1;
    int lc0 = (tid & 1) * 2;
    const __nv_bfloat16* gA = A + (size_t)(bm * 128 + lrow) * DPAIR;
    const __nv_bfloat16* gB = B + (size_t)(bn * 128 + lrow) * DPAIR;
    uint32_t rowoff = lrow * ROWB;
    uint32_t dA[2], dB[2];
#pragma unroll
    for (int b = 0; b < 2; b++) {
        dA[b] = smem_u32(sA[b]) + rowoff;
        dB[b] = smem_u32(sB[b]) + rowoff;
    }

    int g = lane >> 3, r = lane & 7;
    int rofs = (g & 1) * 8 + r;
    int kofs = (g >> 1) * 8;

    uint32_t aHb[2], bHb[2];
    {
        uint32_t aoff = (uint32_t)((wm + rofs) * SSTR + kofs) * 2;
        uint32_t boff = (uint32_t)((wn + rofs) * SSTR + kofs) * 2;
#pragma unroll
        for (int b = 0; b < 2; b++) {
            aHb[b] = smem_u32(sA[b]) + aoff;
            bHb[b] = smem_u32(sB[b]) + boff;
        }
    }

#define LOAD_TILE1(buf, k0) do { \
    cp_async16(dA[buf] + (lc0 + 0) * 16, gA + (k0) + (lc0 + 0) * 8); \
    cp_async16(dA[buf] + (lc0 + 1) * 16, gA + (k0) + (lc0 + 1) * 8); \
    cp_async16(dB[buf] + (lc0 + 0) * 16, gB + (k0) + (lc0 + 0) * 8); \
    cp_async16(dB[buf] + (lc0 + 1) * 16, gB + (k0) + (lc0 + 1) * 8); \
    asm volatile("cp.async.commit_group;"); \
} while (0)

    LOAD_TILE1(0, 0);
    LOAD_TILE1(1, BKD);

    const int NIT = DMODEL / BKD;
    for (int it = 0; it < NIT; it++) {
        int buf = it & 1;
        if (it + 2 < NIT)
            asm volatile("cp.async.wait_group 1;" ::: "memory");
        else
            asm volatile("cp.async.wait_group 0;" ::: "memory");
        __syncthreads();

        uint32_t aHx = aHb[buf], bHx = bHb[buf];
#pragma unroll
        for (int kk = 0; kk < 2; kk++) {
            const uint32_t ko = kk * 32;
            uint32_t aH[2][4];
#pragma unroll
            for (int mt = 0; mt < 2; mt++)
                ldsm_x4(aH[mt][0], aH[mt][1], aH[mt][2], aH[mt][3],
                        aHx + mt * (16 * ROWB) + ko);
            uint32_t bF[8][2];
#pragma unroll
            for (int np = 0; np < 4; np++) {
                uint32_t r0, r1, r2, r3;
                ldsm_x4(r0, r1, r2, r3, bHx + np * (16 * ROWB) + ko);
                bF[np * 2 + 0][0] = r0; bF[np * 2 + 0][1] = r2;
                bF[np * 2 + 1][0] = r1; bF[np * 2 + 1][1] = r3;
            }
#pragma unroll
            for (int mt = 0; mt < 2; mt++)
#pragma unroll
                for (int nt = 0; nt < 8; nt++)
                    mma_bf16(acc[mt][nt][0], acc[mt][nt][1], acc[mt][nt][2], acc[mt][nt][3],
                             aH[mt][0], aH[mt][1], aH[mt][2], aH[mt][3],
                             bF[nt][0], bF[nt][1]);
        }
        __syncthreads();
        if (it + 2 < NIT) LOAD_TILE1(buf, (it + 2) * BKD);
    }
#undef LOAD_TILE1
}

// ---------------- fused QKV GEMM: Q,K single-term; V 3-term split ----------------
__global__ __launch_bounds__(256, 2) void gemm_qkv(
    const __nv_bfloat16* __restrict__ A, const __nv_bfloat16* __restrict__ Wbase,
    int wslot0, QKVPtrs P) {
    extern __shared__ __nv_bfloat16 smem[];
    int z = blockIdx.z;
    const __nv_bfloat16* B = Wbase + (size_t)(wslot0 + z) * DMODEL * DPAIR;
    const float* bias = P.bias[z];
    __nv_bfloat16* Cbf = P.out[z];

    float acc[2][8][4];
#pragma unroll
    for (int i = 0; i < 2; i++)
#pragma unroll
        for (int j = 0; j < 8; j++)
#pragma unroll
            for (int k = 0; k < 4; k++) acc[i][j][k] = 0.f;

    if (z < 2)
        gemm_mainloop_single(A, B, smem, blockIdx.y, blockIdx.x, acc);
    else
        gemm_mainloop(A, B, smem, blockIdx.y, blockIdx.x, acc);

    int lane = threadIdx.x & 31, wid = threadIdx.x >> 5;
    int wm = (wid >> 1) * 32, wn = (wid & 1) * 64;
    int gid = lane >> 2, tig = lane & 3;
#pragma unroll
    for (int mt = 0; mt < 2; mt++) {
#pragma unroll
        for (int half = 0; half < 2; half++) {
            int m = blockIdx.y * 128 + wm + mt * 16 + gid + half * 8;
            __nv_bfloat16* prow = Cbf + (size_t)m * DPAIR;
#pragma unroll
            for (int nt = 0; nt < 8; nt++) {
                int ncol = blockIdx.x * 128 + wn + nt * 8 + tig * 2;
                float v0 = acc[mt][nt][half * 2 + 0] + bias[ncol];
                float v1 = acc[mt][nt][half * 2 + 1] + bias[ncol + 1];
                if (z < 2) {
                    *(__nv_bfloat162*)(prow + ncol) =
                        __nv_bfloat162(__float2bfloat16_rn(v0), __float2bfloat16_rn(v1));
                } else {
                    __nv_bfloat16 h0, l0, h1, l1;
                    split_bf16(v0, h0, l0);
                    split_bf16(v1, h1, l1);
                    *(__nv_bfloat162*)(prow + ncol) = __nv_bfloat162(h0, h1);
                    *(__nv_bfloat162*)(prow + DMODEL + ncol) = __nv_bfloat162(l0, l1);
                }
            }
        }
    }
}

// ---------------- projection GEMM: bias + residual, fp32 C + optional bf16 pairs ----------------
__global__ __launch_bounds__(256, 2) void gemm_split(
    const __nv_bfloat16* __restrict__ A, const __nv_bfloat16* __restrict__ B,
    const float* __restrict__ bias, const float* __restrict__ res,
    float* __restrict__ C, __nv_bfloat16* __restrict__ Cbf) {
    extern __shared__ __nv_bfloat16 smem[];
    float acc[2][8][4];
#pragma unroll
    for (int i = 0; i < 2; i++)
#pragma unroll
        for (int j = 0; j < 8; j++)
#pragma unroll
            for (int k = 0; k < 4; k++) acc[i][j][k] = 0.f;

    gemm_mainloop(A, B, smem, blockIdx.y, blockIdx.x, acc);

    int lane = threadIdx.x & 31, wid = threadIdx.x >> 5;
    int wm = (wid >> 1) * 32, wn = (wid & 1) * 64;
    int gid = lane >> 2, tig = lane & 3;
#pragma unroll
    for (int mt = 0; mt < 2; mt++) {
#pragma unroll
        for (int half = 0; half < 2; half++) {
            int m = blockIdx.y * 128 + wm + mt * 16 + gid + half * 8;
            float* crow = C + (size_t)m * DMODEL;
            const float* rrow = res + (size_t)m * DMODEL;
            __nv_bfloat16* prow = Cbf ? Cbf + (size_t)m * DPAIR : nullptr;
#pragma unroll
            for (int nt = 0; nt < 8; nt++) {
                int ncol = blockIdx.x * 128 + wn + nt * 8 + tig * 2;
                float v0 = acc[mt][nt][half * 2 + 0] + bias[ncol] + rrow[ncol];
                float v1 = acc[mt][nt][half * 2 + 1] + bias[ncol + 1] + rrow[ncol + 1];
                *(float2*)(crow + ncol) = make_float2(v0, v1);
                if (prow) {
                    __nv_bfloat16 h0, l0, h1, l1;
                    split_bf16(v0, h0, l0);
                    split_bf16(v1, h1, l1);
                    *(__nv_bfloat162*)(prow + ncol) = __nv_bfloat162(h0, h1);
                    *(__nv_bfloat162*)(prow + DMODEL + ncol) = __nv_bfloat162(l0, l1);
                }
            }
        }
    }
}

// ---------------- tensor-core flash attention: single Q/K phase A, P hi/lo, V hi/lo ----------------
template <int DH>
__global__ __launch_bounds__(256) void attn_tc(
    const __nv_bfloat16* __restrict__ Q, const __nv_bfloat16* __restrict__ K,
    const __nv_bfloat16* __restrict__ V, const void* __restrict__ xids,
    __nv_bfloat16* __restrict__ O) {
    extern __shared__ __nv_bfloat16 smb[];
    const int SSTRA = DH + 8;
    const int PSTR = 72;
    __nv_bfloat16* qhi_s = smb;
    __nv_bfloat16* khi_s = qhi_s + 64 * SSTRA;
    __nv_bfloat16* vhi_s = khi_s + 64 * SSTRA;
    __nv_bfloat16* vlo_s = vhi_s + 64 * SSTRA;
    __nv_bfloat16* phi_s = vlo_s + 64 * SSTRA;
    __nv_bfloat16* plo_s = phi_s + 64 * PSTR;
    __shared__ int msk[64];
    __shared__ float psumw[64][2];

    int qt = blockIdx.x, h = blockIdx.y, b = blockIdx.z;
    int tid = threadIdx.x, wid = tid >> 5, lane = tid & 31;
    int mt = wid >> 1, nh = wid & 1;
    float scale = rsqrtf((float)DH);
    int q0 = qt * 64;
    int gg = lane >> 3, rr8 = lane & 7;
    int rofs = (gg & 1) * 8 + rr8, kofs = (gg >> 1) * 8;
    int rowA = mt * 16 + (lane >> 2), rowB = rowA + 8;
    int colq = (lane & 3) * 2;
    const int CHK = DH / 8;
    const int NG = DH / 16;

    for (int i = tid; i < 64 * CHK; i += 256) {
        int r = i / CHK, c = i % CHK;
        size_t gi = (size_t)(b * SEQ + q0 + r) * DPAIR + h * DH + c * 8;
        *(uint4*)(qhi_s + r * SSTRA + c * 8) = *(const uint4*)(Q + gi);
    }

    float o[NG][4];
#pragma unroll
    for (int i = 0; i < NG; i++) { o[i][0] = 0.f; o[i][1] = 0.f; o[i][2] = 0.f; o[i][3] = 0.f; }
    float sumA = 0.f, sumB = 0.f;

    int is64 = g_is64;

    for (int kt = 0; kt < SEQ / 64; kt++) {
        int k0 = kt * 64;
        __syncthreads();
        for (int i = tid; i < 64 * CHK; i += 256) {
            int r = i / CHK, c = i % CHK;
            size_t gi = (size_t)(b * SEQ + k0 + r) * DPAIR + h * DH + c * 8;
            *(uint4*)(khi_s + r * SSTRA + c * 8) = *(const uint4*)(K + gi);
            *(uint4*)(vhi_s + r * SSTRA + c * 8) = *(const uint4*)(V + gi);
            *(uint4*)(vlo_s + r * SSTRA + c * 8) = *(const uint4*)(V + gi + DMODEL);
        }
        if (tid < 64) {
            long long idv = is64 ? ((const long long*)xids)[b * SEQ + k0 + tid]
                                 : (long long)((const int*)xids)[b * SEQ + k0 + tid];
            msk[tid] = (idv != 0) ? 1 : 0;
        }
        __syncthreads();

        // ---- phase A: scores via single-term HMMA (QK error cancels in softmax) ----
        float sc[4][4];
#pragma unroll
        for (int gq = 0; gq < 4; gq++) { sc[gq][0] = 0.f; sc[gq][1] = 0.f; sc[gq][2] = 0.f; sc[gq][3] = 0.f; }
#pragma unroll
        for (int ks = 0; ks < DH / 16; ks++) {
            uint32_t aH[4];
            ldsm_x4(aH[0], aH[1], aH[2], aH[3],
                    smem_u32(qhi_s + (mt * 16 + rofs) * SSTRA + ks * 16 + kofs));
            uint32_t bH[4][2];
#pragma unroll
            for (int kg = 0; kg < 2; kg++) {
                uint32_t r0, r1, r2, r3;
                ldsm_x4(r0, r1, r2, r3,
                        smem_u32(khi_s + (nh * 32 + kg * 16 + rofs) * SSTRA + ks * 16 + kofs));
                bH[kg * 2 + 0][0] = r0; bH[kg * 2 + 0][1] = r2;
                bH[kg * 2 + 1][0] = r1; bH[kg * 2 + 1][1] = r3;
            }
#pragma unroll
            for (int gq = 0; gq < 4; gq++)
                mma_bf16(sc[gq][0], sc[gq][1], sc[gq][2], sc[gq][3],
                         aH[0], aH[1], aH[2], aH[3], bH[gq][0], bH[gq][1]);
        }

        // mask + scale + exp (shift-free softmax) + P hi/lo store (P split REQUIRED)
#pragma unroll
        for (int gq = 0; gq < 4; gq++) {
            int cb = nh * 32 + gq * 8 + colq;
            bool k0m = msk[cb] != 0, k1m = msk[cb + 1] != 0;
            float p0 = k0m ? fast_exp(sc[gq][0] * scale) : 0.f;
            float p1 = k1m ? fast_exp(sc[gq][1] * scale) : 0.f;
            float p2 = k0m ? fast_exp(sc[gq][2] * scale) : 0.f;
            float p3 = k1m ? fast_exp(sc[gq][3] * scale) : 0.f;
            sumA += p0 + p1; sumB += p2 + p3;
            __nv_bfloat16 h0, l0, h1, l1;
            split_bf16(p0, h0, l0); split_bf16(p1, h1, l1);
            *(__nv_bfloat162*)(phi_s + rowA * PSTR + cb) = __nv_bfloat162(h0, h1);
            *(__nv_bfloat162*)(plo_s + rowA * PSTR + cb) = __nv_bfloat162(l0, l1);
            split_bf16(p2, h0, l0); split_bf16(p3, h1, l1);
            *(__nv_bfloat162*)(phi_s + rowB * PSTR + cb) = __nv_bfloat162(h0, h1);
            *(__nv_bfloat162*)(plo_s + rowB * PSTR + cb) = __nv_bfloat162(l0, l1);
        }
        __syncthreads();

        // ---- phase C: O += P @ V via 3-term HMMA ----
#pragma unroll
        for (int ksv = 0; ksv < 4; ksv++) {
            uint32_t pH[4], pL[4];
            ldsm_x4(pH[0], pH[1], pH[2], pH[3],
                    smem_u32(phi_s + (mt * 16 + rofs) * PSTR + ksv * 16 + kofs));
            ldsm_x4(pL[0], pL[1], pL[2], pL[3],
                    smem_u32(plo_s + (mt * 16 + rofs) * PSTR + ksv * 16 + kofs));
            int vrow = ksv * 16 + rr8 + ((lane >> 4) << 3);
            int vcb = nh * (DH / 2) + ((lane >> 3) & 1) * 8;
#pragma unroll
            for (int vg = 0; vg < NG / 2; vg++) {
                uint32_t r0, r1, r2, r3;
                ldsm_x4t(r0, r1, r2, r3,
                         smem_u32(vhi_s + vrow * SSTRA + vcb + vg * 16));
                uint32_t bH0[2] = {r0, r2}, bH1[2] = {r1, r3};
                ldsm_x4t(r0, r1, r2, r3,
                         smem_u32(vlo_s + vrow * SSTRA + vcb + vg * 16));
                uint32_t bL0[2] = {r0, r2}, bL1[2] = {r1, r3};
                int g0 = vg * 2, g1 = vg * 2 + 1;
                mma_bf16(o[g0][0], o[g0][1], o[g0][2], o[g0][3],
                         pH[0], pH[1], pH[2], pH[3], bH0[0], bH0[1]);
                mma_bf16(o[g1][0], o[g1][1], o[g1][2], o[g1][3],
                         pH[0], pH[1], pH[2], pH[3], bH1[0], bH1[1]);
                mma_bf16(o[g0][0], o[g0][1], o[g0][2], o[g0][3],
                         pL[0], pL[1], pL[2], pL[3], bH0[0], bH0[1]);
                mma_bf16(o[g1][0], o[g1][1], o[g1][2], o[g1][3],
                         pL[0], pL[1], pL[2], pL[3], bH1[0], bH1[1]);
                mma_bf16(o[g0][0], o[g0][1], o[g0][2], o[g0][3],
                         pH[0], pH[1], pH[2], pH[3], bL0[0], bL0[1]);
                mma_bf16(o[g1][0], o[g1][1], o[g1][2], o[g1][3],
                         pH[0], pH[1], pH[2], pH[3], bL1[0], bL1[1]);
            }
        }
    }

    sumA += __shfl_xor_sync(0xFFFFFFFF, sumA, 1);
    sumA += __shfl_xor_sync(0xFFFFFFFF, sumA, 2);
    sumB += __shfl_xor_sync(0xFFFFFFFF, sumB, 1);
    sumB += __shfl_xor_sync(0xFFFFFFFF, sumB, 2);
    __syncthreads();
    if ((lane & 3) == 0) { psumw[rowA][nh] = sumA; psumw[rowB][nh] = sumB; }
    __syncthreads();

    float invA = 1.0f / fmaxf(psumw[rowA][0] + psumw[rowA][1], 1e-20f);
    float invB = 1.0f / fmaxf(psumw[rowB][0] + psumw[rowB][1], 1e-20f);
    size_t bA = (size_t)(b * SEQ + q0 + rowA) * DPAIR;
    size_t bB = (size_t)(b * SEQ + q0 + rowB) * DPAIR;
#pragma unroll
    for (int gq = 0; gq < NG; gq++) {
        int cb = h * DH + nh * (DH / 2) + gq * 8 + colq;
        float v0 = o[gq][0] * invA, v1 = o[gq][1] * invA;
        float v2 = o[gq][2] * invB, v3 = o[gq][3] * invB;
        __nv_bfloat16 h0, l0, h1, l1;
        split_bf16(v0, h0, l0); split_bf16(v1, h1, l1);
        *(__nv_bfloat162*)(O + bA + cb) = __nv_bfloat162(h0, h1);
        *(__nv_bfloat162*)(O + bA + DMODEL + cb) = __nv_bfloat162(l0, l1);
        split_bf16(v2, h0, l0); split_bf16(v3, h1, l1);
        *(__nv_bfloat162*)(O + bB + cb) = __nv_bfloat162(h0, h1);
        *(__nv_bfloat162*)(O + bB + DMODEL + cb) = __nv_bfloat162(l0, l1);
    }
}

// ---------------- masked mean pooling of (g_h2 + g_emb) ----------------
__global__ void pool_kernel(const void* __restrict__ xids) {
    int b = blockIdx.y;
    int col = blockIdx.x * 128 + threadIdx.x;
    __shared__ int smask[SEQ];
    int is64 = g_is64;
    for (int s = threadIdx.x; s < SEQ; s += 128) {
        long long idv = is64 ? ((const long long*)xids)[b * SEQ + s]
                             : (long long)((const int*)xids)[b * SEQ + s];
        smask[s] = (idv != 0) ? 1 : 0;
    }
    __syncthreads();
    float acc = 0.f;
    int cnt = 0;
    for (int s = 0; s < SEQ; s++) {
        if (smask[s]) {
            size_t idx = (size_t)(b * SEQ + s) * DMODEL + col;
            acc += g_h2[idx] + g_emb[idx];
            cnt++;
        }
    }
    g_pooled[b * DMODEL + col] = acc / (float)cnt;
}

// ---------------- LayerNorm + linear head ----------------
__global__ void lnlin_kernel(const float* __restrict__ ng, const float* __restrict__ nb,
                             const float* __restrict__ lw, const float* __restrict__ lb,
                             float* __restrict__ out) {
    int b = blockIdx.x, tid = threadIdx.x;
    __shared__ float red[256];
    float x[4];
    float s = 0.f;
#pragma unroll
    for (int k = 0; k < 4; k++) {
        x[k] = g_pooled[b * DMODEL + tid + k * 256];
        s += x[k];
    }
    red[tid] = s; __syncthreads();
    for (int st = 128; st > 0; st >>= 1) { if (tid < st) red[tid] += red[tid + st]; __syncthreads(); }
    float mu = red[0] / (float)DMODEL;
    __syncthreads();
    float s2 = 0.f;
#pragma unroll
    for (int k = 0; k < 4; k++) { float d = x[k] - mu; s2 += d * d; }
    red[tid] = s2; __syncthreads();
    for (int st = 128; st > 0; st >>= 1) { if (tid < st) red[tid] += red[tid + st]; __syncthreads(); }
    float var = red[0] / (float)DMODEL;
    float rstd = rsqrtf(var + 1e-5f);
    __syncthreads();
    float acc = 0.f;
#pragma unroll
    for (int k = 0; k < 4; k++) {
        int col = tid + k * 256;
        acc += ((x[k] - mu) * rstd * ng[col] + nb[col]) * lw[col];
    }
    red[tid] = acc; __syncthreads();
    for (int st = 128; st > 0; st >>= 1) { if (tid < st) red[tid] += red[tid + st]; __syncthreads(); }
    if (tid == 0) out[b] = red[0] + lb[0];
}

// ---------------- launch ----------------
extern "C" void kernel_launch(void* const* d_in, const int* in_sizes, int n_in,
                              void* d_out, int out_size) {
    const void*  x      = d_in[0];
    const float* emb_w  = (const float*)d_in[1];
    const float* pos_w  = (const float*)d_in[2];
    const float* a1_qw  = (const float*)d_in[3];
    const float* a1_qb  = (const float*)d_in[4];
    const float* a1_kw  = (const float*)d_in[5];
    const float* a1_kb  = (const float*)d_in[6];
    const float* a1_vw  = (const float*)d_in[7];
    const float* a1_vb  = (const float*)d_in[8];
    const float* a1_pw  = (const float*)d_in[9];
    const float* a1_pb  = (const float*)d_in[10];
    const float* a2_qw  = (const float*)d_in[11];
    const float* a2_qb  = (const float*)d_in[12];
    const float* a2_kw  = (const float*)d_in[13];
    const float* a2_kb  = (const float*)d_in[14];
    const float* a2_vw  = (const float*)d_in[15];
    const float* a2_vb  = (const float*)d_in[16];
    const float* a2_pw  = (const float*)d_in[17];
    const float* a2_pb  = (const float*)d_in[18];
    const float* norm_g = (const float*)d_in[19];
    const float* norm_b = (const float*)d_in[20];
    const float* lin_w  = (const float*)d_in[21];
    const float* lin_b  = (const float*)d_in[22];
    float* out = (float*)d_out;

    float *p_emb, *p_h1, *p_h2, *p_q, *p_k, *p_v;
    __nv_bfloat16 *p_a, *p_b, *p_w;
    cudaGetSymbolAddress((void**)&p_emb, g_emb);
    cudaGetSymbolAddress((void**)&p_h1,  g_h1);
    cudaGetSymbolAddress((void**)&p_h2,  g_h2);
    cudaGetSymbolAddress((void**)&p_q,   g_q);
    cudaGetSymbolAddress((void**)&p_k,   g_k);
    cudaGetSymbolAddress((void**)&p_v,   g_v);
    cudaGetSymbolAddress((void**)&p_a,   g_abuf);
    cudaGetSymbolAddress((void**)&p_b,   g_bbuf);
    cudaGetSymbolAddress((void**)&p_w,   g_wbuf);

    __nv_bfloat16* qp = (__nv_bfloat16*)p_q;
    __nv_bfloat16* kp = (__nv_bfloat16*)p_k;
    __nv_bfloat16* vp = (__nv_bfloat16*)p_v;

    const int GEMM_SMEM = 8 * TILE_E * 2;   // 81920 bytes
    cudaFuncSetAttribute(gemm_split, cudaFuncAttributeMaxDynamicSharedMemorySize, GEMM_SMEM);
    cudaFuncSetAttribute(gemm_qkv,   cudaFuncAttributeMaxDynamicSharedMemorySize, GEMM_SMEM);
    const int asm128 = (4 * 64 * (128 + 8) + 2 * 64 * 72) * 2;   // 88064
    const int asm256 = (4 * 64 * (256 + 8) + 2 * 64 * 72) * 2;   // 153600
    cudaFuncSetAttribute(attn_tc<128>, cudaFuncAttributeMaxDynamicSharedMemorySize, asm128);
    cudaFuncSetAttribute(attn_tc<256>, cudaFuncAttributeMaxDynamicSharedMemorySize, asm256);

    detect_kernel<<<1, 256>>>((const int*)x);
    wtrans_all_kernel<<<dim3(32, 32, 8), dim3(32, 8)>>>(
        a1_qw, a1_kw, a1_vw, a1_pw, a2_qw, a2_kw, a2_vw, a2_pw, p_w);
    embed_kernel<<<NTOK, 256>>>(x, emb_w, pos_w);

    dim3 gq3(DMODEL / 128, NTOK / 128, 3);   // fused QKV
    dim3 gg(DMODEL / 128, NTOK / 128);

    // Layer 1 (8 heads, dh=128)
    QKVPtrs p1 = {{a1_qb, a1_kb, a1_vb}, {qp, kp, vp}};
    gemm_qkv<<<gq3, 256, GEMM_SMEM>>>(p_a, p_w, 0, p1);
    attn_tc<128><<<dim3(SEQ / 64, 8, BATCH), 256, asm128>>>(qp, kp, vp, x, p_b);
    gemm_split<<<gg, 256, GEMM_SMEM>>>(p_b, p_w + (size_t)3 * DMODEL * DPAIR,
                                       a1_pb, p_emb, p_h1, p_a);

    // Layer 2 (4 heads, dh=256)
    QKVPtrs p2 = {{a2_qb, a2_kb, a2_vb}, {qp, kp, vp}};
    gemm_qkv<<<gq3, 256, GEMM_SMEM>>>(p_a, p_w, 4, p2);
    attn_tc<256><<<dim3(SEQ / 64, 4, BATCH), 256, asm256>>>(qp, kp, vp, x, p_b);
    gemm_split<<<gg, 256, GEMM_SMEM>>>(p_b, p_w + (size_t)7 * DMODEL * DPAIR,
                                       a2_pb, p_h1, p_h2, nullptr);

    pool_kernel<<<dim3(DMODEL / 128, BATCH), 128>>>(x);
    lnlin_kernel<<<BATCH, 256>>>(norm_g, norm_b, lin_w, lin_b, out);
}

// round 17
// speedup vs baseline: 2.7470x; 1.0230x over previous
#include <cuda_runtime.h>
#include <cuda_bf16.h>
#include <cuda_fp16.h>
#include <cstdint>
#include <math.h>

#define DMODEL 1024
#define DPAIR (2 * DMODEL)          // paired-row stride: [hi 1024 | lo 1024]
#define SEQ 512
#define BATCH 64
#define NTOK (BATCH * SEQ)

// ---------------- scratch (static device globals; no allocation) ----------------
__device__ float g_emb[(size_t)NTOK * DMODEL];
__device__ float g_h1[(size_t)NTOK * DMODEL];
__device__ float g_h2[(size_t)NTOK * DMODEL];
__device__ float g_q[(size_t)NTOK * DMODEL];   // bf16 paired rows (NTOK x DPAIR)
__device__ float g_k[(size_t)NTOK * DMODEL];
__device__ float g_v[(size_t)NTOK * DMODEL];   // fp16 paired rows for V
__device__ __nv_bfloat16 g_abuf[(size_t)NTOK * DPAIR];
__device__ __nv_bfloat16 g_bbuf[(size_t)NTOK * DPAIR];
__device__ __nv_bfloat16 g_wbuf[(size_t)8 * DMODEL * DPAIR];
__device__ float g_pooled[BATCH * DMODEL];
__device__ int g_is64;

struct QKVPtrs {
    const float* bias[3];
    __nv_bfloat16* out[3];
};

// ---------------- helpers ----------------
__device__ __forceinline__ uint32_t smem_u32(const void* p) {
    uint32_t a;
    asm("{ .reg .u64 t; cvta.to.shared.u64 t, %1; cvt.u32.u64 %0, t; }" : "=r"(a) : "l"(p));
    return a;
}
__device__ __forceinline__ void cp_async16(uint32_t dst, const void* src) {
    asm volatile("cp.async.cg.shared.global [%0], [%1], 16;" :: "r"(dst), "l"(src));
}
__device__ __forceinline__ void ldsm_x4(uint32_t& r0, uint32_t& r1, uint32_t& r2, uint32_t& r3,
                                        uint32_t addr) {
    asm volatile("ldmatrix.sync.aligned.m8n8.x4.shared.b16 {%0,%1,%2,%3}, [%4];"
                 : "=r"(r0), "=r"(r1), "=r"(r2), "=r"(r3) : "r"(addr));
}
__device__ __forceinline__ void ldsm_x4t(uint32_t& r0, uint32_t& r1, uint32_t& r2, uint32_t& r3,
                                         uint32_t addr) {
    asm volatile("ldmatrix.sync.aligned.m8n8.x4.trans.shared.b16 {%0,%1,%2,%3}, [%4];"
                 : "=r"(r0), "=r"(r1), "=r"(r2), "=r"(r3) : "r"(addr));
}
__device__ __forceinline__ void mma_bf16(float& c0, float& c1, float& c2, float& c3,
                                         uint32_t a0, uint32_t a1, uint32_t a2, uint32_t a3,
                                         uint32_t b0, uint32_t b1) {
    asm volatile("mma.sync.aligned.m16n8k16.row.col.f32.bf16.bf16.f32 "
                 "{%0,%1,%2,%3}, {%4,%5,%6,%7}, {%8,%9}, {%0,%1,%2,%3};"
                 : "+f"(c0), "+f"(c1), "+f"(c2), "+f"(c3)
                 : "r"(a0), "r"(a1), "r"(a2), "r"(a3), "r"(b0), "r"(b1));
}
__device__ __forceinline__ void mma_f16(float& c0, float& c1, float& c2, float& c3,
                                        uint32_t a0, uint32_t a1, uint32_t a2, uint32_t a3,
                                        uint32_t b0, uint32_t b1) {
    asm volatile("mma.sync.aligned.m16n8k16.row.col.f32.f16.f16.f32 "
                 "{%0,%1,%2,%3}, {%4,%5,%6,%7}, {%8,%9}, {%0,%1,%2,%3};"
                 : "+f"(c0), "+f"(c1), "+f"(c2), "+f"(c3)
                 : "r"(a0), "r"(a1), "r"(a2), "r"(a3), "r"(b0), "r"(b1));
}
__device__ __forceinline__ void split_bf16(float v, __nv_bfloat16& hi, __nv_bfloat16& lo) {
    hi = __float2bfloat16_rn(v);
    lo = __float2bfloat16_rn(v - __bfloat162float(hi));
}
__device__ __forceinline__ void split_f16(float v, __half& hi, __half& lo) {
    hi = __float2half_rn(v);
    lo = __float2half_rn(v - __half2float(hi));
}
__device__ __forceinline__ float fast_exp(float x) {
    if (x < -80.f) return 0.f;
    float t = x * 1.4426950408889634f;
    float n = floorf(t + 0.5f);
    float g = (t - n) * 0.6931471805599453f;
    float p = 1.f + g * (1.f + g * (0.5f + g * (0.16666667f + g * (0.041666667f + g * 0.0083333f))));
    return __uint_as_float((uint32_t)(((int)n + 127) << 23)) * p;
}

// ---------------- dtype detection ----------------
__global__ void detect_kernel(const int* __restrict__ x) {
    __shared__ int any;
    if (threadIdx.x == 0) any = 0;
    __syncthreads();
    int local = 0;
    for (int i = threadIdx.x * 2 + 1; i < NTOK; i += blockDim.x * 2) local |= x[i];
    if (local) atomicOr(&any, 1);
    __syncthreads();
    if (threadIdx.x == 0) g_is64 = (any == 0) ? 1 : 0;
}
__device__ __forceinline__ long long get_id(const void* x, int i) {
    return g_is64 ? ((const long long*)x)[i] : (long long)((const int*)x)[i];
}

// ---------------- fused 8x weight transpose + bf16 hi/lo (paired rows) ----------------
__global__ void wtrans_all_kernel(
    const float* __restrict__ W0, const float* __restrict__ W1,
    const float* __restrict__ W2, const float* __restrict__ W3,
    const float* __restrict__ W4, const float* __restrict__ W5,
    const float* __restrict__ W6, const float* __restrict__ W7,
    __nv_bfloat16* __restrict__ WT) {
    __shared__ float t[32][33];
    int w = blockIdx.z;
    const float* W = (w == 0) ? W0 : (w == 1) ? W1 : (w == 2) ? W2 : (w == 3) ? W3
                   : (w == 4) ? W4 : (w == 5) ? W5 : (w == 6) ? W6 : W7;
    size_t wofs = (size_t)w * DMODEL * DPAIR;
    int n0 = blockIdx.x * 32, k0 = blockIdx.y * 32;
    int tx = threadIdx.x, ty = threadIdx.y;
#pragma unroll
    for (int i = 0; i < 4; i++)
        t[ty + 8 * i][tx] = W[(size_t)(k0 + ty + 8 * i) * DMODEL + n0 + tx];
    __syncthreads();
#pragma unroll
    for (int i = 0; i < 4; i++) {
        float v = t[tx][ty + 8 * i];
        __nv_bfloat16 hi, lo;
        split_bf16(v, hi, lo);
        size_t idx = wofs + (size_t)(n0 + ty + 8 * i) * DPAIR + k0 + tx;
        WT[idx] = hi;
        WT[idx + DMODEL] = lo;
    }
}

// ---------------- embedding: fp32 + paired bf16 hi/lo ----------------
__global__ void embed_kernel(const void* __restrict__ x,
                             const float* __restrict__ emb_w,
                             const float* __restrict__ pos_w) {
    int tok = blockIdx.x;
    int s = tok & (SEQ - 1);
    long long id = get_id(x, tok);
    const float4* ew = (const float4*)(emb_w + (size_t)id * DMODEL);
    const float4* pw = (const float4*)(pos_w + (size_t)s * DMODEL);
    float4* out = (float4*)(g_emb + (size_t)tok * DMODEL);
    __nv_bfloat16* op = g_abuf + (size_t)tok * DPAIR;
    for (int i = threadIdx.x; i < DMODEL / 4; i += blockDim.x) {
        float4 a = ew[i], b = pw[i];
        float4 o = make_float4(a.x + b.x, a.y + b.y, a.z + b.z, a.w + b.w);
        out[i] = o;
        __nv_bfloat16 h0, l0, h1, l1, h2, l2, h3, l3;
        split_bf16(o.x, h0, l0); split_bf16(o.y, h1, l1);
        split_bf16(o.z, h2, l2); split_bf16(o.w, h3, l3);
        op[4 * i + 0] = h0; op[4 * i + 1] = h1; op[4 * i + 2] = h2; op[4 * i + 3] = h3;
        op[DMODEL + 4 * i + 0] = l0; op[DMODEL + 4 * i + 1] = l1;
        op[DMODEL + 4 * i + 2] = l2; op[DMODEL + 4 * i + 3] = l3;
    }
}

// ---------------- GEMM mainloops (paired rows) ----------------
#define BKD 32
#define SSTR 40
#define TILE_E (128 * SSTR)
#define ROWB (SSTR * 2)

// 3-term split mainloop (proven precision)
__device__ __forceinline__ void gemm_mainloop(
    const __nv_bfloat16* A, const __nv_bfloat16* B,
    __nv_bfloat16* smem, int bm, int bn, float acc[2][8][4]) {
    __nv_bfloat16* sAhi[2] = {smem + 0 * TILE_E, smem + 1 * TILE_E};
    __nv_bfloat16* sAlo[2] = {smem + 2 * TILE_E, smem + 3 * TILE_E};
    __nv_bfloat16* sBhi[2] = {smem + 4 * TILE_E, smem + 5 * TILE_E};
    __nv_bfloat16* sBlo[2] = {smem + 6 * TILE_E, smem + 7 * TILE_E};

    int tid = threadIdx.x, wid = tid >> 5, lane = tid & 31;
    int wm = (wid >> 1) * 32;
    int wn = (wid & 1) * 64;

    int lrow = tid >> 1;
    int lc0 = (tid & 1) * 2;
    const __nv_bfloat16* gA = A + (size_t)(bm * 128 + lrow) * DPAIR;
    const __nv_bfloat16* gB = B + (size_t)(bn * 128 + lrow) * DPAIR;
    uint32_t rowoff = lrow * ROWB;
    uint32_t dAhi[2], dAlo[2], dBhi[2], dBlo[2];
#pragma unroll
    for (int b = 0; b < 2; b++) {
        dAhi[b] = smem_u32(sAhi[b]) + rowoff;
        dAlo[b] = smem_u32(sAlo[b]) + rowoff;
        dBhi[b] = smem_u32(sBhi[b]) + rowoff;
        dBlo[b] = smem_u32(sBlo[b]) + rowoff;
    }

    int g = lane >> 3, r = lane & 7;
    int rofs = (g & 1) * 8 + r;
    int kofs = (g >> 1) * 8;

    uint32_t aHb[2], aLb[2], bHb[2], bLb[2];
    {
        uint32_t aoff = (uint32_t)((wm + rofs) * SSTR + kofs) * 2;
        uint32_t boff = (uint32_t)((wn + rofs) * SSTR + kofs) * 2;
#pragma unroll
        for (int b = 0; b < 2; b++) {
            aHb[b] = smem_u32(sAhi[b]) + aoff;
            aLb[b] = smem_u32(sAlo[b]) + aoff;
            bHb[b] = smem_u32(sBhi[b]) + boff;
            bLb[b] = smem_u32(sBlo[b]) + boff;
        }
    }

#define LOAD_TILE(buf, k0) do { \
    cp_async16(dAhi[buf] + (lc0 + 0) * 16, gA + (k0) + (lc0 + 0) * 8); \
    cp_async16(dAhi[buf] + (lc0 + 1) * 16, gA + (k0) + (lc0 + 1) * 8); \
    cp_async16(dAlo[buf] + (lc0 + 0) * 16, gA + DMODEL + (k0) + (lc0 + 0) * 8); \
    cp_async16(dAlo[buf] + (lc0 + 1) * 16, gA + DMODEL + (k0) + (lc0 + 1) * 8); \
    cp_async16(dBhi[buf] + (lc0 + 0) * 16, gB + (k0) + (lc0 + 0) * 8); \
    cp_async16(dBhi[buf] + (lc0 + 1) * 16, gB + (k0) + (lc0 + 1) * 8); \
    cp_async16(dBlo[buf] + (lc0 + 0) * 16, gB + DMODEL + (k0) + (lc0 + 0) * 8); \
    cp_async16(dBlo[buf] + (lc0 + 1) * 16, gB + DMODEL + (k0) + (lc0 + 1) * 8); \
    asm volatile("cp.async.commit_group;"); \
} while (0)

    LOAD_TILE(0, 0);
    LOAD_TILE(1, BKD);

    const int NIT = DMODEL / BKD;
    for (int it = 0; it < NIT; it++) {
        int buf = it & 1;
        if (it + 2 < NIT)
            asm volatile("cp.async.wait_group 1;" ::: "memory");
        else
            asm volatile("cp.async.wait_group 0;" ::: "memory");
        __syncthreads();

        uint32_t aHx = aHb[buf], aLx = aLb[buf], bHx = bHb[buf], bLx = bLb[buf];
#pragma unroll
        for (int kk = 0; kk < 2; kk++) {
            const uint32_t ko = kk * 32;
            uint32_t aH[2][4];
#pragma unroll
            for (int mt = 0; mt < 2; mt++)
                ldsm_x4(aH[mt][0], aH[mt][1], aH[mt][2], aH[mt][3],
                        aHx + mt * (16 * ROWB) + ko);
            uint32_t bF[8][2];
#pragma unroll
            for (int np = 0; np < 4; np++) {
                uint32_t r0, r1, r2, r3;
                ldsm_x4(r0, r1, r2, r3, bHx + np * (16 * ROWB) + ko);
                bF[np * 2 + 0][0] = r0; bF[np * 2 + 0][1] = r2;
                bF[np * 2 + 1][0] = r1; bF[np * 2 + 1][1] = r3;
            }
#pragma unroll
            for (int mt = 0; mt < 2; mt++)
#pragma unroll
                for (int nt = 0; nt < 8; nt++)
                    mma_bf16(acc[mt][nt][0], acc[mt][nt][1], acc[mt][nt][2], acc[mt][nt][3],
                             aH[mt][0], aH[mt][1], aH[mt][2], aH[mt][3],
                             bF[nt][0], bF[nt][1]);
            {
                uint32_t aL[2][4];
#pragma unroll
                for (int mt = 0; mt < 2; mt++)
                    ldsm_x4(aL[mt][0], aL[mt][1], aL[mt][2], aL[mt][3],
                            aLx + mt * (16 * ROWB) + ko);
#pragma unroll
                for (int mt = 0; mt < 2; mt++)
#pragma unroll
                    for (int nt = 0; nt < 8; nt++)
                        mma_bf16(acc[mt][nt][0], acc[mt][nt][1], acc[mt][nt][2], acc[mt][nt][3],
                                 aL[mt][0], aL[mt][1], aL[mt][2], aL[mt][3],
                                 bF[nt][0], bF[nt][1]);
            }
#pragma unroll
            for (int np = 0; np < 4; np++) {
                uint32_t r0, r1, r2, r3;
                ldsm_x4(r0, r1, r2, r3, bLx + np * (16 * ROWB) + ko);
                bF[np * 2 + 0][0] = r0; bF[np * 2 + 0][1] = r2;
                bF[np * 2 + 1][0] = r1; bF[np * 2 + 1][1] = r3;
            }
#pragma unroll
            for (int mt = 0; mt < 2; mt++)
#pragma unroll
                for (int nt = 0; nt < 8; nt++)
                    mma_bf16(acc[mt][nt][0], acc[mt][nt][1], acc[mt][nt][2], acc[mt][nt][3],
                             aH[mt][0], aH[mt][1], aH[mt][2], aH[mt][3],
                             bF[nt][0], bF[nt][1]);
        }
        __syncthreads();
        if (it + 2 < NIT) LOAD_TILE(buf, (it + 2) * BKD);
    }
#undef LOAD_TILE
}

// single-term mainloop (hi x hi) — for Q/K projections (error cancels in softmax)
__device__ __forceinline__ void gemm_mainloop_single(
    const __nv_bfloat16* A, const __nv_bfloat16* B,
    __nv_bfloat16* smem, int bm, int bn, float acc[2][8][4]) {
    __nv_bfloat16* sA[2] = {smem + 0 * TILE_E, smem + 1 * TILE_E};
    __nv_bfloat16* sB[2] = {smem + 2 * TILE_E, smem + 3 * TILE_E};

    int tid = threadIdx.x, wid = tid >> 5, lane = tid & 31;
    int wm = (wid >> 1) * 32;
    int wn = (wid & 1) * 64;

    int lrow = tid >> 1;
    int lc0 = (tid & 1) * 2;
    const __nv_bfloat16* gA = A + (size_t)(bm * 128 + lrow) * DPAIR;
    const __nv_bfloat16* gB = B + (size_t)(bn * 128 + lrow) * DPAIR;
    uint32_t rowoff = lrow * ROWB;
    uint32_t dA[2], dB[2];
#pragma unroll
    for (int b = 0; b < 2; b++) {
        dA[b] = smem_u32(sA[b]) + rowoff;
        dB[b] = smem_u32(sB[b]) + rowoff;
    }

    int g = lane >> 3, r = lane & 7;
    int rofs = (g & 1) * 8 + r;
    int kofs = (g >> 1) * 8;

    uint32_t aHb[2], bHb[2];
    {
        uint32_t aoff = (uint32_t)((wm + rofs) * SSTR + kofs) * 2;
        uint32_t boff = (uint32_t)((wn + rofs) * SSTR + kofs) * 2;
#pragma unroll
        for (int b = 0; b < 2; b++) {
            aHb[b] = smem_u32(sA[b]) + aoff;
            bHb[b] = smem_u32(sB[b]) + boff;
        }
    }

#define LOAD_TILE1(buf, k0) do { \
    cp_async16(dA[buf] + (lc0 + 0) * 16, gA + (k0) + (lc0 + 0) * 8); \
    cp_async16(dA[buf] + (lc0 + 1) * 16, gA + (k0) + (lc0 + 1) * 8); \
    cp_async16(dB[buf] + (lc0 + 0) * 16, gB + (k0) + (lc0 + 0) * 8); \
    cp_async16(dB[buf] + (lc0 + 1) * 16, gB + (k0) + (lc0 + 1) * 8); \
    asm volatile("cp.async.commit_group;"); \
} while (0)

    LOAD_TILE1(0, 0);
    LOAD_TILE1(1, BKD);

    const int NIT = DMODEL / BKD;
    for (int it = 0; it < NIT; it++) {
        int buf = it & 1;
        if (it + 2 < NIT)
            asm volatile("cp.async.wait_group 1;" ::: "memory");
        else
            asm volatile("cp.async.wait_group 0;" ::: "memory");
        __syncthreads();

        uint32_t aHx = aHb[buf], bHx = bHb[buf];
#pragma unroll
        for (int kk = 0; kk < 2; kk++) {
            const uint32_t ko = kk * 32;
            uint32_t aH[2][4];
#pragma unroll
            for (int mt = 0; mt < 2; mt++)
                ldsm_x4(aH[mt][0], aH[mt][1], aH[mt][2], aH[mt][3],
                        aHx + mt * (16 * ROWB) + ko);
            uint32_t bF[8][2];
#pragma unroll
            for (int np = 0; np < 4; np++) {
                uint32_t r0, r1, r2, r3;
                ldsm_x4(r0, r1, r2, r3, bHx + np * (16 * ROWB) + ko);
                bF[np * 2 + 0][0] = r0; bF[np * 2 + 0][1] = r2;
                bF[np * 2 + 1][0] = r1; bF[np * 2 + 1][1] = r3;
            }
#pragma unroll
            for (int mt = 0; mt < 2; mt++)
#pragma unroll
                for (int nt = 0; nt < 8; nt++)
                    mma_bf16(acc[mt][nt][0], acc[mt][nt][1], acc[mt][nt][2], acc[mt][nt][3],
                             aH[mt][0], aH[mt][1], aH[mt][2], aH[mt][3],
                             bF[nt][0], bF[nt][1]);
        }
        __syncthreads();
        if (it + 2 < NIT) LOAD_TILE1(buf, (it + 2) * BKD);
    }
#undef LOAD_TILE1
}

// ---------------- fused QKV GEMM: Q,K single-term bf16; V 3-term -> fp16 pairs ----------------
__global__ __launch_bounds__(256, 2) void gemm_qkv(
    const __nv_bfloat16* __restrict__ A, const __nv_bfloat16* __restrict__ Wbase,
    int wslot0, QKVPtrs P) {
    extern __shared__ __nv_bfloat16 smem[];
    int z = blockIdx.z;
    const __nv_bfloat16* B = Wbase + (size_t)(wslot0 + z) * DMODEL * DPAIR;
    const float* bias = P.bias[z];

    float acc[2][8][4];
#pragma unroll
    for (int i = 0; i < 2; i++)
#pragma unroll
        for (int j = 0; j < 8; j++)
#pragma unroll
            for (int k = 0; k < 4; k++) acc[i][j][k] = 0.f;

    if (z < 2)
        gemm_mainloop_single(A, B, smem, blockIdx.y, blockIdx.x, acc);
    else
        gemm_mainloop(A, B, smem, blockIdx.y, blockIdx.x, acc);

    int lane = threadIdx.x & 31, wid = threadIdx.x >> 5;
    int wm = (wid >> 1) * 32, wn = (wid & 1) * 64;
    int gid = lane >> 2, tig = lane & 3;
#pragma unroll
    for (int mt = 0; mt < 2; mt++) {
#pragma unroll
        for (int half = 0; half < 2; half++) {
            int m = blockIdx.y * 128 + wm + mt * 16 + gid + half * 8;
#pragma unroll
            for (int nt = 0; nt < 8; nt++) {
                int ncol = blockIdx.x * 128 + wn + nt * 8 + tig * 2;
                float v0 = acc[mt][nt][half * 2 + 0] + bias[ncol];
                float v1 = acc[mt][nt][half * 2 + 1] + bias[ncol + 1];
                if (z < 2) {
                    __nv_bfloat16* prow = P.out[z] + (size_t)m * DPAIR;
                    *(__nv_bfloat162*)(prow + ncol) =
                        __nv_bfloat162(__float2bfloat16_rn(v0), __float2bfloat16_rn(v1));
                } else {
                    // V: fp16 hi/lo pairs (phase C runs on the f16 MMA pipe)
                    __half* prow = (__half*)P.out[2] + (size_t)m * DPAIR;
                    __half h0, l0, h1, l1;
                    split_f16(v0, h0, l0);
                    split_f16(v1, h1, l1);
                    *(__half2*)(prow + ncol) = __halves2half2(h0, h1);
                    *(__half2*)(prow + DMODEL + ncol) = __halves2half2(l0, l1);
                }
            }
        }
    }
}

// ---------------- projection GEMM: bias + residual, fp32 C + optional bf16 pairs ----------------
__global__ __launch_bounds__(256, 2) void gemm_split(
    const __nv_bfloat16* __restrict__ A, const __nv_bfloat16* __restrict__ B,
    const float* __restrict__ bias, const float* __restrict__ res,
    float* __restrict__ C, __nv_bfloat16* __restrict__ Cbf) {
    extern __shared__ __nv_bfloat16 smem[];
    float acc[2][8][4];
#pragma unroll
    for (int i = 0; i < 2; i++)
#pragma unroll
        for (int j = 0; j < 8; j++)
#pragma unroll
            for (int k = 0; k < 4; k++) acc[i][j][k] = 0.f;

    gemm_mainloop(A, B, smem, blockIdx.y, blockIdx.x, acc);

    int lane = threadIdx.x & 31, wid = threadIdx.x >> 5;
    int wm = (wid >> 1) * 32, wn = (wid & 1) * 64;
    int gid = lane >> 2, tig = lane & 3;
#pragma unroll
    for (int mt = 0; mt < 2; mt++) {
#pragma unroll
        for (int half = 0; half < 2; half++) {
            int m = blockIdx.y * 128 + wm + mt * 16 + gid + half * 8;
            float* crow = C + (size_t)m * DMODEL;
            const float* rrow = res + (size_t)m * DMODEL;
            __nv_bfloat16* prow = Cbf ? Cbf + (size_t)m * DPAIR : nullptr;
#pragma unroll
            for (int nt = 0; nt < 8; nt++) {
                int ncol = blockIdx.x * 128 + wn + nt * 8 + tig * 2;
                float v0 = acc[mt][nt][half * 2 + 0] + bias[ncol] + rrow[ncol];
                float v1 = acc[mt][nt][half * 2 + 1] + bias[ncol + 1] + rrow[ncol + 1];
                *(float2*)(crow + ncol) = make_float2(v0, v1);
                if (prow) {
                    __nv_bfloat16 h0, l0, h1, l1;
                    split_bf16(v0, h0, l0);
                    split_bf16(v1, h1, l1);
                    *(__nv_bfloat162*)(prow + ncol) = __nv_bfloat162(h0, h1);
                    *(__nv_bfloat162*)(prow + DMODEL + ncol) = __nv_bfloat162(l0, l1);
                }
            }
        }
    }
}

// ---------------- tensor-core flash attention: Q/K single bf16; P fp16; V fp16 hi/lo ----------------
template <int DH>
__global__ __launch_bounds__(256) void attn_tc(
    const __nv_bfloat16* __restrict__ Q, const __nv_bfloat16* __restrict__ K,
    const __half* __restrict__ V, const void* __restrict__ xids,
    __nv_bfloat16* __restrict__ O) {
    extern __shared__ __nv_bfloat16 smb[];
    const int SSTRA = DH + 8;
    const int PSTR = 72;
    __nv_bfloat16* qhi_s = smb;
    __nv_bfloat16* khi_s = qhi_s + 64 * SSTRA;
    __half* vhi_s = (__half*)(khi_s + 64 * SSTRA);
    __half* vlo_s = vhi_s + 64 * SSTRA;
    __half* phi_s = vlo_s + 64 * SSTRA;
    __shared__ int msk[64];
    __shared__ float psumw[64][2];

    int qt = blockIdx.x, h = blockIdx.y, b = blockIdx.z;
    int tid = threadIdx.x, wid = tid >> 5, lane = tid & 31;
    int mt = wid >> 1, nh = wid & 1;
    float scale = rsqrtf((float)DH);
    int q0 = qt * 64;
    int gg = lane >> 3, rr8 = lane & 7;
    int rofs = (gg & 1) * 8 + rr8, kofs = (gg >> 1) * 8;
    int rowA = mt * 16 + (lane >> 2), rowB = rowA + 8;
    int colq = (lane & 3) * 2;
    const int CHK = DH / 8;
    const int NG = DH / 16;

    for (int i = tid; i < 64 * CHK; i += 256) {
        int r = i / CHK, c = i % CHK;
        size_t gi = (size_t)(b * SEQ + q0 + r) * DPAIR + h * DH + c * 8;
        *(uint4*)(qhi_s + r * SSTRA + c * 8) = *(const uint4*)(Q + gi);
    }

    float o[NG][4];
#pragma unroll
    for (int i = 0; i < NG; i++) { o[i][0] = 0.f; o[i][1] = 0.f; o[i][2] = 0.f; o[i][3] = 0.f; }
    float sumA = 0.f, sumB = 0.f;

    int is64 = g_is64;

    for (int kt = 0; kt < SEQ / 64; kt++) {
        int k0 = kt * 64;
        __syncthreads();
        for (int i = tid; i < 64 * CHK; i += 256) {
            int r = i / CHK, c = i % CHK;
            size_t gi = (size_t)(b * SEQ + k0 + r) * DPAIR + h * DH + c * 8;
            *(uint4*)(khi_s + r * SSTRA + c * 8) = *(const uint4*)(K + gi);
            *(uint4*)(vhi_s + r * SSTRA + c * 8) = *(const uint4*)(V + gi);
            *(uint4*)(vlo_s + r * SSTRA + c * 8) = *(const uint4*)(V + gi + DMODEL);
        }
        if (tid < 64) {
            long long idv = is64 ? ((const long long*)xids)[b * SEQ + k0 + tid]
                                 : (long long)((const int*)xids)[b * SEQ + k0 + tid];
            msk[tid] = (idv != 0) ? 1 : 0;
        }
        __syncthreads();

        // ---- phase A: scores via single-term bf16 HMMA (QK error cancels in softmax) ----
        float sc[4][4];
#pragma unroll
        for (int gq = 0; gq < 4; gq++) { sc[gq][0] = 0.f; sc[gq][1] = 0.f; sc[gq][2] = 0.f; sc[gq][3] = 0.f; }
#pragma unroll
        for (int ks = 0; ks < DH / 16; ks++) {
            uint32_t aH[4];
            ldsm_x4(aH[0], aH[1], aH[2], aH[3],
                    smem_u32(qhi_s + (mt * 16 + rofs) * SSTRA + ks * 16 + kofs));
            uint32_t bH[4][2];
#pragma unroll
            for (int kg = 0; kg < 2; kg++) {
                uint32_t r0, r1, r2, r3;
                ldsm_x4(r0, r1, r2, r3,
                        smem_u32(khi_s + (nh * 32 + kg * 16 + rofs) * SSTRA + ks * 16 + kofs));
                bH[kg * 2 + 0][0] = r0; bH[kg * 2 + 0][1] = r2;
                bH[kg * 2 + 1][0] = r1; bH[kg * 2 + 1][1] = r3;
            }
#pragma unroll
            for (int gq = 0; gq < 4; gq++)
                mma_bf16(sc[gq][0], sc[gq][1], sc[gq][2], sc[gq][3],
                         aH[0], aH[1], aH[2], aH[3], bH[gq][0], bH[gq][1]);
        }

        // mask + scale + exp (shift-free softmax) + P store (single fp16: 2^-12 rounding)
#pragma unroll
        for (int gq = 0; gq < 4; gq++) {
            int cb = nh * 32 + gq * 8 + colq;
            bool k0m = msk[cb] != 0, k1m = msk[cb + 1] != 0;
            float p0 = k0m ? fast_exp(sc[gq][0] * scale) : 0.f;
            float p1 = k1m ? fast_exp(sc[gq][1] * scale) : 0.f;
            float p2 = k0m ? fast_exp(sc[gq][2] * scale) : 0.f;
            float p3 = k1m ? fast_exp(sc[gq][3] * scale) : 0.f;
            sumA += p0 + p1; sumB += p2 + p3;
            *(__half2*)(phi_s + rowA * PSTR + cb) = __floats2half2_rn(p0, p1);
            *(__half2*)(phi_s + rowB * PSTR + cb) = __floats2half2_rn(p2, p3);
        }
        __syncthreads();

        // ---- phase C: O += P @ (Vhi + Vlo), fp16 MMA ----
#pragma unroll
        for (int ksv = 0; ksv < 4; ksv++) {
            uint32_t pF[4];
            ldsm_x4(pF[0], pF[1], pF[2], pF[3],
                    smem_u32(phi_s + (mt * 16 + rofs) * PSTR + ksv * 16 + kofs));
            int vrow = ksv * 16 + rr8 + ((lane >> 4) << 3);
            int vcb = nh * (DH / 2) + ((lane >> 3) & 1) * 8;
#pragma unroll
            for (int vg = 0; vg < NG / 2; vg++) {
                uint32_t r0, r1, r2, r3;
                ldsm_x4t(r0, r1, r2, r3,
                         smem_u32(vhi_s + vrow * SSTRA + vcb + vg * 16));
                uint32_t bH0[2] = {r0, r2}, bH1[2] = {r1, r3};
                ldsm_x4t(r0, r1, r2, r3,
                         smem_u32(vlo_s + vrow * SSTRA + vcb + vg * 16));
                uint32_t bL0[2] = {r0, r2}, bL1[2] = {r1, r3};
                int g0 = vg * 2, g1 = vg * 2 + 1;
                mma_f16(o[g0][0], o[g0][1], o[g0][2], o[g0][3],
                        pF[0], pF[1], pF[2], pF[3], bH0[0], bH0[1]);
                mma_f16(o[g1][0], o[g1][1], o[g1][2], o[g1][3],
                        pF[0], pF[1], pF[2], pF[3], bH1[0], bH1[1]);
                mma_f16(o[g0][0], o[g0][1], o[g0][2], o[g0][3],
                        pF[0], pF[1], pF[2], pF[3], bL0[0], bL0[1]);
                mma_f16(o[g1][0], o[g1][1], o[g1][2], o[g1][3],
                        pF[0], pF[1], pF[2], pF[3], bL1[0], bL1[1]);
            }
        }
    }

    sumA += __shfl_xor_sync(0xFFFFFFFF, sumA, 1);
    sumA += __shfl_xor_sync(0xFFFFFFFF, sumA, 2);
    sumB += __shfl_xor_sync(0xFFFFFFFF, sumB, 1);
    sumB += __shfl_xor_sync(0xFFFFFFFF, sumB, 2);
    __syncthreads();
    if ((lane & 3) == 0) { psumw[rowA][nh] = sumA; psumw[rowB][nh] = sumB; }
    __syncthreads();

    float invA = 1.0f / fmaxf(psumw[rowA][0] + psumw[rowA][1], 1e-20f);
    float invB = 1.0f / fmaxf(psumw[rowB][0] + psumw[rowB][1], 1e-20f);
    size_t bA = (size_t)(b * SEQ + q0 + rowA) * DPAIR;
    size_t bB = (size_t)(b * SEQ + q0 + rowB) * DPAIR;
#pragma unroll
    for (int gq = 0; gq < NG; gq++) {
        int cb = h * DH + nh * (DH / 2) + gq * 8 + colq;
        float v0 = o[gq][0] * invA, v1 = o[gq][1] * invA;
        float v2 = o[gq][2] * invB, v3 = o[gq][3] * invB;
        __nv_bfloat16 h0, l0, h1, l1;
        split_bf16(v0, h0, l0); split_bf16(v1, h1, l1);
        *(__nv_bfloat162*)(O + bA + cb) = __nv_bfloat162(h0, h1);
        *(__nv_bfloat162*)(O + bA + DMODEL + cb) = __nv_bfloat162(l0, l1);
        split_bf16(v2, h0, l0); split_bf16(v3, h1, l1);
        *(__nv_bfloat162*)(O + bB + cb) = __nv_bfloat162(h0, h1);
        *(__nv_bfloat162*)(O + bB + DMODEL + cb) = __nv_bfloat162(l0, l1);
    }
}

// ---------------- masked mean pooling of (g_h2 + g_emb) ----------------
__global__ void pool_kernel(const void* __restrict__ xids) {
    int b = blockIdx.y;
    int col = blockIdx.x * 128 + threadIdx.x;
    __shared__ int smask[SEQ];
    int is64 = g_is64;
    for (int s = threadIdx.x; s < SEQ; s += 128) {
        long long idv = is64 ? ((const long long*)xids)[b * SEQ + s]
                             : (long long)((const int*)xids)[b * SEQ + s];
        smask[s] = (idv != 0) ? 1 : 0;
    }
    __syncthreads();
    float acc = 0.f;
    int cnt = 0;
    for (int s = 0; s < SEQ; s++) {
        if (smask[s]) {
            size_t idx = (size_t)(b * SEQ + s) * DMODEL + col;
            acc += g_h2[idx] + g_emb[idx];
            cnt++;
        }
    }
    g_pooled[b * DMODEL + col] = acc / (float)cnt;
}

// ---------------- LayerNorm + linear head ----------------
__global__ void lnlin_kernel(const float* __restrict__ ng, const float* __restrict__ nb,
                             const float* __restrict__ lw, const float* __restrict__ lb,
                             float* __restrict__ out) {
    int b = blockIdx.x, tid = threadIdx.x;
    __shared__ float red[256];
    float x[4];
    float s = 0.f;
#pragma unroll
    for (int k = 0; k < 4; k++) {
        x[k] = g_pooled[b * DMODEL + tid + k * 256];
        s += x[k];
    }
    red[tid] = s; __syncthreads();
    for (int st = 128; st > 0; st >>= 1) { if (tid < st) red[tid] += red[tid + st]; __syncthreads(); }
    float mu = red[0] / (float)DMODEL;
    __syncthreads();
    float s2 = 0.f;
#pragma unroll
    for (int k = 0; k < 4; k++) { float d = x[k] - mu; s2 += d * d; }
    red[tid] = s2; __syncthreads();
    for (int st = 128; st > 0; st >>= 1) { if (tid < st) red[tid] += red[tid + st]; __syncthreads(); }
    float var = red[0] / (float)DMODEL;
    float rstd = rsqrtf(var + 1e-5f);
    __syncthreads();
    float acc = 0.f;
#pragma unroll
    for (int k = 0; k < 4; k++) {
        int col = tid + k * 256;
        acc += ((x[k] - mu) * rstd * ng[col] + nb[col]) * lw[col];
    }
    red[tid] = acc; __syncthreads();
    for (int st = 128; st > 0; st >>= 1) { if (tid < st) red[tid] += red[tid + st]; __syncthreads(); }
    if (tid == 0) out[b] = red[0] + lb[0];
}

// ---------------- launch ----------------
extern "C" void kernel_launch(void* const* d_in, const int* in_sizes, int n_in,
                              void* d_out, int out_size) {
    const void*  x      = d_in[0];
    const float* emb_w  = (const float*)d_in[1];
    const float* pos_w  = (const float*)d_in[2];
    const float* a1_qw  = (const float*)d_in[3];
    const float* a1_qb  = (const float*)d_in[4];
    const float* a1_kw  = (const float*)d_in[5];
    const float* a1_kb  = (const float*)d_in[6];
    const float* a1_vw  = (const float*)d_in[7];
    const float* a1_vb  = (const float*)d_in[8];
    const float* a1_pw  = (const float*)d_in[9];
    const float* a1_pb  = (const float*)d_in[10];
    const float* a2_qw  = (const float*)d_in[11];
    const float* a2_qb  = (const float*)d_in[12];
    const float* a2_kw  = (const float*)d_in[13];
    const float* a2_kb  = (const float*)d_in[14];
    const float* a2_vw  = (const float*)d_in[15];
    const float* a2_vb  = (const float*)d_in[16];
    const float* a2_pw  = (const float*)d_in[17];
    const float* a2_pb  = (const float*)d_in[18];
    const float* norm_g = (const float*)d_in[19];
    const float* norm_b = (const float*)d_in[20];
    const float* lin_w  = (const float*)d_in[21];
    const float* lin_b  = (const float*)d_in[22];
    float* out = (float*)d_out;

    float *p_emb, *p_h1, *p_h2, *p_q, *p_k, *p_v;
    __nv_bfloat16 *p_a, *p_b, *p_w;
    cudaGetSymbolAddress((void**)&p_emb, g_emb);
    cudaGetSymbolAddress((void**)&p_h1,  g_h1);
    cudaGetSymbolAddress((void**)&p_h2,  g_h2);
    cudaGetSymbolAddress((void**)&p_q,   g_q);
    cudaGetSymbolAddress((void**)&p_k,   g_k);
    cudaGetSymbolAddress((void**)&p_v,   g_v);
    cudaGetSymbolAddress((void**)&p_a,   g_abuf);
    cudaGetSymbolAddress((void**)&p_b,   g_bbuf);
    cudaGetSymbolAddress((void**)&p_w,   g_wbuf);

    __nv_bfloat16* qp = (__nv_bfloat16*)p_q;
    __nv_bfloat16* kp = (__nv_bfloat16*)p_k;
    __nv_bfloat16* vp = (__nv_bfloat16*)p_v;   // actually fp16 pairs, cast at use
    const __half* vph = (const __half*)p_v;

    const int GEMM_SMEM = 8 * TILE_E * 2;   // 81920 bytes
    cudaFuncSetAttribute(gemm_split, cudaFuncAttributeMaxDynamicSharedMemorySize, GEMM_SMEM);
    cudaFuncSetAttribute(gemm_qkv,   cudaFuncAttributeMaxDynamicSharedMemorySize, GEMM_SMEM);
    const int asm128 = (4 * 64 * (128 + 8) + 64 * 72) * 2;   // 78848
    const int asm256 = (4 * 64 * (256 + 8) + 64 * 72) * 2;   // 144384
    cudaFuncSetAttribute(attn_tc<128>, cudaFuncAttributeMaxDynamicSharedMemorySize, asm128);
    cudaFuncSetAttribute(attn_tc<256>, cudaFuncAttributeMaxDynamicSharedMemorySize, asm256);

    detect_kernel<<<1, 256>>>((const int*)x);
    wtrans_all_kernel<<<dim3(32, 32, 8), dim3(32, 8)>>>(
        a1_qw, a1_kw, a1_vw, a1_pw, a2_qw, a2_kw, a2_vw, a2_pw, p_w);
    embed_kernel<<<NTOK, 256>>>(x, emb_w, pos_w);

    dim3 gq3(DMODEL / 128, NTOK / 128, 3);   // fused QKV
    dim3 gg(DMODEL / 128, NTOK / 128);

    // Layer 1 (8 heads, dh=128)
    QKVPtrs p1 = {{a1_qb, a1_kb, a1_vb}, {qp, kp, vp}};
    gemm_qkv<<<gq3, 256, GEMM_SMEM>>>(p_a, p_w, 0, p1);
    attn_tc<128><<<dim3(SEQ / 64, 8, BATCH), 256, asm128>>>(qp, kp, vph, x, p_b);
    gemm_split<<<gg, 256, GEMM_SMEM>>>(p_b, p_w + (size_t)3 * DMODEL * DPAIR,
                                       a1_pb, p_emb, p_h1, p_a);

    // Layer 2 (4 heads, dh=256)
    QKVPtrs p2 = {{a2_qb, a2_kb, a2_vb}, {qp, kp, vp}};
    gemm_qkv<<<gq3, 256, GEMM_SMEM>>>(p_a, p_w, 4, p2);
    attn_tc<256><<<dim3(SEQ / 64, 4, BATCH), 256, asm256>>>(qp, kp, vph, x, p_b);
    gemm_split<<<gg, 256, GEMM_SMEM>>>(p_b, p_w + (size_t)7 * DMODEL * DPAIR,
                                       a2_pb, p_h1, p_h2, nullptr);

    pool_kernel<<<dim3(DMODEL / 128, BATCH), 128>>>(x);
    lnlin_kernel<<<BATCH, 256>>>(norm_g, norm_b, lin_w, lin_b, out);
}